// round 2
// baseline (speedup 1.0000x reference)
#include <cuda_runtime.h>
#include <math.h>

#define BH 32
#define NTOK 4096
#define EH 64
#define MF 128
#define DM 512
#define NCH 16
#define TSTRIDE 132

#define SQRT_TEMP 0.35355339059327373f
#define TEMPF 0.125f
#define HALF_LOG_M 2.4260151319598084f
#define LN2F 0.6931471805599453f

// ---------------- scratch ----------------
__device__ float g_q[BH*NTOK*EH];
__device__ float g_k[BH*NTOK*EH];
__device__ float g_v[BH*NTOK*EH];
__device__ float g_qn2[BH*NTOK];
__device__ float g_kn2[BH*NTOK];
__device__ float g_MQ2[BH];
__device__ float g_MK2[BH];
__device__ float g_hashq[2*BH*NTOK];
__device__ float g_hashk[2*BH*NTOK];
__device__ int   g_qpos[2*BH*NTOK];
__device__ int   g_kpos[2*BH*NTOK];
__device__ int   g_qrev[2*BH*NTOK];
__device__ int   g_krev[2*BH*NTOK];
__device__ float g_qp[(size_t)BH*NTOK*MF];
__device__ float g_kp[(size_t)BH*NTOK*MF];
__device__ float g_qls[BH*NTOK];
__device__ float g_krm[BH*NTOK];
__device__ float g_kls[BH];
__device__ float g_kvp[(size_t)NCH*BH*MF*EH];
__device__ float g_ksp[NCH*BH*MF];
__device__ float g_kv[BH*MF*EH];
__device__ float g_ksum[BH*MF];
__device__ float g_qk1[BH*NTOK];
__device__ float g_qkv[(size_t)BH*NTOK*EH];
__device__ float g_ob[(size_t)2*BH*NTOK*EH];
__device__ float g_lseb[2*BH*NTOK];
__device__ float g_dsb[2*BH*NTOK];
__device__ float g_on[(size_t)BH*NTOK*EH];

// ---------------- K1: split heads + squared norms ----------------
__global__ void k_split(const float* __restrict__ query, const float* __restrict__ key,
                        const float* __restrict__ value) {
    int t = blockIdx.x, bh = blockIdx.y, e = threadIdx.x;
    int b = bh >> 3, hh = bh & 7;
    size_t gi = ((size_t)(b*NTOK + t))*DM + hh*EH + e;
    float qv = query[gi], kv = key[gi], vv = value[gi];
    size_t oi = ((size_t)bh*NTOK + t)*EH + e;
    g_q[oi] = qv; g_k[oi] = kv; g_v[oi] = vv;
    float q2 = qv*qv, k2 = kv*kv;
    #pragma unroll
    for (int o = 16; o; o >>= 1) {
        q2 += __shfl_down_sync(0xffffffffu, q2, o);
        k2 += __shfl_down_sync(0xffffffffu, k2, o);
    }
    __shared__ float sq[2], sk[2];
    if ((e & 31) == 0) { sq[e>>5] = q2; sk[e>>5] = k2; }
    __syncthreads();
    if (e == 0) {
        g_qn2[bh*NTOK + t] = sq[0] + sq[1];
        g_kn2[bh*NTOK + t] = sk[0] + sk[1];
    }
}

// ---------------- K2: per-bh max squared norms ----------------
__global__ void k_maxn() {
    int bh = blockIdx.x, tid = threadIdx.x;
    float mq = 0.f, mk = 0.f;
    for (int i = tid; i < NTOK; i += 256) {
        mq = fmaxf(mq, g_qn2[bh*NTOK + i]);
        mk = fmaxf(mk, g_kn2[bh*NTOK + i]);
    }
    #pragma unroll
    for (int o = 16; o; o >>= 1) {
        mq = fmaxf(mq, __shfl_xor_sync(0xffffffffu, mq, o));
        mk = fmaxf(mk, __shfl_xor_sync(0xffffffffu, mk, o));
    }
    __shared__ float sq[8], sk[8];
    if ((tid & 31) == 0) { sq[tid>>5] = mq; sk[tid>>5] = mk; }
    __syncthreads();
    if (tid == 0) {
        float a = sq[0], b = sk[0];
        for (int w = 1; w < 8; w++) { a = fmaxf(a, sq[w]); b = fmaxf(b, sk[w]); }
        g_MQ2[bh] = a; g_MK2[bh] = b;
    }
}

// ---------------- K3: LSH hashes ----------------
__global__ void k_hash(const float* __restrict__ alpha, const float* __restrict__ beta) {
    int bh = blockIdx.y;
    int t = blockIdx.x*256 + threadIdx.x;
    const float* qr = g_q + ((size_t)bh*NTOK + t)*EH;
    const float* kr = g_k + ((size_t)bh*NTOK + t)*EH;
    float a0 = 0.f, a1 = 0.f, c0 = 0.f, c1 = 0.f;
    #pragma unroll 8
    for (int e = 0; e < EH; e++) {
        float al0 = alpha[e*2], al1 = alpha[e*2+1];
        float qe = qr[e], ke = kr[e];
        a0 += qe*al0; a1 += qe*al1;
        c0 += ke*al0; c1 += ke*al1;
    }
    float S = g_MQ2[bh] + g_MK2[bh];
    float extq = sqrtf(fmaxf(S - g_qn2[bh*NTOK + t], 0.f));
    float extk = sqrtf(fmaxf(S - g_kn2[bh*NTOK + t], 0.f));
    g_hashq[bh*NTOK + t]           = a0 + extq*alpha[EH*2]       + beta[0];
    g_hashq[BH*NTOK + bh*NTOK + t] = a1 + extq*alpha[EH*2+1]     + beta[1];
    g_hashk[bh*NTOK + t]           = c0 + extk*alpha[(EH+1)*2]   + beta[0];
    g_hashk[BH*NTOK + bh*NTOK + t] = c1 + extk*alpha[(EH+1)*2+1] + beta[1];
}

// ---------------- K4: stable bitonic argsort ----------------
__global__ void k_sort() {
    __shared__ float sv[NTOK];
    __shared__ int   si[NTOK];
    int which = blockIdx.x >> 6;   // 0 = q, 1 = k
    int rem   = blockIdx.x & 63;   // h*BH + bh
    const float* src = which ? (g_hashk + (size_t)rem*NTOK) : (g_hashq + (size_t)rem*NTOK);
    int tid = threadIdx.x;
    for (int i = tid; i < NTOK; i += 512) { sv[i] = src[i]; si[i] = i; }
    __syncthreads();
    for (int k = 2; k <= NTOK; k <<= 1)
        for (int j = k >> 1; j > 0; j >>= 1) {
            for (int p = tid; p < NTOK/2; p += 512) {
                int i  = ((p & ~(j-1)) << 1) | (p & (j-1));
                int ix = i | j;
                bool up = ((i & k) == 0);
                float vi = sv[i], vj = sv[ix];
                int ii = si[i], ij = si[ix];
                bool agt = (vi > vj) || (vi == vj && ii > ij);
                if (agt == up) { sv[i] = vj; sv[ix] = vi; si[i] = ij; si[ix] = ii; }
            }
            __syncthreads();
        }
    int* pos = which ? g_kpos : g_qpos;
    int* rev = which ? g_krev : g_qrev;
    for (int r = tid; r < NTOK; r += 512) {
        int idx = si[r];
        pos[rem*NTOK + r]   = idx;
        rev[rem*NTOK + idx] = r;
    }
}

// ---------------- K5: performer feature maps ----------------
__global__ void k_feat(const float* __restrict__ W) {
    int bh = blockIdx.y, isK = blockIdx.z, tid = threadIdx.x;
    const float* X  = isK ? g_k   : g_q;
    const float* n2 = isK ? g_kn2 : g_qn2;
    float w[EH];
    #pragma unroll
    for (int e = 0; e < EH; e++) w[e] = W[tid*EH + e];
    __shared__ float xr[EH];
    __shared__ float wr[4];
    for (int r = 0; r < 32; r++) {
        int t = blockIdx.x*32 + r;
        if (tid < EH) xr[tid] = X[((size_t)bh*NTOK + t)*EH + tid];
        __syncthreads();
        float proj = 0.f;
        const float4* x4 = (const float4*)xr;
        #pragma unroll
        for (int e4 = 0; e4 < 16; e4++) {
            float4 xv = x4[e4];
            proj += xv.x*w[4*e4] + xv.y*w[4*e4+1] + xv.z*w[4*e4+2] + xv.w*w[4*e4+3];
        }
        float lp = proj*SQRT_TEMP - 0.5f*TEMPF*n2[bh*NTOK + t] - HALF_LOG_M;
        float mv = lp;
        #pragma unroll
        for (int o = 16; o; o >>= 1) mv = fmaxf(mv, __shfl_xor_sync(0xffffffffu, mv, o));
        if ((tid & 31) == 0) wr[tid>>5] = mv;
        __syncthreads();
        float stab = fmaxf(fmaxf(wr[0], wr[1]), fmaxf(wr[2], wr[3]));
        size_t oi = ((size_t)bh*NTOK + t)*MF + tid;
        if (!isK) {
            g_qp[oi] = __expf(lp - stab);
            if (tid == 0) g_qls[bh*NTOK + t] = stab;
        } else {
            g_kp[oi] = lp;
            if (tid == 0) g_krm[bh*NTOK + t] = stab;
        }
        __syncthreads();
    }
}

// ---------------- K6: per-bh max of k log-phi ----------------
__global__ void k_kls() {
    int bh = blockIdx.x, tid = threadIdx.x;
    float m = -1e30f;
    for (int i = tid; i < NTOK; i += 256) m = fmaxf(m, g_krm[bh*NTOK + i]);
    #pragma unroll
    for (int o = 16; o; o >>= 1) m = fmaxf(m, __shfl_xor_sync(0xffffffffu, m, o));
    __shared__ float s[8];
    if ((tid & 31) == 0) s[tid>>5] = m;
    __syncthreads();
    if (tid == 0) {
        float r = s[0];
        for (int w = 1; w < 8; w++) r = fmaxf(r, s[w]);
        g_kls[bh] = r;
    }
}

// ---------------- K7: exponentiate k features ----------------
__global__ void k_expk() {
    size_t idx = (size_t)blockIdx.x*256 + threadIdx.x;
    g_kp[idx] = __expf(g_kp[idx] - g_kls[idx / ((size_t)NTOK*MF)]);
}

// ---------------- K8: partial kv = k'^T v and column sums ----------------
__global__ void k_kvpart() {
    int ch = blockIdx.x, bh = blockIdx.y, m = threadIdx.x;
    __shared__ float sv[1024];
    float acc[EH];
    #pragma unroll
    for (int d = 0; d < EH; d++) acc[d] = 0.f;
    float ssum = 0.f;
    for (int t0 = ch*256; t0 < ch*256 + 256; t0 += 16) {
        __syncthreads();
        for (int l = m; l < 1024; l += 128)
            sv[l] = g_v[((size_t)bh*NTOK + t0 + (l>>6))*EH + (l & 63)];
        __syncthreads();
        for (int tt = 0; tt < 16; tt++) {
            float kp = g_kp[((size_t)bh*NTOK + t0 + tt)*MF + m];
            ssum += kp;
            const float4* v4 = (const float4*)(sv + tt*64);
            #pragma unroll
            for (int d4 = 0; d4 < 16; d4++) {
                float4 vv = v4[d4];
                acc[4*d4]   += kp*vv.x; acc[4*d4+1] += kp*vv.y;
                acc[4*d4+2] += kp*vv.z; acc[4*d4+3] += kp*vv.w;
            }
        }
    }
    float* dst = g_kvp + (((size_t)ch*BH + bh)*MF + m)*EH;
    #pragma unroll
    for (int d = 0; d < EH; d++) dst[d] = acc[d];
    g_ksp[(ch*BH + bh)*MF + m] = ssum;
}

// ---------------- K8b: deterministic reduce ----------------
__global__ void k_kvred() {
    int idx = blockIdx.x*256 + threadIdx.x;   // BH*MF*EH
    float s = 0.f;
    #pragma unroll
    for (int c = 0; c < NCH; c++) s += g_kvp[(size_t)c*BH*MF*EH + idx];
    g_kv[idx] = s;
    if (idx < BH*MF) {
        float ss = 0.f;
        #pragma unroll
        for (int c = 0; c < NCH; c++) ss += g_ksp[c*BH*MF + idx];
        g_ksum[idx] = ss;
    }
}

// ---------------- K9: qkv = q' kv ; qk1 = q' . ksum ----------------
__global__ __launch_bounds__(128) void k_qkv() {
    int bh = blockIdx.y, tid = threadIdx.x;
    int d = tid & 63, rr = tid >> 6;
    __shared__ float ks[MF];
    __shared__ float qpr[2*MF];
    __shared__ float r4[4];
    float kvreg[MF];
    #pragma unroll
    for (int m = 0; m < MF; m++) kvreg[m] = g_kv[((size_t)bh*MF + m)*EH + d];
    if (tid < MF) ks[tid] = g_ksum[bh*MF + tid];
    __syncthreads();
    for (int pair = 0; pair < 16; pair++) {
        int tbase = blockIdx.x*32 + pair*2;
        __syncthreads();
        for (int l = tid; l < 256; l += 128)
            qpr[l] = g_qp[((size_t)bh*NTOK + tbase + (l>>7))*MF + (l & 127)];
        __syncthreads();
        const float4* q4 = (const float4*)(qpr + rr*MF);
        float a = 0.f;
        #pragma unroll
        for (int m4 = 0; m4 < 32; m4++) {
            float4 qv = q4[m4];
            a += qv.x*kvreg[4*m4] + qv.y*kvreg[4*m4+1] + qv.z*kvreg[4*m4+2] + qv.w*kvreg[4*m4+3];
        }
        g_qkv[((size_t)bh*NTOK + tbase + rr)*EH + d] = a;
        float p = qpr[rr*MF + 2*d]*ks[2*d] + qpr[rr*MF + 2*d+1]*ks[2*d+1];
        #pragma unroll
        for (int o = 16; o; o >>= 1) p += __shfl_down_sync(0xffffffffu, p, o);
        int lane = tid & 31, wp = tid >> 5;
        if (lane == 0) r4[wp] = p;
        __syncthreads();
        if (tid == 0)  g_qk1[bh*NTOK + tbase]     = r4[0] + r4[1];
        if (tid == 64) g_qk1[bh*NTOK + tbase + 1] = r4[2] + r4[3];
    }
}

// ---------------- K10: fused bucketed exact-attention correction ----------------
#define BKT_SMEM_FLOATS (2*128*TSTRIDE + 128 + 4*128)

__global__ __launch_bounds__(256, 1) void k_bucket() {
    extern __shared__ float sm[];
    float* sPls = sm + 2*128*TSTRIDE;
    int* sQi = (int*)(sPls + 128);
    int* sKi = sQi + 128;
    int* sQb = sKi + 128;
    int* sKb = sQb + 128;

    int nb = blockIdx.x, bh = blockIdx.y, h = blockIdx.z;
    int tid = threadIdx.x, tx = tid & 15, ty = tid >> 4;
    int o = 1 - h;

    if (tid < 128) {
        int qi = g_qpos[(h*BH + bh)*NTOK + nb*128 + tid];
        int ki = g_kpos[(h*BH + bh)*NTOK + nb*128 + tid];
        sQi[tid] = qi; sKi[tid] = ki;
        sQb[tid] = g_qrev[(o*BH + bh)*NTOK + qi] >> 7;
        sKb[tid] = g_krev[(o*BH + bh)*NTOK + ki] >> 7;
        sPls[tid] = g_qls[bh*NTOK + qi] + g_kls[bh];
    }
    __syncthreads();

    // ---- Phase A: inner = q k^T ----
    float* sQt = sm;                   // [64][TSTRIDE]
    float* sKt = sm + 64*TSTRIDE;
    for (int idx = tid; idx < 8192; idx += 256) {
        int i = idx >> 6, e = idx & 63;
        sQt[e*TSTRIDE + i] = g_q[((size_t)bh*NTOK + sQi[i])*EH + e];
        sKt[e*TSTRIDE + i] = g_k[((size_t)bh*NTOK + sKi[i])*EH + e];
    }
    __syncthreads();
    float accI[8][8];
    #pragma unroll
    for (int r = 0; r < 8; r++)
        #pragma unroll
        for (int c = 0; c < 8; c++) accI[r][c] = 0.f;
    for (int e = 0; e < 64; e++) {
        float a[8], b[8];
        float4 t0 = *(const float4*)(sQt + e*TSTRIDE + ty*8);
        float4 t1 = *(const float4*)(sQt + e*TSTRIDE + ty*8 + 4);
        a[0]=t0.x; a[1]=t0.y; a[2]=t0.z; a[3]=t0.w; a[4]=t1.x; a[5]=t1.y; a[6]=t1.z; a[7]=t1.w;
        float4 u0 = *(const float4*)(sKt + e*TSTRIDE + tx*8);
        float4 u1 = *(const float4*)(sKt + e*TSTRIDE + tx*8 + 4);
        b[0]=u0.x; b[1]=u0.y; b[2]=u0.z; b[3]=u0.w; b[4]=u1.x; b[5]=u1.y; b[6]=u1.z; b[7]=u1.w;
        #pragma unroll
        for (int r = 0; r < 8; r++)
            #pragma unroll
            for (int c = 0; c < 8; c++) accI[r][c] += a[r]*b[c];
    }
    __syncthreads();

    // ---- Phase B: dots_prime = q' k'^T ----
    float* sQPt = sm;                  // [128][TSTRIDE]
    float* sKPt = sm + 128*TSTRIDE;
    for (int idx = tid; idx < 16384; idx += 256) {
        int i = idx >> 7, m = idx & 127;
        sQPt[m*TSTRIDE + i] = g_qp[((size_t)bh*NTOK + sQi[i])*MF + m];
        sKPt[m*TSTRIDE + i] = g_kp[((size_t)bh*NTOK + sKi[i])*MF + m];
    }
    __syncthreads();
    float accP[8][8];
    #pragma unroll
    for (int r = 0; r < 8; r++)
        #pragma unroll
        for (int c = 0; c < 8; c++) accP[r][c] = 0.f;
    for (int m = 0; m < 128; m++) {
        float a[8], b[8];
        float4 t0 = *(const float4*)(sQPt + m*TSTRIDE + ty*8);
        float4 t1 = *(const float4*)(sQPt + m*TSTRIDE + ty*8 + 4);
        a[0]=t0.x; a[1]=t0.y; a[2]=t0.z; a[3]=t0.w; a[4]=t1.x; a[5]=t1.y; a[6]=t1.z; a[7]=t1.w;
        float4 u0 = *(const float4*)(sKPt + m*TSTRIDE + tx*8);
        float4 u1 = *(const float4*)(sKPt + m*TSTRIDE + tx*8 + 4);
        b[0]=u0.x; b[1]=u0.y; b[2]=u0.z; b[3]=u0.w; b[4]=u1.x; b[5]=u1.y; b[6]=u1.z; b[7]=u1.w;
        #pragma unroll
        for (int r = 0; r < 8; r++)
            #pragma unroll
            for (int c = 0; c < 8; c++) accP[r][c] += a[r]*b[c];
    }
    __syncthreads();

    // ---- Epilogue: dup correction, LSE, exp, dots to smem ----
    float* sD = sm;                    // [128][TSTRIDE]
    float* sV = sm + 128*TSTRIDE;      // [128][68]
    int qb[8], kb[8]; float pls[8];
    #pragma unroll
    for (int r = 0; r < 8; r++) { qb[r] = sQb[ty*8 + r]; pls[r] = sPls[ty*8 + r]; }
    #pragma unroll
    for (int c = 0; c < 8; c++) kb[c] = sKb[tx*8 + c];
    float lse[8], dsum[8];
    #pragma unroll
    for (int r = 0; r < 8; r++) {
        float rm = -1e30f;
        #pragma unroll
        for (int c = 0; c < 8; c++) {
            bool d2 = (qb[r] == kb[c]);
            float in = accI[r][c]*TEMPF - (d2 ? LN2F : 0.f);
            accI[r][c] = in;
            accP[r][c] *= d2 ? 0.5f : 1.f;
            rm = fmaxf(rm, in);
        }
        #pragma unroll
        for (int off = 8; off; off >>= 1) rm = fmaxf(rm, __shfl_xor_sync(0xffffffffu, rm, off));
        float l = fmaxf(rm, pls[r]);
        lse[r] = l;
        float pe = __expf(pls[r] - l);
        float s = 0.f;
        #pragma unroll
        for (int c = 0; c < 8; c++) {
            float dv = __expf(accI[r][c] - l) - accP[r][c]*pe;
            sD[(ty*8 + r)*TSTRIDE + tx*8 + c] = dv;
            s += dv;
        }
        #pragma unroll
        for (int off = 8; off; off >>= 1) s += __shfl_xor_sync(0xffffffffu, s, off);
        dsum[r] = s;
    }
    if (tx == 0) {
        #pragma unroll
        for (int r = 0; r < 8; r++) {
            int t = sQi[ty*8 + r];
            size_t bi = (size_t)(h*BH + bh)*NTOK + t;
            g_lseb[bi] = lse[r];
            g_dsb[bi]  = dsum[r];
        }
    }
    // gather V (overwrites old sKPt region; safe after sync above)
    for (int idx = tid; idx < 8192; idx += 256) {
        int i = idx >> 6, d = idx & 63;
        sV[i*68 + d] = g_v[((size_t)bh*NTOK + sKi[i])*EH + d];
    }
    __syncthreads();

    // ---- Phase C: so = dots @ V, scatter to unsorted order ----
    float accO[8][4];
    #pragma unroll
    for (int r = 0; r < 8; r++)
        #pragma unroll
        for (int c = 0; c < 4; c++) accO[r][c] = 0.f;
    for (int j = 0; j < 128; j++) {
        float4 bv = *(const float4*)(sV + j*68 + tx*4);
        #pragma unroll
        for (int r = 0; r < 8; r++) {
            float av = sD[(ty*8 + r)*TSTRIDE + j];
            accO[r][0] += av*bv.x; accO[r][1] += av*bv.y;
            accO[r][2] += av*bv.z; accO[r][3] += av*bv.w;
        }
    }
    #pragma unroll
    for (int r = 0; r < 8; r++) {
        int t = sQi[ty*8 + r];
        float4 ov; ov.x = accO[r][0]; ov.y = accO[r][1]; ov.z = accO[r][2]; ov.w = accO[r][3];
        *(float4*)(g_ob + ((size_t)(h*BH + bh)*NTOK + t)*EH + tx*4) = ov;
    }
}

// ---------------- K11: merge performer + LSH branches ----------------
__global__ void k_merge() {
    int tid = threadIdx.x;
    int t = blockIdx.x*4 + (tid >> 6);
    int d = tid & 63;
    int bh = blockIdx.y;
    size_t i0 = (size_t)bh*NTOK + t;
    size_t i1 = (size_t)(BH + bh)*NTOK + t;
    float l0 = g_lseb[i0], l1 = g_lseb[i1];
    float mx = fmaxf(l0, l1);
    float norm = mx + logf(__expf(l0 - mx) + __expf(l1 - mx));
    float p0 = __expf(l0 - norm), p1 = __expf(l1 - norm);
    float pls = g_qls[bh*NTOK + t] + g_kls[bh];
    float psc = __expf(pls - norm);
    float z = g_dsb[i0]*p0 + g_dsb[i1]*p1 + g_qk1[bh*NTOK + t]*psc;
    z = fmaxf(z, 1e-6f);
    size_t base = ((size_t)bh*NTOK + t)*EH + d;
    float outv = g_ob[i0*EH + d]*p0 + g_ob[i1*EH + d]*p1 + g_qkv[base]*psc;
    g_on[base] = outv / z;
}

// ---------------- K12: final projection ----------------
__global__ __launch_bounds__(256) void k_final(const float* __restrict__ Wf,
                                               const float* __restrict__ bias,
                                               float* __restrict__ out) {
    __shared__ float sW[128*68];
    __shared__ float sX[4*128];
    int tid = threadIdx.x;
    int tok = tid >> 6, eo = tid & 63;
    int g0 = blockIdx.x*4;
    float acc = 0.f;
    for (int c = 0; c < 4; c++) {
        __syncthreads();
        for (int idx = tid; idx < 8192; idx += 256) {
            int e2 = idx >> 7, hd = idx & 127;
            sW[hd*68 + e2] = Wf[e2*512 + c*128 + hd];
        }
        for (int idx = tid; idx < 512; idx += 256) {
            int tk = idx >> 7, hd = idx & 127;
            int gg = g0 + tk;
            int b = gg >> 12, t = gg & 4095;
            int hdg = c*128 + hd;
            sX[tk*128 + hd] = g_on[(((size_t)(b*8 + (hdg >> 6)))*NTOK + t)*EH + (hdg & 63)];
        }
        __syncthreads();
        const float4* x4 = (const float4*)(sX + tok*128);
        #pragma unroll
        for (int h4 = 0; h4 < 32; h4++) {
            float4 xv = x4[h4];
            acc += xv.x*sW[(4*h4)*68 + eo]   + xv.y*sW[(4*h4+1)*68 + eo]
                 + xv.z*sW[(4*h4+2)*68 + eo] + xv.w*sW[(4*h4+3)*68 + eo];
        }
    }
    out[(size_t)(g0 + tok)*EH + eo] = acc + bias[eo];
}

// ---------------- launch ----------------
extern "C" void kernel_launch(void* const* d_in, const int* in_sizes, int n_in,
                              void* d_out, int out_size) {
    const float* query = (const float*)d_in[0];
    const float* key   = (const float*)d_in[1];
    const float* value = (const float*)d_in[2];
    const float* projW = (const float*)d_in[3];
    const float* alpha = (const float*)d_in[4];
    const float* beta  = (const float*)d_in[5];
    const float* outW  = (const float*)d_in[6];
    const float* outb  = (const float*)d_in[7];
    float* out = (float*)d_out;

    cudaFuncSetAttribute(k_bucket, cudaFuncAttributeMaxDynamicSharedMemorySize,
                         BKT_SMEM_FLOATS*4);

    k_split<<<dim3(NTOK, BH), 64>>>(query, key, value);
    k_maxn<<<BH, 256>>>();
    k_hash<<<dim3(NTOK/256, BH), 256>>>(alpha, beta);
    k_sort<<<128, 512>>>();
    k_feat<<<dim3(NTOK/32, BH, 2), 128>>>(projW);
    k_kls<<<BH, 256>>>();
    k_expk<<<BH*NTOK*MF/256, 256>>>();
    k_kvpart<<<dim3(NCH, BH), 128>>>();
    k_kvred<<<BH*MF*EH/256, 256>>>();
    k_qkv<<<dim3(NTOK/32, BH), 128>>>();
    k_bucket<<<dim3(32, BH, 2), 256, BKT_SMEM_FLOATS*4>>>();
    k_merge<<<dim3(NTOK/4, BH), 256>>>();
    k_final<<<(4*NTOK)/4, 256>>>(outW, outb, out);
}

// round 3
// speedup vs baseline: 1.0909x; 1.0909x over previous
#include <cuda_runtime.h>
#include <math.h>

#define BH 32
#define NTOK 4096
#define EH 64
#define MF 128
#define DM 512
#define NCH 32
#define TSTRIDE 144

#define SQRT_TEMP 0.35355339059327373f
#define TEMPF 0.125f
#define HALF_LOG_M 2.4260151319598084f
#define LN2F 0.6931471805599453f

// ---------------- scratch ----------------
__device__ float g_q[BH*NTOK*EH];
__device__ float g_k[BH*NTOK*EH];
__device__ float g_v[BH*NTOK*EH];
__device__ float g_qn2[BH*NTOK];
__device__ float g_kn2[BH*NTOK];
__device__ float g_MQ2[BH];
__device__ float g_MK2[BH];
__device__ float g_hashq[2*BH*NTOK];
__device__ float g_hashk[2*BH*NTOK];
__device__ int   g_qpos[2*BH*NTOK];
__device__ int   g_kpos[2*BH*NTOK];
__device__ int   g_qrev[2*BH*NTOK];
__device__ int   g_krev[2*BH*NTOK];
__device__ float g_qp[(size_t)BH*NTOK*MF];
__device__ float g_kp[(size_t)BH*NTOK*MF];
__device__ float g_qls[BH*NTOK];
__device__ float g_krm[BH*NTOK];
__device__ float g_kls[BH];
__device__ float g_kvp[(size_t)NCH*BH*MF*EH];
__device__ float g_ksp[NCH*BH*MF];
__device__ float g_kv[BH*MF*EH];
__device__ float g_ksum[BH*MF];
__device__ float g_qk1[BH*NTOK];
__device__ float g_qkv[(size_t)BH*NTOK*EH];
__device__ float g_ob[(size_t)2*BH*NTOK*EH];
__device__ float g_lseb[2*BH*NTOK];
__device__ float g_dsb[2*BH*NTOK];
__device__ float g_on[(size_t)BH*NTOK*EH];

// ---------------- K1: split heads + squared norms (4 tokens/block) ----------------
__global__ __launch_bounds__(256) void k_split(const float* __restrict__ query,
                                               const float* __restrict__ key,
                                               const float* __restrict__ value) {
    int tid = threadIdx.x;
    int tl = tid >> 6, e = tid & 63;
    int t = blockIdx.x*4 + tl, bh = blockIdx.y;
    int b = bh >> 3, hh = bh & 7;
    size_t gi = ((size_t)(b*NTOK + t))*DM + hh*EH + e;
    float qv = query[gi], kv = key[gi], vv = value[gi];
    size_t oi = ((size_t)bh*NTOK + t)*EH + e;
    g_q[oi] = qv; g_k[oi] = kv; g_v[oi] = vv;
    float q2 = qv*qv, k2 = kv*kv;
    #pragma unroll
    for (int o = 16; o; o >>= 1) {
        q2 += __shfl_down_sync(0xffffffffu, q2, o);
        k2 += __shfl_down_sync(0xffffffffu, k2, o);
    }
    __shared__ float sq[8], sk[8];
    if ((tid & 31) == 0) { sq[tid>>5] = q2; sk[tid>>5] = k2; }
    __syncthreads();
    if (e == 0) {
        g_qn2[bh*NTOK + t] = sq[2*tl] + sq[2*tl+1];
        g_kn2[bh*NTOK + t] = sk[2*tl] + sk[2*tl+1];
    }
}

// ---------------- K2: per-bh max squared norms ----------------
__global__ void k_maxn() {
    int bh = blockIdx.x, tid = threadIdx.x;
    float mq = 0.f, mk = 0.f;
    for (int i = tid; i < NTOK; i += 256) {
        mq = fmaxf(mq, g_qn2[bh*NTOK + i]);
        mk = fmaxf(mk, g_kn2[bh*NTOK + i]);
    }
    #pragma unroll
    for (int o = 16; o; o >>= 1) {
        mq = fmaxf(mq, __shfl_xor_sync(0xffffffffu, mq, o));
        mk = fmaxf(mk, __shfl_xor_sync(0xffffffffu, mk, o));
    }
    __shared__ float sq[8], sk[8];
    if ((tid & 31) == 0) { sq[tid>>5] = mq; sk[tid>>5] = mk; }
    __syncthreads();
    if (tid == 0) {
        float a = sq[0], b = sk[0];
        for (int w = 1; w < 8; w++) { a = fmaxf(a, sq[w]); b = fmaxf(b, sk[w]); }
        g_MQ2[bh] = a; g_MK2[bh] = b;
    }
}

// ---------------- K3: LSH hashes ----------------
__global__ void k_hash(const float* __restrict__ alpha, const float* __restrict__ beta) {
    int bh = blockIdx.y;
    int t = blockIdx.x*256 + threadIdx.x;
    const float* qr = g_q + ((size_t)bh*NTOK + t)*EH;
    const float* kr = g_k + ((size_t)bh*NTOK + t)*EH;
    float a0 = 0.f, a1 = 0.f, c0 = 0.f, c1 = 0.f;
    #pragma unroll 8
    for (int e = 0; e < EH; e++) {
        float al0 = alpha[e*2], al1 = alpha[e*2+1];
        float qe = qr[e], ke = kr[e];
        a0 += qe*al0; a1 += qe*al1;
        c0 += ke*al0; c1 += ke*al1;
    }
    float S = g_MQ2[bh] + g_MK2[bh];
    float extq = sqrtf(fmaxf(S - g_qn2[bh*NTOK + t], 0.f));
    float extk = sqrtf(fmaxf(S - g_kn2[bh*NTOK + t], 0.f));
    g_hashq[bh*NTOK + t]           = a0 + extq*alpha[EH*2]       + beta[0];
    g_hashq[BH*NTOK + bh*NTOK + t] = a1 + extq*alpha[EH*2+1]     + beta[1];
    g_hashk[bh*NTOK + t]           = c0 + extk*alpha[(EH+1)*2]   + beta[0];
    g_hashk[BH*NTOK + bh*NTOK + t] = c1 + extk*alpha[(EH+1)*2+1] + beta[1];
}

// ---------------- K4: stable bitonic argsort ----------------
__global__ void k_sort() {
    __shared__ float sv[NTOK];
    __shared__ int   si[NTOK];
    int which = blockIdx.x >> 6;
    int rem   = blockIdx.x & 63;
    const float* src = which ? (g_hashk + (size_t)rem*NTOK) : (g_hashq + (size_t)rem*NTOK);
    int tid = threadIdx.x;
    for (int i = tid; i < NTOK; i += 512) { sv[i] = src[i]; si[i] = i; }
    __syncthreads();
    for (int k = 2; k <= NTOK; k <<= 1)
        for (int j = k >> 1; j > 0; j >>= 1) {
            for (int p = tid; p < NTOK/2; p += 512) {
                int i  = ((p & ~(j-1)) << 1) | (p & (j-1));
                int ix = i | j;
                bool up = ((i & k) == 0);
                float vi = sv[i], vj = sv[ix];
                int ii = si[i], ij = si[ix];
                bool agt = (vi > vj) || (vi == vj && ii > ij);
                if (agt == up) { sv[i] = vj; sv[ix] = vi; si[i] = ij; si[ix] = ii; }
            }
            __syncthreads();
        }
    int* pos = which ? g_kpos : g_qpos;
    int* rev = which ? g_krev : g_qrev;
    for (int r = tid; r < NTOK; r += 512) {
        int idx = si[r];
        pos[rem*NTOK + r]   = idx;
        rev[rem*NTOK + idx] = r;
    }
}

// ---------------- K5: performer feature maps (2 tokens/iter) ----------------
__global__ __launch_bounds__(256) void k_feat(const float* __restrict__ W) {
    int bh = blockIdx.y, isK = blockIdx.z, tid = threadIdx.x;
    int tok = tid >> 7, f = tid & 127;
    const float* X  = isK ? g_k   : g_q;
    const float* n2 = isK ? g_kn2 : g_qn2;
    float w[EH];
    #pragma unroll
    for (int e = 0; e < EH; e++) w[e] = W[f*EH + e];
    __shared__ float xr[2][EH];
    __shared__ float wr[8];
    for (int it = 0; it < 16; it++) {
        int tb = blockIdx.x*32 + it*2;
        int t = tb + tok;
        if (tid < 128) xr[tid>>6][tid&63] = X[((size_t)bh*NTOK + tb + (tid>>6))*EH + (tid&63)];
        __syncthreads();
        float proj = 0.f;
        const float4* x4 = (const float4*)xr[tok];
        #pragma unroll
        for (int e4 = 0; e4 < 16; e4++) {
            float4 xv = x4[e4];
            proj += xv.x*w[4*e4] + xv.y*w[4*e4+1] + xv.z*w[4*e4+2] + xv.w*w[4*e4+3];
        }
        float lp = proj*SQRT_TEMP - 0.5f*TEMPF*n2[bh*NTOK + t] - HALF_LOG_M;
        float mv = lp;
        #pragma unroll
        for (int o = 16; o; o >>= 1) mv = fmaxf(mv, __shfl_xor_sync(0xffffffffu, mv, o));
        if ((tid & 31) == 0) wr[tid>>5] = mv;
        __syncthreads();
        float stab = fmaxf(fmaxf(wr[tok*4], wr[tok*4+1]), fmaxf(wr[tok*4+2], wr[tok*4+3]));
        size_t oi = ((size_t)bh*NTOK + t)*MF + f;
        if (!isK) {
            g_qp[oi] = __expf(lp - stab);
            if (f == 0) g_qls[bh*NTOK + t] = stab;
        } else {
            g_kp[oi] = lp;
            if (f == 0) g_krm[bh*NTOK + t] = stab;
        }
    }
}

// ---------------- K6: per-bh max of k log-phi ----------------
__global__ void k_kls() {
    int bh = blockIdx.x, tid = threadIdx.x;
    float m = -1e30f;
    for (int i = tid; i < NTOK; i += 256) m = fmaxf(m, g_krm[bh*NTOK + i]);
    #pragma unroll
    for (int o = 16; o; o >>= 1) m = fmaxf(m, __shfl_xor_sync(0xffffffffu, m, o));
    __shared__ float s[8];
    if ((tid & 31) == 0) s[tid>>5] = m;
    __syncthreads();
    if (tid == 0) {
        float r = s[0];
        for (int w = 1; w < 8; w++) r = fmaxf(r, s[w]);
        g_kls[bh] = r;
    }
}

// ---------------- K7: exponentiate k features ----------------
__global__ void k_expk() {
    int bh = blockIdx.y;
    size_t idx = (size_t)bh*NTOK*MF + blockIdx.x*256 + threadIdx.x;
    g_kp[idx] = __expf(g_kp[idx] - g_kls[bh]);
}

// ---------------- K8: partial kv = k'^T v and column sums ----------------
__global__ __launch_bounds__(128) void k_kvpart() {
    int ch = blockIdx.x, bh = blockIdx.y, m = threadIdx.x;
    __shared__ float sv[1024];
    float acc[EH];
    #pragma unroll
    for (int d = 0; d < EH; d++) acc[d] = 0.f;
    float ssum = 0.f;
    for (int t0 = ch*(NTOK/NCH); t0 < (ch+1)*(NTOK/NCH); t0 += 16) {
        __syncthreads();
        for (int l = m; l < 1024; l += 128)
            sv[l] = g_v[((size_t)bh*NTOK + t0 + (l>>6))*EH + (l & 63)];
        __syncthreads();
        for (int tt = 0; tt < 16; tt++) {
            float kp = g_kp[((size_t)bh*NTOK + t0 + tt)*MF + m];
            ssum += kp;
            const float4* v4 = (const float4*)(sv + tt*64);
            #pragma unroll
            for (int d4 = 0; d4 < 16; d4++) {
                float4 vv = v4[d4];
                acc[4*d4]   += kp*vv.x; acc[4*d4+1] += kp*vv.y;
                acc[4*d4+2] += kp*vv.z; acc[4*d4+3] += kp*vv.w;
            }
        }
    }
    float* dst = g_kvp + (((size_t)ch*BH + bh)*MF + m)*EH;
    #pragma unroll
    for (int d = 0; d < EH; d++) dst[d] = acc[d];
    g_ksp[(ch*BH + bh)*MF + m] = ssum;
}

// ---------------- K8b: deterministic reduce ----------------
__global__ void k_kvred() {
    int idx = blockIdx.x*256 + threadIdx.x;
    float s = 0.f;
    #pragma unroll
    for (int c = 0; c < NCH; c++) s += g_kvp[(size_t)c*BH*MF*EH + idx];
    g_kv[idx] = s;
    if (idx < BH*MF) {
        float ss = 0.f;
        #pragma unroll
        for (int c = 0; c < NCH; c++) ss += g_ksp[c*BH*MF + idx];
        g_ksum[idx] = ss;
    }
}

// ---------------- K9: qkv = q' kv ; qk1 = q' . ksum ----------------
__global__ __launch_bounds__(128) void k_qkv() {
    int bh = blockIdx.y, tid = threadIdx.x;
    int d = tid & 63, rr = tid >> 6;
    __shared__ float ks[MF];
    __shared__ float qpr[2*MF];
    __shared__ float r4[4];
    float kvreg[MF];
    #pragma unroll
    for (int m = 0; m < MF; m++) kvreg[m] = g_kv[((size_t)bh*MF + m)*EH + d];
    if (tid < MF) ks[tid] = g_ksum[bh*MF + tid];
    __syncthreads();
    for (int pair = 0; pair < 16; pair++) {
        int tbase = blockIdx.x*32 + pair*2;
        __syncthreads();
        for (int l = tid; l < 256; l += 128)
            qpr[l] = g_qp[((size_t)bh*NTOK + tbase + (l>>7))*MF + (l & 127)];
        __syncthreads();
        const float4* q4 = (const float4*)(qpr + rr*MF);
        float a = 0.f;
        #pragma unroll
        for (int m4 = 0; m4 < 32; m4++) {
            float4 qv = q4[m4];
            a += qv.x*kvreg[4*m4] + qv.y*kvreg[4*m4+1] + qv.z*kvreg[4*m4+2] + qv.w*kvreg[4*m4+3];
        }
        g_qkv[((size_t)bh*NTOK + tbase + rr)*EH + d] = a;
        float p = qpr[rr*MF + 2*d]*ks[2*d] + qpr[rr*MF + 2*d+1]*ks[2*d+1];
        #pragma unroll
        for (int o = 16; o; o >>= 1) p += __shfl_down_sync(0xffffffffu, p, o);
        int lane = tid & 31, wp = tid >> 5;
        if (lane == 0) r4[wp] = p;
        __syncthreads();
        if (tid == 0)  g_qk1[bh*NTOK + tbase]     = r4[0] + r4[1];
        if (tid == 64) g_qk1[bh*NTOK + tbase + 1] = r4[2] + r4[3];
    }
}

// ---------------- K10: fused bucketed exact-attention correction ----------------
#define BKT_SMEM_FLOATS (2*128*TSTRIDE + 128 + 4*128)

__global__ __launch_bounds__(512, 1) void k_bucket() {
    extern __shared__ float sm[];
    float* sPls = sm + 2*128*TSTRIDE;
    int* sQi = (int*)(sPls + 128);
    int* sKi = sQi + 128;
    int* sQb = sKi + 128;
    int* sKb = sQb + 128;

    int nb = blockIdx.x, bh = blockIdx.y, h = blockIdx.z;
    int tid = threadIdx.x, tx = tid & 31, ty = tid >> 5;
    int o = 1 - h;

    if (tid < 128) {
        int qi = g_qpos[(h*BH + bh)*NTOK + nb*128 + tid];
        int ki = g_kpos[(h*BH + bh)*NTOK + nb*128 + tid];
        sQi[tid] = qi; sKi[tid] = ki;
        sQb[tid] = g_qrev[(o*BH + bh)*NTOK + qi] >> 7;
        sKb[tid] = g_krev[(o*BH + bh)*NTOK + ki] >> 7;
        sPls[tid] = g_qls[bh*NTOK + qi] + g_kls[bh];
    }
    __syncthreads();

    // ---- Phase A: inner = q k^T ----
    float* sQt = sm;                    // [64][TSTRIDE]
    float* sKt = sm + 64*TSTRIDE;
    for (int idx = tid; idx < 8192; idx += 512) {
        int i = idx >> 6, e = idx & 63;
        sQt[e*TSTRIDE + i] = g_q[((size_t)bh*NTOK + sQi[i])*EH + e];
        sKt[e*TSTRIDE + i] = g_k[((size_t)bh*NTOK + sKi[i])*EH + e];
    }
    __syncthreads();
    float accI[8][4];
    #pragma unroll
    for (int r = 0; r < 8; r++)
        #pragma unroll
        for (int c = 0; c < 4; c++) accI[r][c] = 0.f;
    for (int e = 0; e < 64; e++) {
        float a[8], b[4];
        float4 t0 = *(const float4*)(sQt + e*TSTRIDE + ty*8);
        float4 t1 = *(const float4*)(sQt + e*TSTRIDE + ty*8 + 4);
        a[0]=t0.x; a[1]=t0.y; a[2]=t0.z; a[3]=t0.w; a[4]=t1.x; a[5]=t1.y; a[6]=t1.z; a[7]=t1.w;
        float4 u0 = *(const float4*)(sKt + e*TSTRIDE + tx*4);
        b[0]=u0.x; b[1]=u0.y; b[2]=u0.z; b[3]=u0.w;
        #pragma unroll
        for (int r = 0; r < 8; r++)
            #pragma unroll
            for (int c = 0; c < 4; c++) accI[r][c] += a[r]*b[c];
    }
    __syncthreads();

    // ---- Phase B: dots_prime = q' k'^T ----
    float* sQPt = sm;                   // [128][TSTRIDE]
    float* sKPt = sm + 128*TSTRIDE;
    for (int idx = tid; idx < 16384; idx += 512) {
        int i = idx >> 7, m = idx & 127;
        sQPt[m*TSTRIDE + i] = g_qp[((size_t)bh*NTOK + sQi[i])*MF + m];
        sKPt[m*TSTRIDE + i] = g_kp[((size_t)bh*NTOK + sKi[i])*MF + m];
    }
    __syncthreads();
    float accP[8][4];
    #pragma unroll
    for (int r = 0; r < 8; r++)
        #pragma unroll
        for (int c = 0; c < 4; c++) accP[r][c] = 0.f;
    for (int m = 0; m < 128; m++) {
        float a[8], b[4];
        float4 t0 = *(const float4*)(sQPt + m*TSTRIDE + ty*8);
        float4 t1 = *(const float4*)(sQPt + m*TSTRIDE + ty*8 + 4);
        a[0]=t0.x; a[1]=t0.y; a[2]=t0.z; a[3]=t0.w; a[4]=t1.x; a[5]=t1.y; a[6]=t1.z; a[7]=t1.w;
        float4 u0 = *(const float4*)(sKPt + m*TSTRIDE + tx*4);
        b[0]=u0.x; b[1]=u0.y; b[2]=u0.z; b[3]=u0.w;
        #pragma unroll
        for (int r = 0; r < 8; r++)
            #pragma unroll
            for (int c = 0; c < 4; c++) accP[r][c] += a[r]*b[c];
    }
    __syncthreads();

    // ---- Epilogue: dup correction, LSE, exp, dots to smem ----
    float* sD = sm;                     // [128][TSTRIDE]
    float* sV = sm + 128*TSTRIDE;       // [128][68]
    int qb[8], kb[4]; float pls[8];
    #pragma unroll
    for (int r = 0; r < 8; r++) { qb[r] = sQb[ty*8 + r]; pls[r] = sPls[ty*8 + r]; }
    #pragma unroll
    for (int c = 0; c < 4; c++) kb[c] = sKb[tx*4 + c];
    float lse[8], dsum[8];
    #pragma unroll
    for (int r = 0; r < 8; r++) {
        float rm = -1e30f;
        #pragma unroll
        for (int c = 0; c < 4; c++) {
            bool d2 = (qb[r] == kb[c]);
            float in = accI[r][c]*TEMPF - (d2 ? LN2F : 0.f);
            accI[r][c] = in;
            accP[r][c] *= d2 ? 0.5f : 1.f;
            rm = fmaxf(rm, in);
        }
        #pragma unroll
        for (int off = 16; off; off >>= 1) rm = fmaxf(rm, __shfl_xor_sync(0xffffffffu, rm, off));
        float l = fmaxf(rm, pls[r]);
        lse[r] = l;
        float pe = __expf(pls[r] - l);
        float4 dv;
        dv.x = __expf(accI[r][0] - l) - accP[r][0]*pe;
        dv.y = __expf(accI[r][1] - l) - accP[r][1]*pe;
        dv.z = __expf(accI[r][2] - l) - accP[r][2]*pe;
        dv.w = __expf(accI[r][3] - l) - accP[r][3]*pe;
        *(float4*)(sD + (ty*8 + r)*TSTRIDE + tx*4) = dv;
        float s = dv.x + dv.y + dv.z + dv.w;
        #pragma unroll
        for (int off = 16; off; off >>= 1) s += __shfl_xor_sync(0xffffffffu, s, off);
        dsum[r] = s;
    }
    if (tx == 0) {
        #pragma unroll
        for (int r = 0; r < 8; r++) {
            int t = sQi[ty*8 + r];
            size_t bi = (size_t)(h*BH + bh)*NTOK + t;
            g_lseb[bi] = lse[r];
            g_dsb[bi]  = dsum[r];
        }
    }
    for (int idx = tid; idx < 8192; idx += 512) {
        int i = idx >> 6, d = idx & 63;
        sV[i*68 + d] = g_v[((size_t)bh*NTOK + sKi[i])*EH + d];
    }
    __syncthreads();

    // ---- Phase C: so = dots @ V, scatter to unsorted order ----
    int tx2 = tid & 15, ty2 = tid >> 4;   // d = tx2*4, rows = ty2*4..+3
    float accO[4][4];
    #pragma unroll
    for (int r = 0; r < 4; r++)
        #pragma unroll
        for (int c = 0; c < 4; c++) accO[r][c] = 0.f;
    for (int j0 = 0; j0 < 128; j0 += 4) {
        float av[4][4], bv[4][4];
        #pragma unroll
        for (int r = 0; r < 4; r++) {
            float4 t = *(const float4*)(sD + (ty2*4 + r)*TSTRIDE + j0);
            av[r][0]=t.x; av[r][1]=t.y; av[r][2]=t.z; av[r][3]=t.w;
        }
        #pragma unroll
        for (int jj = 0; jj < 4; jj++) {
            float4 t = *(const float4*)(sV + (j0 + jj)*68 + tx2*4);
            bv[jj][0]=t.x; bv[jj][1]=t.y; bv[jj][2]=t.z; bv[jj][3]=t.w;
        }
        #pragma unroll
        for (int r = 0; r < 4; r++)
            #pragma unroll
            for (int jj = 0; jj < 4; jj++)
                #pragma unroll
                for (int c = 0; c < 4; c++) accO[r][c] += av[r][jj]*bv[jj][c];
    }
    #pragma unroll
    for (int r = 0; r < 4; r++) {
        int t = sQi[ty2*4 + r];
        float4 ov; ov.x = accO[r][0]; ov.y = accO[r][1]; ov.z = accO[r][2]; ov.w = accO[r][3];
        *(float4*)(g_ob + ((size_t)(h*BH + bh)*NTOK + t)*EH + tx2*4) = ov;
    }
}

// ---------------- K11: merge performer + LSH branches ----------------
__global__ void k_merge() {
    int tid = threadIdx.x;
    int t = blockIdx.x*4 + (tid >> 6);
    int d = tid & 63;
    int bh = blockIdx.y;
    size_t i0 = (size_t)bh*NTOK + t;
    size_t i1 = (size_t)(BH + bh)*NTOK + t;
    float l0 = g_lseb[i0], l1 = g_lseb[i1];
    float mx = fmaxf(l0, l1);
    float norm = mx + logf(__expf(l0 - mx) + __expf(l1 - mx));
    float p0 = __expf(l0 - norm), p1 = __expf(l1 - norm);
    float pls = g_qls[bh*NTOK + t] + g_kls[bh];
    float psc = __expf(pls - norm);
    float z = g_dsb[i0]*p0 + g_dsb[i1]*p1 + g_qk1[bh*NTOK + t]*psc;
    z = fmaxf(z, 1e-6f);
    size_t base = ((size_t)bh*NTOK + t)*EH + d;
    float outv = g_ob[i0*EH + d]*p0 + g_ob[i1*EH + d]*p1 + g_qkv[base]*psc;
    g_on[base] = outv / z;
}

// ---------------- K12: final projection ----------------
__global__ __launch_bounds__(256) void k_final(const float* __restrict__ Wf,
                                               const float* __restrict__ bias,
                                               float* __restrict__ out) {
    __shared__ float sW[128*68];
    __shared__ float sX[4*128];
    int tid = threadIdx.x;
    int tok = tid >> 6, eo = tid & 63;
    int g0 = blockIdx.x*4;
    float acc = 0.f;
    for (int c = 0; c < 4; c++) {
        __syncthreads();
        for (int idx = tid; idx < 8192; idx += 256) {
            int e2 = idx >> 7, hd = idx & 127;
            sW[hd*68 + e2] = Wf[e2*512 + c*128 + hd];
        }
        for (int idx = tid; idx < 512; idx += 256) {
            int tk = idx >> 7, hd = idx & 127;
            int gg = g0 + tk;
            int b = gg >> 12, t = gg & 4095;
            int hdg = c*128 + hd;
            sX[tk*128 + hd] = g_on[(((size_t)(b*8 + (hdg >> 6)))*NTOK + t)*EH + (hdg & 63)];
        }
        __syncthreads();
        const float4* x4 = (const float4*)(sX + tok*128);
        #pragma unroll
        for (int h4 = 0; h4 < 32; h4++) {
            float4 xv = x4[h4];
            acc += xv.x*sW[(4*h4)*68 + eo]   + xv.y*sW[(4*h4+1)*68 + eo]
                 + xv.z*sW[(4*h4+2)*68 + eo] + xv.w*sW[(4*h4+3)*68 + eo];
        }
    }
    out[(size_t)(g0 + tok)*EH + eo] = acc + bias[eo];
}

// ---------------- launch ----------------
extern "C" void kernel_launch(void* const* d_in, const int* in_sizes, int n_in,
                              void* d_out, int out_size) {
    const float* query = (const float*)d_in[0];
    const float* key   = (const float*)d_in[1];
    const float* value = (const float*)d_in[2];
    const float* projW = (const float*)d_in[3];
    const float* alpha = (const float*)d_in[4];
    const float* beta  = (const float*)d_in[5];
    const float* outW  = (const float*)d_in[6];
    const float* outb  = (const float*)d_in[7];
    float* out = (float*)d_out;

    cudaFuncSetAttribute(k_bucket, cudaFuncAttributeMaxDynamicSharedMemorySize,
                         BKT_SMEM_FLOATS*4);

    k_split<<<dim3(NTOK/4, BH), 256>>>(query, key, value);
    k_maxn<<<BH, 256>>>();
    k_hash<<<dim3(NTOK/256, BH), 256>>>(alpha, beta);
    k_sort<<<128, 512>>>();
    k_feat<<<dim3(NTOK/32, BH, 2), 256>>>(projW);
    k_kls<<<BH, 256>>>();
    k_expk<<<dim3(NTOK*MF/256, BH), 256>>>();
    k_kvpart<<<dim3(NCH, BH), 128>>>();
    k_kvred<<<BH*MF*EH/256, 256>>>();
    k_qkv<<<dim3(NTOK/32, BH), 128>>>();
    k_bucket<<<dim3(32, BH, 2), 512, BKT_SMEM_FLOATS*4>>>();
    k_merge<<<dim3(NTOK/4, BH), 256>>>();
    k_final<<<(4*NTOK)/4, 256>>>(outW, outb, out);
}

// round 4
// speedup vs baseline: 1.3498x; 1.2374x over previous
#include <cuda_runtime.h>
#include <math.h>

#define BH 32
#define NTOK 4096
#define EH 64
#define MF 128
#define DM 512
#define NCH 32
#define TSTRIDE 144
#define DSTRIDE 132

#define SQRT_TEMP 0.35355339059327373f
#define TEMPF 0.125f
#define HALF_LOG_M 2.4260151319598084f
#define LN2F 0.6931471805599453f

typedef unsigned long long u64t;
__device__ __forceinline__ u64t splat2(float x) {
    u64t r; asm("mov.b64 %0, {%1, %1};" : "=l"(r) : "f"(x)); return r;
}
__device__ __forceinline__ u64t pack2(float x, float y) {
    u64t r; asm("mov.b64 %0, {%1, %2};" : "=l"(r) : "f"(x), "f"(y)); return r;
}
__device__ __forceinline__ void fma2(u64t& c, u64t a, u64t b) {
    asm("fma.rn.f32x2 %0, %1, %2, %0;" : "+l"(c) : "l"(a), "l"(b));
}
__device__ __forceinline__ float2 unpk(u64t v) {
    float2 f; asm("mov.b64 {%0, %1}, %2;" : "=f"(f.x), "=f"(f.y) : "l"(v)); return f;
}

// ---------------- scratch ----------------
__device__ float g_q[BH*NTOK*EH];
__device__ float g_k[BH*NTOK*EH];
__device__ float g_v[BH*NTOK*EH];
__device__ float g_qn2[BH*NTOK];
__device__ float g_kn2[BH*NTOK];
__device__ float g_MQ2[BH];
__device__ float g_MK2[BH];
__device__ float g_hashq[2*BH*NTOK];
__device__ float g_hashk[2*BH*NTOK];
__device__ int   g_qpos[2*BH*NTOK];
__device__ int   g_kpos[2*BH*NTOK];
__device__ int   g_qrev[2*BH*NTOK];
__device__ int   g_krev[2*BH*NTOK];
__device__ float g_qp[(size_t)BH*NTOK*MF];
__device__ float g_kp[(size_t)BH*NTOK*MF];    // stores log-phi (pre-exp)
__device__ float g_qls[BH*NTOK];
__device__ float g_krm[BH*NTOK];
__device__ float g_kls[BH];
__device__ float g_kvp[(size_t)NCH*BH*MF*EH];
__device__ float g_ksp[NCH*BH*MF];
__device__ float g_kv[BH*MF*EH];
__device__ float g_ksum[BH*MF];
__device__ float g_qk1[BH*NTOK];
__device__ float g_qkv[(size_t)BH*NTOK*EH];
__device__ float g_ob[(size_t)2*BH*NTOK*EH];
__device__ float g_lseb[2*BH*NTOK];
__device__ float g_dsb[2*BH*NTOK];
__device__ float g_on[(size_t)BH*NTOK*EH];

// ---------------- K1: split heads + squared norms ----------------
__global__ __launch_bounds__(256) void k_split(const float* __restrict__ query,
                                               const float* __restrict__ key,
                                               const float* __restrict__ value) {
    int tid = threadIdx.x;
    int tl = tid >> 6, e = tid & 63;
    int t = blockIdx.x*4 + tl, bh = blockIdx.y;
    int b = bh >> 3, hh = bh & 7;
    size_t gi = ((size_t)(b*NTOK + t))*DM + hh*EH + e;
    float qv = query[gi], kv = key[gi], vv = value[gi];
    size_t oi = ((size_t)bh*NTOK + t)*EH + e;
    g_q[oi] = qv; g_k[oi] = kv; g_v[oi] = vv;
    float q2 = qv*qv, k2 = kv*kv;
    #pragma unroll
    for (int o = 16; o; o >>= 1) {
        q2 += __shfl_down_sync(0xffffffffu, q2, o);
        k2 += __shfl_down_sync(0xffffffffu, k2, o);
    }
    __shared__ float sq[8], sk[8];
    if ((tid & 31) == 0) { sq[tid>>5] = q2; sk[tid>>5] = k2; }
    __syncthreads();
    if (e == 0) {
        g_qn2[bh*NTOK + t] = sq[2*tl] + sq[2*tl+1];
        g_kn2[bh*NTOK + t] = sk[2*tl] + sk[2*tl+1];
    }
}

// ---------------- K2: per-bh max squared norms ----------------
__global__ void k_maxn() {
    int bh = blockIdx.x, tid = threadIdx.x;
    float mq = 0.f, mk = 0.f;
    for (int i = tid; i < NTOK; i += 256) {
        mq = fmaxf(mq, g_qn2[bh*NTOK + i]);
        mk = fmaxf(mk, g_kn2[bh*NTOK + i]);
    }
    #pragma unroll
    for (int o = 16; o; o >>= 1) {
        mq = fmaxf(mq, __shfl_xor_sync(0xffffffffu, mq, o));
        mk = fmaxf(mk, __shfl_xor_sync(0xffffffffu, mk, o));
    }
    __shared__ float sq[8], sk[8];
    if ((tid & 31) == 0) { sq[tid>>5] = mq; sk[tid>>5] = mk; }
    __syncthreads();
    if (tid == 0) {
        float a = sq[0], b = sk[0];
        for (int w = 1; w < 8; w++) { a = fmaxf(a, sq[w]); b = fmaxf(b, sk[w]); }
        g_MQ2[bh] = a; g_MK2[bh] = b;
    }
}

// ---------------- K3: LSH hashes ----------------
__global__ void k_hash(const float* __restrict__ alpha, const float* __restrict__ beta) {
    int bh = blockIdx.y;
    int t = blockIdx.x*256 + threadIdx.x;
    const float* qr = g_q + ((size_t)bh*NTOK + t)*EH;
    const float* kr = g_k + ((size_t)bh*NTOK + t)*EH;
    float a0 = 0.f, a1 = 0.f, c0 = 0.f, c1 = 0.f;
    #pragma unroll 8
    for (int e = 0; e < EH; e++) {
        float al0 = alpha[e*2], al1 = alpha[e*2+1];
        float qe = qr[e], ke = kr[e];
        a0 += qe*al0; a1 += qe*al1;
        c0 += ke*al0; c1 += ke*al1;
    }
    float S = g_MQ2[bh] + g_MK2[bh];
    float extq = sqrtf(fmaxf(S - g_qn2[bh*NTOK + t], 0.f));
    float extk = sqrtf(fmaxf(S - g_kn2[bh*NTOK + t], 0.f));
    g_hashq[bh*NTOK + t]           = a0 + extq*alpha[EH*2]       + beta[0];
    g_hashq[BH*NTOK + bh*NTOK + t] = a1 + extq*alpha[EH*2+1]     + beta[1];
    g_hashk[bh*NTOK + t]           = c0 + extk*alpha[(EH+1)*2]   + beta[0];
    g_hashk[BH*NTOK + bh*NTOK + t] = c1 + extk*alpha[(EH+1)*2+1] + beta[1];
}

// ---------------- K4: stable bitonic argsort ----------------
__global__ void k_sort() {
    __shared__ float sv[NTOK];
    __shared__ int   si[NTOK];
    int which = blockIdx.x >> 6;
    int rem   = blockIdx.x & 63;
    const float* src = which ? (g_hashk + (size_t)rem*NTOK) : (g_hashq + (size_t)rem*NTOK);
    int tid = threadIdx.x;
    for (int i = tid; i < NTOK; i += 512) { sv[i] = src[i]; si[i] = i; }
    __syncthreads();
    for (int k = 2; k <= NTOK; k <<= 1)
        for (int j = k >> 1; j > 0; j >>= 1) {
            for (int p = tid; p < NTOK/2; p += 512) {
                int i  = ((p & ~(j-1)) << 1) | (p & (j-1));
                int ix = i | j;
                bool up = ((i & k) == 0);
                float vi = sv[i], vj = sv[ix];
                int ii = si[i], ij = si[ix];
                bool agt = (vi > vj) || (vi == vj && ii > ij);
                if (agt == up) { sv[i] = vj; sv[ix] = vi; si[i] = ij; si[ix] = ii; }
            }
            __syncthreads();
        }
    int* pos = which ? g_kpos : g_qpos;
    int* rev = which ? g_krev : g_qrev;
    for (int r = tid; r < NTOK; r += 512) {
        int idx = si[r];
        pos[rem*NTOK + r]   = idx;
        rev[rem*NTOK + idx] = r;
    }
}

// ---------------- K5: performer feature maps ----------------
__global__ __launch_bounds__(256) void k_feat(const float* __restrict__ W) {
    int bh = blockIdx.y, isK = blockIdx.z, tid = threadIdx.x;
    int tok = tid >> 7, f = tid & 127;
    const float* X  = isK ? g_k   : g_q;
    const float* n2 = isK ? g_kn2 : g_qn2;
    u64t w2[32];
    const float4* W4 = (const float4*)(W + f*EH);
    #pragma unroll
    for (int e4 = 0; e4 < 16; e4++) {
        float4 t = W4[e4];
        w2[2*e4]   = pack2(t.x, t.y);
        w2[2*e4+1] = pack2(t.z, t.w);
    }
    __shared__ float xr[2][EH];
    __shared__ float wr[8];
    for (int it = 0; it < 16; it++) {
        int tb = blockIdx.x*32 + it*2;
        int t = tb + tok;
        if (tid < 128) xr[tid>>6][tid&63] = X[((size_t)bh*NTOK + tb + (tid>>6))*EH + (tid&63)];
        __syncthreads();
        u64t p2 = 0;
        const float4* x4 = (const float4*)xr[tok];
        #pragma unroll
        for (int e4 = 0; e4 < 16; e4++) {
            float4 xv = x4[e4];
            fma2(p2, pack2(xv.x, xv.y), w2[2*e4]);
            fma2(p2, pack2(xv.z, xv.w), w2[2*e4+1]);
        }
        float2 pu = unpk(p2);
        float proj = pu.x + pu.y;
        float lp = proj*SQRT_TEMP - 0.5f*TEMPF*n2[bh*NTOK + t] - HALF_LOG_M;
        float mv = lp;
        #pragma unroll
        for (int o = 16; o; o >>= 1) mv = fmaxf(mv, __shfl_xor_sync(0xffffffffu, mv, o));
        if ((tid & 31) == 0) wr[tid>>5] = mv;
        __syncthreads();
        float stab = fmaxf(fmaxf(wr[tok*4], wr[tok*4+1]), fmaxf(wr[tok*4+2], wr[tok*4+3]));
        size_t oi = ((size_t)bh*NTOK + t)*MF + f;
        if (!isK) {
            g_qp[oi] = __expf(lp - stab);
            if (f == 0) g_qls[bh*NTOK + t] = stab;
        } else {
            g_kp[oi] = lp;
            if (f == 0) g_krm[bh*NTOK + t] = stab;
        }
    }
}

// ---------------- K6: per-bh max of k log-phi ----------------
__global__ void k_kls() {
    int bh = blockIdx.x, tid = threadIdx.x;
    float m = -1e30f;
    for (int i = tid; i < NTOK; i += 256) m = fmaxf(m, g_krm[bh*NTOK + i]);
    #pragma unroll
    for (int o = 16; o; o >>= 1) m = fmaxf(m, __shfl_xor_sync(0xffffffffu, m, o));
    __shared__ float s[8];
    if ((tid & 31) == 0) s[tid>>5] = m;
    __syncthreads();
    if (tid == 0) {
        float r = s[0];
        for (int w = 1; w < 8; w++) r = fmaxf(r, s[w]);
        g_kls[bh] = r;
    }
}

// ---------------- K8: partial kv = exp(k')^T v and column sums ----------------
__global__ __launch_bounds__(128) void k_kvpart() {
    int ch = blockIdx.x, bh = blockIdx.y, m = threadIdx.x;
    float kls = g_kls[bh];
    __shared__ float sv[1024];
    u64t acc2[32];
    #pragma unroll
    for (int d = 0; d < 32; d++) acc2[d] = 0ull;
    float ssum = 0.f;
    for (int t0 = ch*(NTOK/NCH); t0 < (ch+1)*(NTOK/NCH); t0 += 16) {
        __syncthreads();
        for (int l = m; l < 1024; l += 128)
            sv[l] = g_v[((size_t)bh*NTOK + t0 + (l>>6))*EH + (l & 63)];
        __syncthreads();
        for (int tt = 0; tt < 16; tt++) {
            float kpr = __expf(g_kp[((size_t)bh*NTOK + t0 + tt)*MF + m] - kls);
            ssum += kpr;
            u64t kp2 = splat2(kpr);
            const float4* v4 = (const float4*)(sv + tt*64);
            #pragma unroll
            for (int d4 = 0; d4 < 16; d4++) {
                float4 vv = v4[d4];
                fma2(acc2[2*d4],   kp2, pack2(vv.x, vv.y));
                fma2(acc2[2*d4+1], kp2, pack2(vv.z, vv.w));
            }
        }
    }
    float* dst = g_kvp + (((size_t)ch*BH + bh)*MF + m)*EH;
    #pragma unroll
    for (int d2 = 0; d2 < 32; d2++) {
        float2 u = unpk(acc2[d2]);
        dst[2*d2] = u.x; dst[2*d2+1] = u.y;
    }
    g_ksp[(ch*BH + bh)*MF + m] = ssum;
}

// ---------------- K8b: deterministic reduce ----------------
__global__ void k_kvred() {
    int idx = blockIdx.x*256 + threadIdx.x;
    float s = 0.f;
    #pragma unroll
    for (int c = 0; c < NCH; c++) s += g_kvp[(size_t)c*BH*MF*EH + idx];
    g_kv[idx] = s;
    if (idx < BH*MF) {
        float ss = 0.f;
        #pragma unroll
        for (int c = 0; c < NCH; c++) ss += g_ksp[c*BH*MF + idx];
        g_ksum[idx] = ss;
    }
}

// ---------------- K9: qkv = q' kv ; qk1 = q' . ksum ----------------
__global__ __launch_bounds__(128) void k_qkv() {
    int bh = blockIdx.y, tid = threadIdx.x;
    int d = tid & 63, rr = tid >> 6;
    __shared__ float ks[MF];
    __shared__ float qpr[2*MF];
    __shared__ float r4[4];
    u64t kv2[64];
    #pragma unroll
    for (int m2 = 0; m2 < 64; m2++)
        kv2[m2] = pack2(g_kv[((size_t)bh*MF + 2*m2)*EH + d],
                        g_kv[((size_t)bh*MF + 2*m2+1)*EH + d]);
    if (tid < MF) ks[tid] = g_ksum[bh*MF + tid];
    __syncthreads();
    for (int pair = 0; pair < 16; pair++) {
        int tbase = blockIdx.x*32 + pair*2;
        __syncthreads();
        for (int l = tid; l < 256; l += 128)
            qpr[l] = g_qp[((size_t)bh*NTOK + tbase + (l>>7))*MF + (l & 127)];
        __syncthreads();
        const float4* q4 = (const float4*)(qpr + rr*MF);
        u64t acc2 = 0ull;
        #pragma unroll
        for (int m4 = 0; m4 < 32; m4++) {
            float4 qv = q4[m4];
            fma2(acc2, pack2(qv.x, qv.y), kv2[2*m4]);
            fma2(acc2, pack2(qv.z, qv.w), kv2[2*m4+1]);
        }
        float2 su = unpk(acc2);
        g_qkv[((size_t)bh*NTOK + tbase + rr)*EH + d] = su.x + su.y;
        float p = qpr[rr*MF + 2*d]*ks[2*d] + qpr[rr*MF + 2*d+1]*ks[2*d+1];
        #pragma unroll
        for (int o = 16; o; o >>= 1) p += __shfl_down_sync(0xffffffffu, p, o);
        int lane = tid & 31, wp = tid >> 5;
        if (lane == 0) r4[wp] = p;
        __syncthreads();
        if (tid == 0)  g_qk1[bh*NTOK + tbase]     = r4[0] + r4[1];
        if (tid == 64) g_qk1[bh*NTOK + tbase + 1] = r4[2] + r4[3];
    }
}

// ---------------- K10: fused bucketed exact-attention correction ----------------
#define BKT_SMEM_FLOATS (2*128*TSTRIDE + 128*DSTRIDE + 128 + 4*128)

__global__ __launch_bounds__(512, 1) void k_bucket() {
    extern __shared__ float sm[];
    float* sD   = sm + 2*128*TSTRIDE;              // [128][DSTRIDE] inner/dots
    float* sPls = sD + 128*DSTRIDE;
    int* sQi = (int*)(sPls + 128);
    int* sKi = sQi + 128;
    int* sQb = sKi + 128;
    int* sKb = sQb + 128;

    int nb = blockIdx.x, bh = blockIdx.y, h = blockIdx.z;
    int tid = threadIdx.x, tx = tid & 31, ty = tid >> 5;
    int o = 1 - h;
    float kls = g_kls[bh];

    if (tid < 128) {
        int qi = g_qpos[(h*BH + bh)*NTOK + nb*128 + tid];
        int ki = g_kpos[(h*BH + bh)*NTOK + nb*128 + tid];
        sQi[tid] = qi; sKi[tid] = ki;
        sQb[tid] = g_qrev[(o*BH + bh)*NTOK + qi] >> 7;
        sKb[tid] = g_krev[(o*BH + bh)*NTOK + ki] >> 7;
        sPls[tid] = g_qls[bh*NTOK + qi] + kls;
    }
    __syncthreads();

    // ---- Phase A: inner = q k^T  (row-paired f32x2) ----
    float* sQt = sm;                    // [64][TSTRIDE]
    float* sKt = sm + 64*TSTRIDE;
    for (int idx = tid; idx < 8192; idx += 512) {
        int i = idx >> 6, e = idx & 63;
        sQt[e*TSTRIDE + i] = g_q[((size_t)bh*NTOK + sQi[i])*EH + e];
        sKt[e*TSTRIDE + i] = g_k[((size_t)bh*NTOK + sKi[i])*EH + e];
    }
    __syncthreads();
    {
        u64t aI[4][4];
        #pragma unroll
        for (int r = 0; r < 4; r++)
            #pragma unroll
            for (int c = 0; c < 4; c++) aI[r][c] = 0ull;
        for (int e = 0; e < 64; e++) {
            const u64t* ap = (const u64t*)(sQt + e*TSTRIDE + ty*8);
            float4 bq = *(const float4*)(sKt + e*TSTRIDE + tx*4);
            u64t b0 = splat2(bq.x), b1 = splat2(bq.y), b2 = splat2(bq.z), b3 = splat2(bq.w);
            #pragma unroll
            for (int r2 = 0; r2 < 4; r2++) {
                u64t av = ap[r2];
                fma2(aI[r2][0], av, b0); fma2(aI[r2][1], av, b1);
                fma2(aI[r2][2], av, b2); fma2(aI[r2][3], av, b3);
            }
        }
        // park raw inner in sD
        #pragma unroll
        for (int r2 = 0; r2 < 4; r2++) {
            float2 v0 = unpk(aI[r2][0]), v1 = unpk(aI[r2][1]);
            float2 v2 = unpk(aI[r2][2]), v3 = unpk(aI[r2][3]);
            int row = ty*8 + r2*2;
            *(float4*)(sD + row*DSTRIDE + tx*4)     = make_float4(v0.x, v1.x, v2.x, v3.x);
            *(float4*)(sD + (row+1)*DSTRIDE + tx*4) = make_float4(v0.y, v1.y, v2.y, v3.y);
        }
    }
    __syncthreads();

    // ---- Phase B: dots_prime = q' k'^T  (exp of k' folded into gather) ----
    float* sQPt = sm;                   // [128][TSTRIDE]
    float* sKPt = sm + 128*TSTRIDE;
    for (int idx = tid; idx < 16384; idx += 512) {
        int i = idx >> 7, m = idx & 127;
        sQPt[m*TSTRIDE + i] = g_qp[((size_t)bh*NTOK + sQi[i])*MF + m];
        sKPt[m*TSTRIDE + i] = __expf(g_kp[((size_t)bh*NTOK + sKi[i])*MF + m] - kls);
    }
    __syncthreads();
    u64t aP[4][4];
    #pragma unroll
    for (int r = 0; r < 4; r++)
        #pragma unroll
        for (int c = 0; c < 4; c++) aP[r][c] = 0ull;
    for (int m = 0; m < 128; m++) {
        const u64t* ap = (const u64t*)(sQPt + m*TSTRIDE + ty*8);
        float4 bq = *(const float4*)(sKPt + m*TSTRIDE + tx*4);
        u64t b0 = splat2(bq.x), b1 = splat2(bq.y), b2 = splat2(bq.z), b3 = splat2(bq.w);
        #pragma unroll
        for (int r2 = 0; r2 < 4; r2++) {
            u64t av = ap[r2];
            fma2(aP[r2][0], av, b0); fma2(aP[r2][1], av, b1);
            fma2(aP[r2][2], av, b2); fma2(aP[r2][3], av, b3);
        }
    }
    __syncthreads();

    // ---- Epilogue: dup correction, LSE, exp; dots written in place to sD ----
    int kb[4];
    #pragma unroll
    for (int c = 0; c < 4; c++) kb[c] = sKb[tx*4 + c];
    #pragma unroll
    for (int r2 = 0; r2 < 4; r2++) {
        float2 P0 = unpk(aP[r2][0]), P1 = unpk(aP[r2][1]);
        float2 P2 = unpk(aP[r2][2]), P3 = unpk(aP[r2][3]);
        #pragma unroll
        for (int half = 0; half < 2; half++) {
            int row = ty*8 + r2*2 + half;
            int qb = sQb[row]; float pls = sPls[row];
            float4 inn = *(const float4*)(sD + row*DSTRIDE + tx*4);
            float pp0 = half ? P0.y : P0.x;
            float pp1 = half ? P1.y : P1.x;
            float pp2 = half ? P2.y : P2.x;
            float pp3 = half ? P3.y : P3.x;
            float i0 = inn.x*TEMPF - ((qb == kb[0]) ? LN2F : 0.f);
            float i1 = inn.y*TEMPF - ((qb == kb[1]) ? LN2F : 0.f);
            float i2 = inn.z*TEMPF - ((qb == kb[2]) ? LN2F : 0.f);
            float i3 = inn.w*TEMPF - ((qb == kb[3]) ? LN2F : 0.f);
            pp0 *= (qb == kb[0]) ? 0.5f : 1.f;
            pp1 *= (qb == kb[1]) ? 0.5f : 1.f;
            pp2 *= (qb == kb[2]) ? 0.5f : 1.f;
            pp3 *= (qb == kb[3]) ? 0.5f : 1.f;
            float rm = fmaxf(fmaxf(i0, i1), fmaxf(i2, i3));
            #pragma unroll
            for (int off = 16; off; off >>= 1) rm = fmaxf(rm, __shfl_xor_sync(0xffffffffu, rm, off));
            float l = fmaxf(rm, pls);
            float pe = __expf(pls - l);
            float4 dv;
            dv.x = __expf(i0 - l) - pp0*pe;
            dv.y = __expf(i1 - l) - pp1*pe;
            dv.z = __expf(i2 - l) - pp2*pe;
            dv.w = __expf(i3 - l) - pp3*pe;
            *(float4*)(sD + row*DSTRIDE + tx*4) = dv;
            float s = dv.x + dv.y + dv.z + dv.w;
            #pragma unroll
            for (int off = 16; off; off >>= 1) s += __shfl_xor_sync(0xffffffffu, s, off);
            if (tx == 0) {
                int t = sQi[row];
                size_t bi = (size_t)(h*BH + bh)*NTOK + t;
                g_lseb[bi] = l;
                g_dsb[bi]  = s;
            }
        }
    }
    // gather V into buf1 (sKPt region, reads done)
    float* sV = sm + 128*TSTRIDE;       // [128][68]
    for (int idx = tid; idx < 8192; idx += 512) {
        int i = idx >> 6, d = idx & 63;
        sV[i*68 + d] = g_v[((size_t)bh*NTOK + sKi[i])*EH + d];
    }
    __syncthreads();

    // ---- Phase C: so = dots @ V (col-paired f32x2), scatter unsorted ----
    int tx2 = tid & 15, ty2 = tid >> 4;
    u64t accO[4][2];
    #pragma unroll
    for (int r = 0; r < 4; r++) { accO[r][0] = 0ull; accO[r][1] = 0ull; }
    for (int j0 = 0; j0 < 128; j0 += 4) {
        float4 a0 = *(const float4*)(sD + (ty2*4+0)*DSTRIDE + j0);
        float4 a1 = *(const float4*)(sD + (ty2*4+1)*DSTRIDE + j0);
        float4 a2 = *(const float4*)(sD + (ty2*4+2)*DSTRIDE + j0);
        float4 a3 = *(const float4*)(sD + (ty2*4+3)*DSTRIDE + j0);
        #pragma unroll
        for (int jj = 0; jj < 4; jj++) {
            float4 t = *(const float4*)(sV + (j0 + jj)*68 + tx2*4);
            u64t bv0 = pack2(t.x, t.y), bv1 = pack2(t.z, t.w);
            float av0 = (jj==0)?a0.x:(jj==1)?a0.y:(jj==2)?a0.z:a0.w;
            float av1 = (jj==0)?a1.x:(jj==1)?a1.y:(jj==2)?a1.z:a1.w;
            float av2 = (jj==0)?a2.x:(jj==1)?a2.y:(jj==2)?a2.z:a2.w;
            float av3 = (jj==0)?a3.x:(jj==1)?a3.y:(jj==2)?a3.z:a3.w;
            u64t s0 = splat2(av0), s1 = splat2(av1), s2 = splat2(av2), s3 = splat2(av3);
            fma2(accO[0][0], s0, bv0); fma2(accO[0][1], s0, bv1);
            fma2(accO[1][0], s1, bv0); fma2(accO[1][1], s1, bv1);
            fma2(accO[2][0], s2, bv0); fma2(accO[2][1], s2, bv1);
            fma2(accO[3][0], s3, bv0); fma2(accO[3][1], s3, bv1);
        }
    }
    #pragma unroll
    for (int r = 0; r < 4; r++) {
        int t = sQi[ty2*4 + r];
        float2 u0 = unpk(accO[r][0]), u1 = unpk(accO[r][1]);
        *(float4*)(g_ob + ((size_t)(h*BH + bh)*NTOK + t)*EH + tx2*4) =
            make_float4(u0.x, u0.y, u1.x, u1.y);
    }
}

// ---------------- K11: merge performer + LSH branches ----------------
__global__ void k_merge() {
    int tid = threadIdx.x;
    int t = blockIdx.x*4 + (tid >> 6);
    int d = tid & 63;
    int bh = blockIdx.y;
    size_t i0 = (size_t)bh*NTOK + t;
    size_t i1 = (size_t)(BH + bh)*NTOK + t;
    float l0 = g_lseb[i0], l1 = g_lseb[i1];
    float mx = fmaxf(l0, l1);
    float norm = mx + logf(__expf(l0 - mx) + __expf(l1 - mx));
    float p0 = __expf(l0 - norm), p1 = __expf(l1 - norm);
    float pls = g_qls[bh*NTOK + t] + g_kls[bh];
    float psc = __expf(pls - norm);
    float z = g_dsb[i0]*p0 + g_dsb[i1]*p1 + g_qk1[bh*NTOK + t]*psc;
    z = fmaxf(z, 1e-6f);
    size_t base = ((size_t)bh*NTOK + t)*EH + d;
    float outv = g_ob[i0*EH + d]*p0 + g_ob[i1*EH + d]*p1 + g_qkv[base]*psc;
    g_on[base] = outv / z;
}

// ---------------- K12: final projection (16 tokens/block) ----------------
#define WS 130
#define XS 132
__global__ __launch_bounds__(256) void k_final(const float* __restrict__ Wf,
                                               const float* __restrict__ bias,
                                               float* __restrict__ out) {
    __shared__ float sW2[64*WS];
    __shared__ float sX[16*XS];
    int tid = threadIdx.x;
    int tok = tid >> 6, eo = tid & 63;
    int g0 = blockIdx.x*16;
    u64t acc2[4];
    #pragma unroll
    for (int tt = 0; tt < 4; tt++) acc2[tt] = 0ull;
    for (int c = 0; c < 4; c++) {
        __syncthreads();
        for (int idx = tid; idx < 8192; idx += 256) {
            int e2 = idx >> 7, hd = idx & 127;
            sW2[e2*WS + hd] = Wf[e2*512 + c*128 + hd];
        }
        for (int idx = tid; idx < 2048; idx += 256) {
            int tk = idx >> 7, hd = idx & 127;
            int gg = g0 + tk;
            int b = gg >> 12, t = gg & 4095;
            int hdg = c*128 + hd;
            sX[tk*XS + hd] = g_on[(((size_t)(b*8 + (hdg >> 6)))*NTOK + t)*EH + (hdg & 63)];
        }
        __syncthreads();
        const u64t* wp = (const u64t*)(sW2 + eo*WS);
        #pragma unroll
        for (int tt = 0; tt < 4; tt++) {
            const float4* x4 = (const float4*)(sX + (tok + tt*4)*XS);
            #pragma unroll
            for (int h4 = 0; h4 < 32; h4++) {
                float4 xv = x4[h4];
                fma2(acc2[tt], pack2(xv.x, xv.y), wp[2*h4]);
                fma2(acc2[tt], pack2(xv.z, xv.w), wp[2*h4+1]);
            }
        }
    }
    float bv = bias[eo];
    #pragma unroll
    for (int tt = 0; tt < 4; tt++) {
        float2 u = unpk(acc2[tt]);
        out[(size_t)(g0 + tok + tt*4)*EH + eo] = u.x + u.y + bv;
    }
}

// ---------------- launch ----------------
extern "C" void kernel_launch(void* const* d_in, const int* in_sizes, int n_in,
                              void* d_out, int out_size) {
    const float* query = (const float*)d_in[0];
    const float* key   = (const float*)d_in[1];
    const float* value = (const float*)d_in[2];
    const float* projW = (const float*)d_in[3];
    const float* alpha = (const float*)d_in[4];
    const float* beta  = (const float*)d_in[5];
    const float* outW  = (const float*)d_in[6];
    const float* outb  = (const float*)d_in[7];
    float* out = (float*)d_out;

    cudaFuncSetAttribute(k_bucket, cudaFuncAttributeMaxDynamicSharedMemorySize,
                         BKT_SMEM_FLOATS*4);

    k_split<<<dim3(NTOK/4, BH), 256>>>(query, key, value);
    k_maxn<<<BH, 256>>>();
    k_hash<<<dim3(NTOK/256, BH), 256>>>(alpha, beta);
    k_sort<<<128, 512>>>();
    k_feat<<<dim3(NTOK/32, BH, 2), 256>>>(projW);
    k_kls<<<BH, 256>>>();
    k_kvpart<<<dim3(NCH, BH), 128>>>();
    k_kvred<<<BH*MF*EH/256, 256>>>();
    k_qkv<<<dim3(NTOK/32, BH), 128>>>();
    k_bucket<<<dim3(32, BH, 2), 512, BKT_SMEM_FLOATS*4>>>();
    k_merge<<<dim3(NTOK/4, BH), 256>>>();
    k_final<<<NTOK*4/16, 256>>>(outW, outb, out);
}

// round 5
// speedup vs baseline: 1.3618x; 1.0089x over previous
#include <cuda_runtime.h>
#include <math.h>

#define BH 32
#define NTOK 4096
#define EH 64
#define MF 128
#define DM 512
#define NCH 32
#define IST 144
#define DST 132

#define SQRT_TEMP 0.35355339059327373f
#define TEMPF 0.125f
#define HALF_LOG_M 2.4260151319598084f
#define LN2F 0.6931471805599453f

typedef unsigned long long u64t;
__device__ __forceinline__ u64t splat2(float x) {
    u64t r; asm("mov.b64 %0, {%1, %1};" : "=l"(r) : "f"(x)); return r;
}
__device__ __forceinline__ u64t pack2(float x, float y) {
    u64t r; asm("mov.b64 %0, {%1, %2};" : "=l"(r) : "f"(x), "f"(y)); return r;
}
__device__ __forceinline__ void fma2(u64t& c, u64t a, u64t b) {
    asm("fma.rn.f32x2 %0, %1, %2, %0;" : "+l"(c) : "l"(a), "l"(b));
}
__device__ __forceinline__ float2 unpk(u64t v) {
    float2 f; asm("mov.b64 {%0, %1}, %2;" : "=f"(f.x), "=f"(f.y) : "l"(v)); return f;
}

// ---------------- scratch ----------------
__device__ float g_q[BH*NTOK*EH];
__device__ float g_k[BH*NTOK*EH];
__device__ float g_v[BH*NTOK*EH];
__device__ float g_qn2[BH*NTOK];
__device__ float g_kn2[BH*NTOK];
__device__ float g_MQ2[BH];
__device__ float g_MK2[BH];
__device__ float g_hashq[2*BH*NTOK];
__device__ float g_hashk[2*BH*NTOK];
__device__ int   g_qpos[2*BH*NTOK];
__device__ int   g_kpos[2*BH*NTOK];
__device__ int   g_qrev[2*BH*NTOK];
__device__ int   g_krev[2*BH*NTOK];
__device__ float g_qp[(size_t)BH*NTOK*MF];
__device__ float g_kp[(size_t)BH*NTOK*MF];    // log-phi (pre-exp)
__device__ float g_qls[BH*NTOK];
__device__ float g_krm[BH*NTOK];
__device__ float g_kls[BH];
__device__ float g_kvp[(size_t)NCH*BH*MF*EH];
__device__ float g_ksp[NCH*BH*MF];
__device__ float g_kv[BH*MF*EH];
__device__ float g_ksum[BH*MF];
__device__ float g_qk1[BH*NTOK];
__device__ float g_qkv[(size_t)BH*NTOK*EH];
__device__ float g_dots[(size_t)2*BH*NTOK*128];   // 134MB: inner then dots, in place
__device__ float g_ob[(size_t)2*BH*NTOK*EH];
__device__ float g_lseb[2*BH*NTOK];
__device__ float g_dsb[2*BH*NTOK];
__device__ float g_on[(size_t)BH*NTOK*EH];

// ---------------- K1: split heads + squared norms ----------------
__global__ __launch_bounds__(256) void k_split(const float* __restrict__ query,
                                               const float* __restrict__ key,
                                               const float* __restrict__ value) {
    int tid = threadIdx.x;
    int tl = tid >> 6, e = tid & 63;
    int t = blockIdx.x*4 + tl, bh = blockIdx.y;
    int b = bh >> 3, hh = bh & 7;
    size_t gi = ((size_t)(b*NTOK + t))*DM + hh*EH + e;
    float qv = query[gi], kv = key[gi], vv = value[gi];
    size_t oi = ((size_t)bh*NTOK + t)*EH + e;
    g_q[oi] = qv; g_k[oi] = kv; g_v[oi] = vv;
    float q2 = qv*qv, k2 = kv*kv;
    #pragma unroll
    for (int o = 16; o; o >>= 1) {
        q2 += __shfl_down_sync(0xffffffffu, q2, o);
        k2 += __shfl_down_sync(0xffffffffu, k2, o);
    }
    __shared__ float sq[8], sk[8];
    if ((tid & 31) == 0) { sq[tid>>5] = q2; sk[tid>>5] = k2; }
    __syncthreads();
    if (e == 0) {
        g_qn2[bh*NTOK + t] = sq[2*tl] + sq[2*tl+1];
        g_kn2[bh*NTOK + t] = sk[2*tl] + sk[2*tl+1];
    }
}

// ---------------- K2: per-bh max squared norms ----------------
__global__ void k_maxn() {
    int bh = blockIdx.x, tid = threadIdx.x;
    float mq = 0.f, mk = 0.f;
    for (int i = tid; i < NTOK; i += 256) {
        mq = fmaxf(mq, g_qn2[bh*NTOK + i]);
        mk = fmaxf(mk, g_kn2[bh*NTOK + i]);
    }
    #pragma unroll
    for (int o = 16; o; o >>= 1) {
        mq = fmaxf(mq, __shfl_xor_sync(0xffffffffu, mq, o));
        mk = fmaxf(mk, __shfl_xor_sync(0xffffffffu, mk, o));
    }
    __shared__ float sq[8], sk[8];
    if ((tid & 31) == 0) { sq[tid>>5] = mq; sk[tid>>5] = mk; }
    __syncthreads();
    if (tid == 0) {
        float a = sq[0], b = sk[0];
        for (int w = 1; w < 8; w++) { a = fmaxf(a, sq[w]); b = fmaxf(b, sk[w]); }
        g_MQ2[bh] = a; g_MK2[bh] = b;
    }
}

// ---------------- K3: LSH hashes ----------------
__global__ void k_hash(const float* __restrict__ alpha, const float* __restrict__ beta) {
    __shared__ float sal[2*(EH+2)];
    __shared__ float sbe[2];
    int bh = blockIdx.y;
    int tid = threadIdx.x;
    if (tid < 2*(EH+2)) sal[tid] = alpha[tid];
    if (tid < 2) sbe[tid] = beta[tid];
    __syncthreads();
    int t = blockIdx.x*256 + tid;
    const float* qr = g_q + ((size_t)bh*NTOK + t)*EH;
    const float* kr = g_k + ((size_t)bh*NTOK + t)*EH;
    float a0 = 0.f, a1 = 0.f, c0 = 0.f, c1 = 0.f;
    #pragma unroll 8
    for (int e = 0; e < EH; e++) {
        float al0 = sal[e*2], al1 = sal[e*2+1];
        float qe = qr[e], ke = kr[e];
        a0 += qe*al0; a1 += qe*al1;
        c0 += ke*al0; c1 += ke*al1;
    }
    float S = g_MQ2[bh] + g_MK2[bh];
    float extq = sqrtf(fmaxf(S - g_qn2[bh*NTOK + t], 0.f));
    float extk = sqrtf(fmaxf(S - g_kn2[bh*NTOK + t], 0.f));
    g_hashq[bh*NTOK + t]           = a0 + extq*sal[EH*2]       + sbe[0];
    g_hashq[BH*NTOK + bh*NTOK + t] = a1 + extq*sal[EH*2+1]     + sbe[1];
    g_hashk[bh*NTOK + t]           = c0 + extk*sal[(EH+1)*2]   + sbe[0];
    g_hashk[BH*NTOK + bh*NTOK + t] = c1 + extk*sal[(EH+1)*2+1] + sbe[1];
}

// ---------------- K4: stable bitonic argsort ----------------
__global__ void k_sort() {
    __shared__ float sv[NTOK];
    __shared__ int   si[NTOK];
    int which = blockIdx.x >> 6;
    int rem   = blockIdx.x & 63;
    const float* src = which ? (g_hashk + (size_t)rem*NTOK) : (g_hashq + (size_t)rem*NTOK);
    int tid = threadIdx.x;
    for (int i = tid; i < NTOK; i += 512) { sv[i] = src[i]; si[i] = i; }
    __syncthreads();
    for (int k = 2; k <= NTOK; k <<= 1)
        for (int j = k >> 1; j > 0; j >>= 1) {
            for (int p = tid; p < NTOK/2; p += 512) {
                int i  = ((p & ~(j-1)) << 1) | (p & (j-1));
                int ix = i | j;
                bool up = ((i & k) == 0);
                float vi = sv[i], vj = sv[ix];
                int ii = si[i], ij = si[ix];
                bool agt = (vi > vj) || (vi == vj && ii > ij);
                if (agt == up) { sv[i] = vj; sv[ix] = vi; si[i] = ij; si[ix] = ii; }
            }
            __syncthreads();
        }
    int* pos = which ? g_kpos : g_qpos;
    int* rev = which ? g_krev : g_qrev;
    for (int r = tid; r < NTOK; r += 512) {
        int idx = si[r];
        pos[rem*NTOK + r]   = idx;
        rev[rem*NTOK + idx] = r;
    }
}

// ---------------- K5: performer feature maps ----------------
__global__ __launch_bounds__(256) void k_feat(const float* __restrict__ W) {
    int bh = blockIdx.y, isK = blockIdx.z, tid = threadIdx.x;
    int tok = tid >> 7, f = tid & 127;
    const float* X  = isK ? g_k   : g_q;
    const float* n2 = isK ? g_kn2 : g_qn2;
    u64t w2[32];
    const float4* W4 = (const float4*)(W + f*EH);
    #pragma unroll
    for (int e4 = 0; e4 < 16; e4++) {
        float4 t = W4[e4];
        w2[2*e4]   = pack2(t.x, t.y);
        w2[2*e4+1] = pack2(t.z, t.w);
    }
    __shared__ float xr[2][EH];
    __shared__ float wr[8];
    for (int it = 0; it < 16; it++) {
        int tb = blockIdx.x*32 + it*2;
        int t = tb + tok;
        if (tid < 128) xr[tid>>6][tid&63] = X[((size_t)bh*NTOK + tb + (tid>>6))*EH + (tid&63)];
        __syncthreads();
        u64t p2 = 0;
        const float4* x4 = (const float4*)xr[tok];
        #pragma unroll
        for (int e4 = 0; e4 < 16; e4++) {
            float4 xv = x4[e4];
            fma2(p2, pack2(xv.x, xv.y), w2[2*e4]);
            fma2(p2, pack2(xv.z, xv.w), w2[2*e4+1]);
        }
        float2 pu = unpk(p2);
        float proj = pu.x + pu.y;
        float lp = proj*SQRT_TEMP - 0.5f*TEMPF*n2[bh*NTOK + t] - HALF_LOG_M;
        float mv = lp;
        #pragma unroll
        for (int o = 16; o; o >>= 1) mv = fmaxf(mv, __shfl_xor_sync(0xffffffffu, mv, o));
        if ((tid & 31) == 0) wr[tid>>5] = mv;
        __syncthreads();
        float stab = fmaxf(fmaxf(wr[tok*4], wr[tok*4+1]), fmaxf(wr[tok*4+2], wr[tok*4+3]));
        size_t oi = ((size_t)bh*NTOK + t)*MF + f;
        if (!isK) {
            g_qp[oi] = __expf(lp - stab);
            if (f == 0) g_qls[bh*NTOK + t] = stab;
        } else {
            g_kp[oi] = lp;
            if (f == 0) g_krm[bh*NTOK + t] = stab;
        }
    }
}

// ---------------- K6: per-bh max of k log-phi ----------------
__global__ void k_kls() {
    int bh = blockIdx.x, tid = threadIdx.x;
    float m = -1e30f;
    for (int i = tid; i < NTOK; i += 256) m = fmaxf(m, g_krm[bh*NTOK + i]);
    #pragma unroll
    for (int o = 16; o; o >>= 1) m = fmaxf(m, __shfl_xor_sync(0xffffffffu, m, o));
    __shared__ float s[8];
    if ((tid & 31) == 0) s[tid>>5] = m;
    __syncthreads();
    if (tid == 0) {
        float r = s[0];
        for (int w = 1; w < 8; w++) r = fmaxf(r, s[w]);
        g_kls[bh] = r;
    }
}

// ---------------- K8: partial kv = exp(k')^T v and column sums ----------------
__global__ __launch_bounds__(128) void k_kvpart() {
    int ch = blockIdx.x, bh = blockIdx.y, m = threadIdx.x;
    float kls = g_kls[bh];
    __shared__ float sv[1024];
    u64t acc2[32];
    #pragma unroll
    for (int d = 0; d < 32; d++) acc2[d] = 0ull;
    float ssum = 0.f;
    for (int t0 = ch*(NTOK/NCH); t0 < (ch+1)*(NTOK/NCH); t0 += 16) {
        __syncthreads();
        for (int l = m; l < 1024; l += 128)
            sv[l] = g_v[((size_t)bh*NTOK + t0 + (l>>6))*EH + (l & 63)];
        __syncthreads();
        for (int tt = 0; tt < 16; tt++) {
            float kpr = __expf(g_kp[((size_t)bh*NTOK + t0 + tt)*MF + m] - kls);
            ssum += kpr;
            u64t kp2 = splat2(kpr);
            const float4* v4 = (const float4*)(sv + tt*64);
            #pragma unroll
            for (int d4 = 0; d4 < 16; d4++) {
                float4 vv = v4[d4];
                fma2(acc2[2*d4],   kp2, pack2(vv.x, vv.y));
                fma2(acc2[2*d4+1], kp2, pack2(vv.z, vv.w));
            }
        }
    }
    float* dst = g_kvp + (((size_t)ch*BH + bh)*MF + m)*EH;
    #pragma unroll
    for (int d2 = 0; d2 < 32; d2++) {
        float2 u = unpk(acc2[d2]);
        dst[2*d2] = u.x; dst[2*d2+1] = u.y;
    }
    g_ksp[(ch*BH + bh)*MF + m] = ssum;
}

// ---------------- K8b: deterministic reduce ----------------
__global__ void k_kvred() {
    int idx = blockIdx.x*256 + threadIdx.x;
    float s = 0.f;
    #pragma unroll
    for (int c = 0; c < NCH; c++) s += g_kvp[(size_t)c*BH*MF*EH + idx];
    g_kv[idx] = s;
    if (idx < BH*MF) {
        float ss = 0.f;
        #pragma unroll
        for (int c = 0; c < NCH; c++) ss += g_ksp[c*BH*MF + idx];
        g_ksum[idx] = ss;
    }
}

// ---------------- K9: qkv = q' kv ; qk1 = q' . ksum ----------------
__global__ __launch_bounds__(128) void k_qkv() {
    int bh = blockIdx.y, tid = threadIdx.x;
    int d = tid & 63, rr = tid >> 6;
    __shared__ float ks[MF];
    __shared__ float qpr[2*MF];
    __shared__ float r4[4];
    u64t kv2[64];
    #pragma unroll
    for (int m2 = 0; m2 < 64; m2++)
        kv2[m2] = pack2(g_kv[((size_t)bh*MF + 2*m2)*EH + d],
                        g_kv[((size_t)bh*MF + 2*m2+1)*EH + d]);
    if (tid < MF) ks[tid] = g_ksum[bh*MF + tid];
    __syncthreads();
    for (int pair = 0; pair < 16; pair++) {
        int tbase = blockIdx.x*32 + pair*2;
        __syncthreads();
        for (int l = tid; l < 256; l += 128)
            qpr[l] = g_qp[((size_t)bh*NTOK + tbase + (l>>7))*MF + (l & 127)];
        __syncthreads();
        const float4* q4 = (const float4*)(qpr + rr*MF);
        u64t acc2 = 0ull;
        #pragma unroll
        for (int m4 = 0; m4 < 32; m4++) {
            float4 qv = q4[m4];
            fma2(acc2, pack2(qv.x, qv.y), kv2[2*m4]);
            fma2(acc2, pack2(qv.z, qv.w), kv2[2*m4+1]);
        }
        float2 su = unpk(acc2);
        g_qkv[((size_t)bh*NTOK + tbase + rr)*EH + d] = su.x + su.y;
        float p = qpr[rr*MF + 2*d]*ks[2*d] + qpr[rr*MF + 2*d+1]*ks[2*d+1];
        #pragma unroll
        for (int o = 16; o; o >>= 1) p += __shfl_down_sync(0xffffffffu, p, o);
        int lane = tid & 31, wp = tid >> 5;
        if (lane == 0) r4[wp] = p;
        __syncthreads();
        if (tid == 0)  g_qk1[bh*NTOK + tbase]     = r4[0] + r4[1];
        if (tid == 64) g_qk1[bh*NTOK + tbase + 1] = r4[2] + r4[3];
    }
}

// ================= bucketed correction: 3 kernels =================
// thread map (256): tx = tid&15 (8 cols), ty = tid>>4 (8 rows)

#define INNER_SMEM ((2*64*IST)*4 + 2*128*4)
__global__ __launch_bounds__(256, 2) void k_inner() {
    extern __shared__ float sm[];
    float* sQt = sm;                    // [64][IST]
    float* sKt = sm + 64*IST;
    int* sQi = (int*)(sm + 2*64*IST);
    int* sKi = sQi + 128;
    int nb = blockIdx.x, bh = blockIdx.y, h = blockIdx.z;
    int tid = threadIdx.x, tx = tid & 15, ty = tid >> 4;
    if (tid < 128) {
        sQi[tid] = g_qpos[(h*BH + bh)*NTOK + nb*128 + tid];
        sKi[tid] = g_kpos[(h*BH + bh)*NTOK + nb*128 + tid];
    }
    __syncthreads();
    for (int idx = tid; idx < 8192; idx += 256) {
        int i = idx >> 6, e = idx & 63;
        sQt[e*IST + i] = g_q[((size_t)bh*NTOK + sQi[i])*EH + e];
        sKt[e*IST + i] = g_k[((size_t)bh*NTOK + sKi[i])*EH + e];
    }
    __syncthreads();
    u64t aI[4][8];
    #pragma unroll
    for (int r = 0; r < 4; r++)
        #pragma unroll
        for (int c = 0; c < 8; c++) aI[r][c] = 0ull;
    for (int e = 0; e < 64; e++) {
        const u64t* ap = (const u64t*)(sQt + e*IST + ty*8);
        float4 b0q = *(const float4*)(sKt + e*IST + tx*8);
        float4 b1q = *(const float4*)(sKt + e*IST + tx*8 + 4);
        u64t bs[8];
        bs[0]=splat2(b0q.x); bs[1]=splat2(b0q.y); bs[2]=splat2(b0q.z); bs[3]=splat2(b0q.w);
        bs[4]=splat2(b1q.x); bs[5]=splat2(b1q.y); bs[6]=splat2(b1q.z); bs[7]=splat2(b1q.w);
        #pragma unroll
        for (int r2 = 0; r2 < 4; r2++) {
            u64t av = ap[r2];
            #pragma unroll
            for (int c = 0; c < 8; c++) fma2(aI[r2][c], av, bs[c]);
        }
    }
    float* dbase = g_dots + ((size_t)(h*BH + bh)*NTOK + nb*128)*128;
    #pragma unroll
    for (int r2 = 0; r2 < 4; r2++) {
        float2 v[8];
        #pragma unroll
        for (int c = 0; c < 8; c++) v[c] = unpk(aI[r2][c]);
        int row = ty*8 + r2*2;
        *(float4*)(dbase + (size_t)row*128 + tx*8)     = make_float4(v[0].x, v[1].x, v[2].x, v[3].x);
        *(float4*)(dbase + (size_t)row*128 + tx*8 + 4) = make_float4(v[4].x, v[5].x, v[6].x, v[7].x);
        *(float4*)(dbase + (size_t)(row+1)*128 + tx*8)     = make_float4(v[0].y, v[1].y, v[2].y, v[3].y);
        *(float4*)(dbase + (size_t)(row+1)*128 + tx*8 + 4) = make_float4(v[4].y, v[5].y, v[6].y, v[7].y);
    }
}

#define PRIME_SMEM ((2*64*IST)*4 + 128*4 + 4*128*4)
__global__ __launch_bounds__(256, 2) void k_prime() {
    extern __shared__ float sm[];
    float* sQPt = sm;                   // [64][IST] (m-chunked)
    float* sKPt = sm + 64*IST;
    float* sPls = sm + 2*64*IST;
    int* sQi = (int*)(sPls + 128);
    int* sKi = sQi + 128;
    int* sQb = sKi + 128;
    int* sKb = sQb + 128;
    int nb = blockIdx.x, bh = blockIdx.y, h = blockIdx.z;
    int tid = threadIdx.x, tx = tid & 15, ty = tid >> 4;
    int o = 1 - h;
    float kls = g_kls[bh];
    if (tid < 128) {
        int qi = g_qpos[(h*BH + bh)*NTOK + nb*128 + tid];
        int ki = g_kpos[(h*BH + bh)*NTOK + nb*128 + tid];
        sQi[tid] = qi; sKi[tid] = ki;
        sQb[tid] = g_qrev[(o*BH + bh)*NTOK + qi] >> 7;
        sKb[tid] = g_krev[(o*BH + bh)*NTOK + ki] >> 7;
        sPls[tid] = g_qls[bh*NTOK + qi] + kls;
    }
    u64t aP[4][8];
    #pragma unroll
    for (int r = 0; r < 4; r++)
        #pragma unroll
        for (int c = 0; c < 8; c++) aP[r][c] = 0ull;
    for (int mc = 0; mc < 2; mc++) {
        __syncthreads();
        for (int idx = tid; idx < 8192; idx += 256) {
            int i = idx >> 6, ml = idx & 63;
            sQPt[ml*IST + i] = g_qp[((size_t)bh*NTOK + sQi[i])*MF + mc*64 + ml];
            sKPt[ml*IST + i] = __expf(g_kp[((size_t)bh*NTOK + sKi[i])*MF + mc*64 + ml] - kls);
        }
        __syncthreads();
        for (int m = 0; m < 64; m++) {
            const u64t* ap = (const u64t*)(sQPt + m*IST + ty*8);
            float4 b0q = *(const float4*)(sKPt + m*IST + tx*8);
            float4 b1q = *(const float4*)(sKPt + m*IST + tx*8 + 4);
            u64t bs[8];
            bs[0]=splat2(b0q.x); bs[1]=splat2(b0q.y); bs[2]=splat2(b0q.z); bs[3]=splat2(b0q.w);
            bs[4]=splat2(b1q.x); bs[5]=splat2(b1q.y); bs[6]=splat2(b1q.z); bs[7]=splat2(b1q.w);
            #pragma unroll
            for (int r2 = 0; r2 < 4; r2++) {
                u64t av = ap[r2];
                #pragma unroll
                for (int c = 0; c < 8; c++) fma2(aP[r2][c], av, bs[c]);
            }
        }
    }
    // epilogue: read inner, dup-correct, LSE, exp, write dots in place
    int kb[8];
    #pragma unroll
    for (int c = 0; c < 8; c++) kb[c] = sKb[tx*8 + c];
    float* dbase = g_dots + ((size_t)(h*BH + bh)*NTOK + nb*128)*128;
    #pragma unroll
    for (int r2 = 0; r2 < 4; r2++) {
        float2 P[8];
        #pragma unroll
        for (int c = 0; c < 8; c++) P[c] = unpk(aP[r2][c]);
        #pragma unroll
        for (int half = 0; half < 2; half++) {
            int row = ty*8 + r2*2 + half;
            int qb = sQb[row]; float pls = sPls[row];
            float4 in0 = *(const float4*)(dbase + (size_t)row*128 + tx*8);
            float4 in1 = *(const float4*)(dbase + (size_t)row*128 + tx*8 + 4);
            float iv[8] = {in0.x, in0.y, in0.z, in0.w, in1.x, in1.y, in1.z, in1.w};
            float pv[8];
            float rm = -1e30f;
            #pragma unroll
            for (int c = 0; c < 8; c++) {
                bool d2 = (qb == kb[c]);
                iv[c] = iv[c]*TEMPF - (d2 ? LN2F : 0.f);
                pv[c] = (half ? P[c].y : P[c].x) * (d2 ? 0.5f : 1.f);
                rm = fmaxf(rm, iv[c]);
            }
            #pragma unroll
            for (int off = 8; off; off >>= 1) rm = fmaxf(rm, __shfl_xor_sync(0xffffffffu, rm, off));
            float l = fmaxf(rm, pls);
            float pe = __expf(pls - l);
            float dv[8];
            float s = 0.f;
            #pragma unroll
            for (int c = 0; c < 8; c++) { dv[c] = __expf(iv[c] - l) - pv[c]*pe; s += dv[c]; }
            *(float4*)(dbase + (size_t)row*128 + tx*8)     = make_float4(dv[0], dv[1], dv[2], dv[3]);
            *(float4*)(dbase + (size_t)row*128 + tx*8 + 4) = make_float4(dv[4], dv[5], dv[6], dv[7]);
            #pragma unroll
            for (int off = 8; off; off >>= 1) s += __shfl_xor_sync(0xffffffffu, s, off);
            if (tx == 0) {
                int t = sQi[row];
                size_t bi = (size_t)(h*BH + bh)*NTOK + t;
                g_lseb[bi] = l;
                g_dsb[bi]  = s;
            }
        }
    }
}

#define OV_SMEM ((128*DST + 128*68)*4 + 2*128*4)
__global__ __launch_bounds__(256, 2) void k_ov() {
    extern __shared__ float sm[];
    float* sD = sm;                     // [128][DST]
    float* sV = sm + 128*DST;           // [128][68]
    int* sQi = (int*)(sV + 128*68);
    int* sKi = sQi + 128;
    int nb = blockIdx.x, bh = blockIdx.y, h = blockIdx.z;
    int tid = threadIdx.x, tx2 = tid & 15, ty2 = tid >> 4;
    if (tid < 128) {
        sQi[tid] = g_qpos[(h*BH + bh)*NTOK + nb*128 + tid];
        sKi[tid] = g_kpos[(h*BH + bh)*NTOK + nb*128 + tid];
    }
    __syncthreads();
    const float* dbase = g_dots + ((size_t)(h*BH + bh)*NTOK + nb*128)*128;
    for (int idx = tid; idx < 4096; idx += 256) {
        int row = idx >> 5, c4 = idx & 31;
        *(float4*)(sD + row*DST + c4*4) = *(const float4*)(dbase + (size_t)row*128 + c4*4);
    }
    for (int idx = tid; idx < 8192; idx += 256) {
        int i = idx >> 6, d = idx & 63;
        sV[i*68 + d] = g_v[((size_t)bh*NTOK + sKi[i])*EH + d];
    }
    __syncthreads();
    u64t accO[8][2];
    #pragma unroll
    for (int r = 0; r < 8; r++) { accO[r][0] = 0ull; accO[r][1] = 0ull; }
    for (int j0 = 0; j0 < 128; j0 += 4) {
        float4 a[8];
        #pragma unroll
        for (int r = 0; r < 8; r++) a[r] = *(const float4*)(sD + (ty2*8 + r)*DST + j0);
        #pragma unroll
        for (int jj = 0; jj < 4; jj++) {
            float4 t = *(const float4*)(sV + (j0 + jj)*68 + tx2*4);
            u64t bv0 = pack2(t.x, t.y), bv1 = pack2(t.z, t.w);
            #pragma unroll
            for (int r = 0; r < 8; r++) {
                float av = (jj==0)?a[r].x:(jj==1)?a[r].y:(jj==2)?a[r].z:a[r].w;
                u64t s = splat2(av);
                fma2(accO[r][0], s, bv0); fma2(accO[r][1], s, bv1);
            }
        }
    }
    #pragma unroll
    for (int r = 0; r < 8; r++) {
        int t = sQi[ty2*8 + r];
        float2 u0 = unpk(accO[r][0]), u1 = unpk(accO[r][1]);
        *(float4*)(g_ob + ((size_t)(h*BH + bh)*NTOK + t)*EH + tx2*4) =
            make_float4(u0.x, u0.y, u1.x, u1.y);
    }
}

// ---------------- K11: merge performer + LSH branches ----------------
__global__ void k_merge() {
    int tid = threadIdx.x;
    int t = blockIdx.x*4 + (tid >> 6);
    int d = tid & 63;
    int bh = blockIdx.y;
    size_t i0 = (size_t)bh*NTOK + t;
    size_t i1 = (size_t)(BH + bh)*NTOK + t;
    float l0 = g_lseb[i0], l1 = g_lseb[i1];
    float mx = fmaxf(l0, l1);
    float norm = mx + logf(__expf(l0 - mx) + __expf(l1 - mx));
    float p0 = __expf(l0 - norm), p1 = __expf(l1 - norm);
    float pls = g_qls[bh*NTOK + t] + g_kls[bh];
    float psc = __expf(pls - norm);
    float z = g_dsb[i0]*p0 + g_dsb[i1]*p1 + g_qk1[bh*NTOK + t]*psc;
    z = fmaxf(z, 1e-6f);
    size_t base = ((size_t)bh*NTOK + t)*EH + d;
    float outv = g_ob[i0*EH + d]*p0 + g_ob[i1*EH + d]*p1 + g_qkv[base]*psc;
    g_on[base] = outv / z;
}

// ---------------- K12: final projection (16 tokens/block) ----------------
#define WS 130
#define XS 132
__global__ __launch_bounds__(256) void k_final(const float* __restrict__ Wf,
                                               const float* __restrict__ bias,
                                               float* __restrict__ out) {
    __shared__ float sW2[64*WS];
    __shared__ float sX[16*XS];
    int tid = threadIdx.x;
    int tok = tid >> 6, eo = tid & 63;
    int g0 = blockIdx.x*16;
    u64t acc2[4];
    #pragma unroll
    for (int tt = 0; tt < 4; tt++) acc2[tt] = 0ull;
    for (int c = 0; c < 4; c++) {
        __syncthreads();
        for (int idx = tid; idx < 8192; idx += 256) {
            int e2 = idx >> 7, hd = idx & 127;
            sW2[e2*WS + hd] = Wf[e2*512 + c*128 + hd];
        }
        for (int idx = tid; idx < 2048; idx += 256) {
            int tk = idx >> 7, hd = idx & 127;
            int gg = g0 + tk;
            int b = gg >> 12, t = gg & 4095;
            int hdg = c*128 + hd;
            sX[tk*XS + hd] = g_on[(((size_t)(b*8 + (hdg >> 6)))*NTOK + t)*EH + (hdg & 63)];
        }
        __syncthreads();
        const u64t* wp = (const u64t*)(sW2 + eo*WS);
        #pragma unroll
        for (int tt = 0; tt < 4; tt++) {
            const float4* x4 = (const float4*)(sX + (tok + tt*4)*XS);
            #pragma unroll
            for (int h4 = 0; h4 < 32; h4++) {
                float4 xv = x4[h4];
                fma2(acc2[tt], pack2(xv.x, xv.y), wp[2*h4]);
                fma2(acc2[tt], pack2(xv.z, xv.w), wp[2*h4+1]);
            }
        }
    }
    float bv = bias[eo];
    #pragma unroll
    for (int tt = 0; tt < 4; tt++) {
        float2 u = unpk(acc2[tt]);
        out[(size_t)(g0 + tok + tt*4)*EH + eo] = u.x + u.y + bv;
    }
}

// ---------------- launch ----------------
extern "C" void kernel_launch(void* const* d_in, const int* in_sizes, int n_in,
                              void* d_out, int out_size) {
    const float* query = (const float*)d_in[0];
    const float* key   = (const float*)d_in[1];
    const float* value = (const float*)d_in[2];
    const float* projW = (const float*)d_in[3];
    const float* alpha = (const float*)d_in[4];
    const float* beta  = (const float*)d_in[5];
    const float* outW  = (const float*)d_in[6];
    const float* outb  = (const float*)d_in[7];
    float* out = (float*)d_out;

    cudaFuncSetAttribute(k_inner, cudaFuncAttributeMaxDynamicSharedMemorySize, INNER_SMEM);
    cudaFuncSetAttribute(k_prime, cudaFuncAttributeMaxDynamicSharedMemorySize, PRIME_SMEM);
    cudaFuncSetAttribute(k_ov,    cudaFuncAttributeMaxDynamicSharedMemorySize, OV_SMEM);

    k_split<<<dim3(NTOK/4, BH), 256>>>(query, key, value);
    k_maxn<<<BH, 256>>>();
    k_hash<<<dim3(NTOK/256, BH), 256>>>(alpha, beta);
    k_feat<<<dim3(NTOK/32, BH, 2), 256>>>(projW);
    k_sort<<<128, 512>>>();
    k_kls<<<BH, 256>>>();
    k_kvpart<<<dim3(NCH, BH), 128>>>();
    k_kvred<<<BH*MF*EH/256, 256>>>();
    k_qkv<<<dim3(NTOK/32, BH), 128>>>();
    k_inner<<<dim3(32, BH, 2), 256, INNER_SMEM>>>();
    k_prime<<<dim3(32, BH, 2), 256, PRIME_SMEM>>>();
    k_ov<<<dim3(32, BH, 2), 256, OV_SMEM>>>();
    k_merge<<<dim3(NTOK/4, BH), 256>>>();
    k_final<<<NTOK*4/16, 256>>>(outW, outb, out);
}

// round 6
// speedup vs baseline: 1.6259x; 1.1939x over previous
#include <cuda_runtime.h>
#include <math.h>

#define BH 32
#define NTOK 4096
#define EH 64
#define MF 128
#define DM 512
#define NCH 32
#define IST 132
#define FST 132
#define DST 132

#define SQRT_TEMP 0.35355339059327373f
#define TEMPF 0.125f
#define HALF_LOG_M 2.4260151319598084f
#define LN2F 0.6931471805599453f

typedef unsigned long long u64t;
__device__ __forceinline__ u64t splat2(float x) {
    u64t r; asm("mov.b64 %0, {%1, %1};" : "=l"(r) : "f"(x)); return r;
}
__device__ __forceinline__ u64t pack2(float x, float y) {
    u64t r; asm("mov.b64 %0, {%1, %2};" : "=l"(r) : "f"(x), "f"(y)); return r;
}
__device__ __forceinline__ void fma2(u64t& c, u64t a, u64t b) {
    asm("fma.rn.f32x2 %0, %1, %2, %0;" : "+l"(c) : "l"(a), "l"(b));
}
__device__ __forceinline__ float2 unpk(u64t v) {
    float2 f; asm("mov.b64 {%0, %1}, %2;" : "=f"(f.x), "=f"(f.y) : "l"(v)); return f;
}

// ---------------- scratch ----------------
__device__ float g_q[BH*NTOK*EH];
__device__ float g_k[BH*NTOK*EH];
__device__ float g_v[BH*NTOK*EH];
__device__ float g_qn2[BH*NTOK];
__device__ float g_kn2[BH*NTOK];
__device__ float g_MQ2[BH];
__device__ float g_MK2[BH];
__device__ float g_hashq[2*BH*NTOK];
__device__ float g_hashk[2*BH*NTOK];
__device__ int   g_qpos[2*BH*NTOK];
__device__ int   g_kpos[2*BH*NTOK];
__device__ int   g_qrev[2*BH*NTOK];
__device__ int   g_krev[2*BH*NTOK];
__device__ float g_qp[(size_t)BH*NTOK*MF];
__device__ float g_kp[(size_t)BH*NTOK*MF];    // log-phi (pre-exp)
__device__ float g_qls[BH*NTOK];
__device__ float g_krm[BH*NTOK];
__device__ float g_kls[BH];
__device__ float g_kvp[(size_t)NCH*BH*MF*EH];
__device__ float g_ksp[NCH*BH*MF];
__device__ float g_kv[BH*MF*EH];
__device__ float g_ksum[BH*MF];
__device__ float g_qk1[BH*NTOK];
__device__ float g_qkv[(size_t)BH*NTOK*EH];
__device__ float g_dots[(size_t)2*BH*NTOK*128];   // inner then dots, in place
__device__ float g_ob[(size_t)2*BH*NTOK*EH];
__device__ float g_lseb[2*BH*NTOK];
__device__ float g_dsb[2*BH*NTOK];
__device__ float g_on[(size_t)BH*NTOK*EH];

// ---------------- K1: split heads + squared norms ----------------
__global__ __launch_bounds__(256) void k_split(const float* __restrict__ query,
                                               const float* __restrict__ key,
                                               const float* __restrict__ value) {
    int tid = threadIdx.x;
    int tl = tid >> 6, e = tid & 63;
    int t = blockIdx.x*4 + tl, bh = blockIdx.y;
    int b = bh >> 3, hh = bh & 7;
    size_t gi = ((size_t)(b*NTOK + t))*DM + hh*EH + e;
    float qv = query[gi], kv = key[gi], vv = value[gi];
    size_t oi = ((size_t)bh*NTOK + t)*EH + e;
    g_q[oi] = qv; g_k[oi] = kv; g_v[oi] = vv;
    float q2 = qv*qv, k2 = kv*kv;
    #pragma unroll
    for (int o = 16; o; o >>= 1) {
        q2 += __shfl_down_sync(0xffffffffu, q2, o);
        k2 += __shfl_down_sync(0xffffffffu, k2, o);
    }
    __shared__ float sq[8], sk[8];
    if ((tid & 31) == 0) { sq[tid>>5] = q2; sk[tid>>5] = k2; }
    __syncthreads();
    if (e == 0) {
        g_qn2[bh*NTOK + t] = sq[2*tl] + sq[2*tl+1];
        g_kn2[bh*NTOK + t] = sk[2*tl] + sk[2*tl+1];
    }
}

// ---------------- K2: per-bh max squared norms ----------------
__global__ void k_maxn() {
    int bh = blockIdx.x, tid = threadIdx.x;
    float mq = 0.f, mk = 0.f;
    for (int i = tid; i < NTOK; i += 256) {
        mq = fmaxf(mq, g_qn2[bh*NTOK + i]);
        mk = fmaxf(mk, g_kn2[bh*NTOK + i]);
    }
    #pragma unroll
    for (int o = 16; o; o >>= 1) {
        mq = fmaxf(mq, __shfl_xor_sync(0xffffffffu, mq, o));
        mk = fmaxf(mk, __shfl_xor_sync(0xffffffffu, mk, o));
    }
    __shared__ float sq[8], sk[8];
    if ((tid & 31) == 0) { sq[tid>>5] = mq; sk[tid>>5] = mk; }
    __syncthreads();
    if (tid == 0) {
        float a = sq[0], b = sk[0];
        for (int w = 1; w < 8; w++) { a = fmaxf(a, sq[w]); b = fmaxf(b, sk[w]); }
        g_MQ2[bh] = a; g_MK2[bh] = b;
    }
}

// ---------------- K3: LSH hashes ----------------
__global__ void k_hash(const float* __restrict__ alpha, const float* __restrict__ beta) {
    __shared__ float sal[2*(EH+2)];
    __shared__ float sbe[2];
    int bh = blockIdx.y;
    int tid = threadIdx.x;
    if (tid < 2*(EH+2)) sal[tid] = alpha[tid];
    if (tid < 2) sbe[tid] = beta[tid];
    __syncthreads();
    int t = blockIdx.x*256 + tid;
    const float* qr = g_q + ((size_t)bh*NTOK + t)*EH;
    const float* kr = g_k + ((size_t)bh*NTOK + t)*EH;
    float a0 = 0.f, a1 = 0.f, c0 = 0.f, c1 = 0.f;
    #pragma unroll 8
    for (int e = 0; e < EH; e++) {
        float al0 = sal[e*2], al1 = sal[e*2+1];
        float qe = qr[e], ke = kr[e];
        a0 += qe*al0; a1 += qe*al1;
        c0 += ke*al0; c1 += ke*al1;
    }
    float S = g_MQ2[bh] + g_MK2[bh];
    float extq = sqrtf(fmaxf(S - g_qn2[bh*NTOK + t], 0.f));
    float extk = sqrtf(fmaxf(S - g_kn2[bh*NTOK + t], 0.f));
    g_hashq[bh*NTOK + t]           = a0 + extq*sal[EH*2]       + sbe[0];
    g_hashq[BH*NTOK + bh*NTOK + t] = a1 + extq*sal[EH*2+1]     + sbe[1];
    g_hashk[bh*NTOK + t]           = c0 + extk*sal[(EH+1)*2]   + sbe[0];
    g_hashk[BH*NTOK + bh*NTOK + t] = c1 + extk*sal[(EH+1)*2+1] + sbe[1];
}

// ---------------- K5: performer feature maps as tiled GEMM ----------------
#define FEATG_SMEM (2*64*FST*4 + 128*4)
__global__ __launch_bounds__(256, 2) void k_featg(const float* __restrict__ W) {
    extern __shared__ float sm[];
    float* sXt = sm;                    // [64][FST]
    float* sWt = sm + 64*FST;           // [64][FST]
    float* sN  = sm + 2*64*FST;         // [128]
    int nb = blockIdx.x, bh = blockIdx.y, isK = blockIdx.z;
    int tid = threadIdx.x, tx = tid & 15, ty = tid >> 4;
    const float* X  = isK ? g_k   : g_q;
    const float* n2 = isK ? g_kn2 : g_qn2;
    int tb = nb*128;
    for (int idx = tid; idx < 8192; idx += 256) {
        int i = idx >> 6, e = idx & 63;
        sXt[e*FST + i] = X[((size_t)bh*NTOK + tb + i)*EH + e];
        sWt[e*FST + i] = W[i*EH + e];
    }
    if (tid < 128) sN[tid] = n2[bh*NTOK + tb + tid];
    __syncthreads();
    u64t acc[4][8];
    #pragma unroll
    for (int r = 0; r < 4; r++)
        #pragma unroll
        for (int c = 0; c < 8; c++) acc[r][c] = 0ull;
    for (int e = 0; e < 64; e++) {
        const u64t* ap = (const u64t*)(sXt + e*FST + ty*8);
        float4 b0q = *(const float4*)(sWt + e*FST + tx*8);
        float4 b1q = *(const float4*)(sWt + e*FST + tx*8 + 4);
        u64t bs[8];
        bs[0]=splat2(b0q.x); bs[1]=splat2(b0q.y); bs[2]=splat2(b0q.z); bs[3]=splat2(b0q.w);
        bs[4]=splat2(b1q.x); bs[5]=splat2(b1q.y); bs[6]=splat2(b1q.z); bs[7]=splat2(b1q.w);
        #pragma unroll
        for (int r2 = 0; r2 < 4; r2++) {
            u64t av = ap[r2];
            #pragma unroll
            for (int c = 0; c < 8; c++) fma2(acc[r2][c], av, bs[c]);
        }
    }
    #pragma unroll
    for (int r2 = 0; r2 < 4; r2++) {
        float2 v[8];
        #pragma unroll
        for (int c = 0; c < 8; c++) v[c] = unpk(acc[r2][c]);
        #pragma unroll
        for (int half = 0; half < 2; half++) {
            int row = ty*8 + r2*2 + half;
            int t = tb + row;
            float nn = 0.5f*TEMPF*sN[row] + HALF_LOG_M;
            float lp[8];
            float rm = -1e30f;
            #pragma unroll
            for (int c = 0; c < 8; c++) {
                lp[c] = (half ? v[c].y : v[c].x)*SQRT_TEMP - nn;
                rm = fmaxf(rm, lp[c]);
            }
            #pragma unroll
            for (int off = 8; off; off >>= 1) rm = fmaxf(rm, __shfl_xor_sync(0xffffffffu, rm, off));
            size_t base = ((size_t)bh*NTOK + t)*MF + tx*8;
            if (!isK) {
                *(float4*)(g_qp + base) = make_float4(__expf(lp[0]-rm), __expf(lp[1]-rm),
                                                      __expf(lp[2]-rm), __expf(lp[3]-rm));
                *(float4*)(g_qp + base + 4) = make_float4(__expf(lp[4]-rm), __expf(lp[5]-rm),
                                                          __expf(lp[6]-rm), __expf(lp[7]-rm));
                if (tx == 0) g_qls[bh*NTOK + t] = rm;
            } else {
                *(float4*)(g_kp + base)     = make_float4(lp[0], lp[1], lp[2], lp[3]);
                *(float4*)(g_kp + base + 4) = make_float4(lp[4], lp[5], lp[6], lp[7]);
                if (tx == 0) g_krm[bh*NTOK + t] = rm;
            }
        }
    }
}

// ---------------- K4: stable bitonic argsort ----------------
__global__ void k_sort() {
    __shared__ float sv[NTOK];
    __shared__ int   si[NTOK];
    int which = blockIdx.x >> 6;
    int rem   = blockIdx.x & 63;
    const float* src = which ? (g_hashk + (size_t)rem*NTOK) : (g_hashq + (size_t)rem*NTOK);
    int tid = threadIdx.x;
    for (int i = tid; i < NTOK; i += 512) { sv[i] = src[i]; si[i] = i; }
    __syncthreads();
    for (int k = 2; k <= NTOK; k <<= 1)
        for (int j = k >> 1; j > 0; j >>= 1) {
            for (int p = tid; p < NTOK/2; p += 512) {
                int i  = ((p & ~(j-1)) << 1) | (p & (j-1));
                int ix = i | j;
                bool up = ((i & k) == 0);
                float vi = sv[i], vj = sv[ix];
                int ii = si[i], ij = si[ix];
                bool agt = (vi > vj) || (vi == vj && ii > ij);
                if (agt == up) { sv[i] = vj; sv[ix] = vi; si[i] = ij; si[ix] = ii; }
            }
            __syncthreads();
        }
    int* pos = which ? g_kpos : g_qpos;
    int* rev = which ? g_krev : g_qrev;
    for (int r = tid; r < NTOK; r += 512) {
        int idx = si[r];
        pos[rem*NTOK + r]   = idx;
        rev[rem*NTOK + idx] = r;
    }
}

// ---------------- K6: per-bh max of k log-phi ----------------
__global__ void k_kls() {
    int bh = blockIdx.x, tid = threadIdx.x;
    float m = -1e30f;
    for (int i = tid; i < NTOK; i += 256) m = fmaxf(m, g_krm[bh*NTOK + i]);
    #pragma unroll
    for (int o = 16; o; o >>= 1) m = fmaxf(m, __shfl_xor_sync(0xffffffffu, m, o));
    __shared__ float s[8];
    if ((tid & 31) == 0) s[tid>>5] = m;
    __syncthreads();
    if (tid == 0) {
        float r = s[0];
        for (int w = 1; w < 8; w++) r = fmaxf(r, s[w]);
        g_kls[bh] = r;
    }
}

// ---------------- K8: partial kv = exp(k')^T v and column sums ----------------
__global__ __launch_bounds__(128) void k_kvpart() {
    int ch = blockIdx.x, bh = blockIdx.y, m = threadIdx.x;
    float kls = g_kls[bh];
    __shared__ float sv[1024];
    u64t acc2[32];
    #pragma unroll
    for (int d = 0; d < 32; d++) acc2[d] = 0ull;
    float ssum = 0.f;
    for (int t0 = ch*(NTOK/NCH); t0 < (ch+1)*(NTOK/NCH); t0 += 16) {
        __syncthreads();
        for (int l = m; l < 1024; l += 128)
            sv[l] = g_v[((size_t)bh*NTOK + t0 + (l>>6))*EH + (l & 63)];
        __syncthreads();
        for (int tt = 0; tt < 16; tt++) {
            float kpr = __expf(g_kp[((size_t)bh*NTOK + t0 + tt)*MF + m] - kls);
            ssum += kpr;
            u64t kp2 = splat2(kpr);
            const float4* v4 = (const float4*)(sv + tt*64);
            #pragma unroll
            for (int d4 = 0; d4 < 16; d4++) {
                float4 vv = v4[d4];
                fma2(acc2[2*d4],   kp2, pack2(vv.x, vv.y));
                fma2(acc2[2*d4+1], kp2, pack2(vv.z, vv.w));
            }
        }
    }
    float* dst = g_kvp + (((size_t)ch*BH + bh)*MF + m)*EH;
    #pragma unroll
    for (int d2 = 0; d2 < 32; d2++) {
        float2 u = unpk(acc2[d2]);
        dst[2*d2] = u.x; dst[2*d2+1] = u.y;
    }
    g_ksp[(ch*BH + bh)*MF + m] = ssum;
}

// ---------------- K8b: deterministic reduce ----------------
__global__ void k_kvred() {
    int idx = blockIdx.x*256 + threadIdx.x;
    float s = 0.f;
    #pragma unroll
    for (int c = 0; c < NCH; c++) s += g_kvp[(size_t)c*BH*MF*EH + idx];
    g_kv[idx] = s;
    if (idx < BH*MF) {
        float ss = 0.f;
        #pragma unroll
        for (int c = 0; c < NCH; c++) ss += g_ksp[c*BH*MF + idx];
        g_ksum[idx] = ss;
    }
}

// ---------------- K9: qkv = q' kv ; qk1 = q' . ksum ----------------
__global__ __launch_bounds__(128) void k_qkv() {
    int bh = blockIdx.y, tid = threadIdx.x;
    int d = tid & 63, rr = tid >> 6;
    __shared__ float ks[MF];
    __shared__ float qpr[2*MF];
    __shared__ float r4[4];
    u64t kv2[64];
    #pragma unroll
    for (int m2 = 0; m2 < 64; m2++)
        kv2[m2] = pack2(g_kv[((size_t)bh*MF + 2*m2)*EH + d],
                        g_kv[((size_t)bh*MF + 2*m2+1)*EH + d]);
    if (tid < MF) ks[tid] = g_ksum[bh*MF + tid];
    __syncthreads();
    for (int pair = 0; pair < 16; pair++) {
        int tbase = blockIdx.x*32 + pair*2;
        __syncthreads();
        for (int l = tid; l < 256; l += 128)
            qpr[l] = g_qp[((size_t)bh*NTOK + tbase + (l>>7))*MF + (l & 127)];
        __syncthreads();
        const float4* q4 = (const float4*)(qpr + rr*MF);
        u64t acc2 = 0ull;
        #pragma unroll
        for (int m4 = 0; m4 < 32; m4++) {
            float4 qv = q4[m4];
            fma2(acc2, pack2(qv.x, qv.y), kv2[2*m4]);
            fma2(acc2, pack2(qv.z, qv.w), kv2[2*m4+1]);
        }
        float2 su = unpk(acc2);
        g_qkv[((size_t)bh*NTOK + tbase + rr)*EH + d] = su.x + su.y;
        float p = qpr[rr*MF + 2*d]*ks[2*d] + qpr[rr*MF + 2*d+1]*ks[2*d+1];
        #pragma unroll
        for (int o = 16; o; o >>= 1) p += __shfl_down_sync(0xffffffffu, p, o);
        int lane = tid & 31, wp = tid >> 5;
        if (lane == 0) r4[wp] = p;
        __syncthreads();
        if (tid == 0)  g_qk1[bh*NTOK + tbase]     = r4[0] + r4[1];
        if (tid == 64) g_qk1[bh*NTOK + tbase + 1] = r4[2] + r4[3];
    }
}

// ================= bucketed correction: 3 kernels =================
#define INNER_SMEM ((2*64*IST)*4 + 2*128*4)
__global__ __launch_bounds__(256, 2) void k_inner() {
    extern __shared__ float sm[];
    float* sQt = sm;                    // [64][IST]
    float* sKt = sm + 64*IST;
    int* sQi = (int*)(sm + 2*64*IST);
    int* sKi = sQi + 128;
    int nb = blockIdx.x, bh = blockIdx.y, h = blockIdx.z;
    int tid = threadIdx.x, tx = tid & 15, ty = tid >> 4;
    if (tid < 128) {
        sQi[tid] = g_qpos[(h*BH + bh)*NTOK + nb*128 + tid];
        sKi[tid] = g_kpos[(h*BH + bh)*NTOK + nb*128 + tid];
    }
    __syncthreads();
    for (int idx = tid; idx < 8192; idx += 256) {
        int i = idx >> 6, e = idx & 63;
        sQt[e*IST + i] = g_q[((size_t)bh*NTOK + sQi[i])*EH + e];
        sKt[e*IST + i] = g_k[((size_t)bh*NTOK + sKi[i])*EH + e];
    }
    __syncthreads();
    u64t aI[4][8];
    #pragma unroll
    for (int r = 0; r < 4; r++)
        #pragma unroll
        for (int c = 0; c < 8; c++) aI[r][c] = 0ull;
    for (int e = 0; e < 64; e++) {
        const u64t* ap = (const u64t*)(sQt + e*IST + ty*8);
        float4 b0q = *(const float4*)(sKt + e*IST + tx*8);
        float4 b1q = *(const float4*)(sKt + e*IST + tx*8 + 4);
        u64t bs[8];
        bs[0]=splat2(b0q.x); bs[1]=splat2(b0q.y); bs[2]=splat2(b0q.z); bs[3]=splat2(b0q.w);
        bs[4]=splat2(b1q.x); bs[5]=splat2(b1q.y); bs[6]=splat2(b1q.z); bs[7]=splat2(b1q.w);
        #pragma unroll
        for (int r2 = 0; r2 < 4; r2++) {
            u64t av = ap[r2];
            #pragma unroll
            for (int c = 0; c < 8; c++) fma2(aI[r2][c], av, bs[c]);
        }
    }
    float* dbase = g_dots + ((size_t)(h*BH + bh)*NTOK + nb*128)*128;
    #pragma unroll
    for (int r2 = 0; r2 < 4; r2++) {
        float2 v[8];
        #pragma unroll
        for (int c = 0; c < 8; c++) v[c] = unpk(aI[r2][c]);
        int row = ty*8 + r2*2;
        *(float4*)(dbase + (size_t)row*128 + tx*8)     = make_float4(v[0].x, v[1].x, v[2].x, v[3].x);
        *(float4*)(dbase + (size_t)row*128 + tx*8 + 4) = make_float4(v[4].x, v[5].x, v[6].x, v[7].x);
        *(float4*)(dbase + (size_t)(row+1)*128 + tx*8)     = make_float4(v[0].y, v[1].y, v[2].y, v[3].y);
        *(float4*)(dbase + (size_t)(row+1)*128 + tx*8 + 4) = make_float4(v[4].y, v[5].y, v[6].y, v[7].y);
    }
}

#define PRIME_SMEM ((2*64*IST)*4 + 128*4 + 4*128*4)
__global__ __launch_bounds__(256, 2) void k_prime() {
    extern __shared__ float sm[];
    float* sQPt = sm;                   // [64][IST] (m-chunked)
    float* sKPt = sm + 64*IST;
    float* sPls = sm + 2*64*IST;
    int* sQi = (int*)(sPls + 128);
    int* sKi = sQi + 128;
    int* sQb = sKi + 128;
    int* sKb = sQb + 128;
    int nb = blockIdx.x, bh = blockIdx.y, h = blockIdx.z;
    int tid = threadIdx.x, tx = tid & 15, ty = tid >> 4;
    int o = 1 - h;
    float kls = g_kls[bh];
    if (tid < 128) {
        int qi = g_qpos[(h*BH + bh)*NTOK + nb*128 + tid];
        int ki = g_kpos[(h*BH + bh)*NTOK + nb*128 + tid];
        sQi[tid] = qi; sKi[tid] = ki;
        sQb[tid] = g_qrev[(o*BH + bh)*NTOK + qi] >> 7;
        sKb[tid] = g_krev[(o*BH + bh)*NTOK + ki] >> 7;
        sPls[tid] = g_qls[bh*NTOK + qi] + kls;
    }
    u64t aP[4][8];
    #pragma unroll
    for (int r = 0; r < 4; r++)
        #pragma unroll
        for (int c = 0; c < 8; c++) aP[r][c] = 0ull;
    for (int mc = 0; mc < 2; mc++) {
        __syncthreads();
        for (int idx = tid; idx < 8192; idx += 256) {
            int i = idx >> 6, ml = idx & 63;
            sQPt[ml*IST + i] = g_qp[((size_t)bh*NTOK + sQi[i])*MF + mc*64 + ml];
            sKPt[ml*IST + i] = __expf(g_kp[((size_t)bh*NTOK + sKi[i])*MF + mc*64 + ml] - kls);
        }
        __syncthreads();
        for (int m = 0; m < 64; m++) {
            const u64t* ap = (const u64t*)(sQPt + m*IST + ty*8);
            float4 b0q = *(const float4*)(sKPt + m*IST + tx*8);
            float4 b1q = *(const float4*)(sKPt + m*IST + tx*8 + 4);
            u64t bs[8];
            bs[0]=splat2(b0q.x); bs[1]=splat2(b0q.y); bs[2]=splat2(b0q.z); bs[3]=splat2(b0q.w);
            bs[4]=splat2(b1q.x); bs[5]=splat2(b1q.y); bs[6]=splat2(b1q.z); bs[7]=splat2(b1q.w);
            #pragma unroll
            for (int r2 = 0; r2 < 4; r2++) {
                u64t av = ap[r2];
                #pragma unroll
                for (int c = 0; c < 8; c++) fma2(aP[r2][c], av, bs[c]);
            }
        }
    }
    int kb[8];
    #pragma unroll
    for (int c = 0; c < 8; c++) kb[c] = sKb[tx*8 + c];
    float* dbase = g_dots + ((size_t)(h*BH + bh)*NTOK + nb*128)*128;
    #pragma unroll
    for (int r2 = 0; r2 < 4; r2++) {
        float2 P[8];
        #pragma unroll
        for (int c = 0; c < 8; c++) P[c] = unpk(aP[r2][c]);
        #pragma unroll
        for (int half = 0; half < 2; half++) {
            int row = ty*8 + r2*2 + half;
            int qb = sQb[row]; float pls = sPls[row];
            float4 in0 = *(const float4*)(dbase + (size_t)row*128 + tx*8);
            float4 in1 = *(const float4*)(dbase + (size_t)row*128 + tx*8 + 4);
            float iv[8] = {in0.x, in0.y, in0.z, in0.w, in1.x, in1.y, in1.z, in1.w};
            float pv[8];
            float rm = -1e30f;
            #pragma unroll
            for (int c = 0; c < 8; c++) {
                bool d2 = (qb == kb[c]);
                iv[c] = iv[c]*TEMPF - (d2 ? LN2F : 0.f);
                pv[c] = (half ? P[c].y : P[c].x) * (d2 ? 0.5f : 1.f);
                rm = fmaxf(rm, iv[c]);
            }
            #pragma unroll
            for (int off = 8; off; off >>= 1) rm = fmaxf(rm, __shfl_xor_sync(0xffffffffu, rm, off));
            float l = fmaxf(rm, pls);
            float pe = __expf(pls - l);
            float dv[8];
            float s = 0.f;
            #pragma unroll
            for (int c = 0; c < 8; c++) { dv[c] = __expf(iv[c] - l) - pv[c]*pe; s += dv[c]; }
            *(float4*)(dbase + (size_t)row*128 + tx*8)     = make_float4(dv[0], dv[1], dv[2], dv[3]);
            *(float4*)(dbase + (size_t)row*128 + tx*8 + 4) = make_float4(dv[4], dv[5], dv[6], dv[7]);
            #pragma unroll
            for (int off = 8; off; off >>= 1) s += __shfl_xor_sync(0xffffffffu, s, off);
            if (tx == 0) {
                int t = sQi[row];
                size_t bi = (size_t)(h*BH + bh)*NTOK + t;
                g_lseb[bi] = l;
                g_dsb[bi]  = s;
            }
        }
    }
}

#define OV_SMEM ((128*DST + 128*68)*4 + 2*128*4)
__global__ __launch_bounds__(256, 2) void k_ov() {
    extern __shared__ float sm[];
    float* sD = sm;                     // [128][DST]
    float* sV = sm + 128*DST;           // [128][68]
    int* sQi = (int*)(sV + 128*68);
    int* sKi = sQi + 128;
    int nb = blockIdx.x, bh = blockIdx.y, h = blockIdx.z;
    int tid = threadIdx.x, tx2 = tid & 15, ty2 = tid >> 4;
    if (tid < 128) {
        sQi[tid] = g_qpos[(h*BH + bh)*NTOK + nb*128 + tid];
        sKi[tid] = g_kpos[(h*BH + bh)*NTOK + nb*128 + tid];
    }
    __syncthreads();
    const float* dbase = g_dots + ((size_t)(h*BH + bh)*NTOK + nb*128)*128;
    for (int idx = tid; idx < 4096; idx += 256) {
        int row = idx >> 5, c4 = idx & 31;
        *(float4*)(sD + row*DST + c4*4) = *(const float4*)(dbase + (size_t)row*128 + c4*4);
    }
    for (int idx = tid; idx < 8192; idx += 256) {
        int i = idx >> 6, d = idx & 63;
        sV[i*68 + d] = g_v[((size_t)bh*NTOK + sKi[i])*EH + d];
    }
    __syncthreads();
    u64t accO[8][2];
    #pragma unroll
    for (int r = 0; r < 8; r++) { accO[r][0] = 0ull; accO[r][1] = 0ull; }
    for (int j0 = 0; j0 < 128; j0 += 4) {
        float4 a[8];
        #pragma unroll
        for (int r = 0; r < 8; r++) a[r] = *(const float4*)(sD + (ty2*8 + r)*DST + j0);
        #pragma unroll
        for (int jj = 0; jj < 4; jj++) {
            float4 t = *(const float4*)(sV + (j0 + jj)*68 + tx2*4);
            u64t bv0 = pack2(t.x, t.y), bv1 = pack2(t.z, t.w);
            #pragma unroll
            for (int r = 0; r < 8; r++) {
                float av = (jj==0)?a[r].x:(jj==1)?a[r].y:(jj==2)?a[r].z:a[r].w;
                u64t s = splat2(av);
                fma2(accO[r][0], s, bv0); fma2(accO[r][1], s, bv1);
            }
        }
    }
    #pragma unroll
    for (int r = 0; r < 8; r++) {
        int t = sQi[ty2*8 + r];
        float2 u0 = unpk(accO[r][0]), u1 = unpk(accO[r][1]);
        *(float4*)(g_ob + ((size_t)(h*BH + bh)*NTOK + t)*EH + tx2*4) =
            make_float4(u0.x, u0.y, u1.x, u1.y);
    }
}

// ---------------- K11: merge performer + LSH branches ----------------
__global__ void k_merge() {
    int tid = threadIdx.x;
    int t = blockIdx.x*4 + (tid >> 6);
    int d = tid & 63;
    int bh = blockIdx.y;
    size_t i0 = (size_t)bh*NTOK + t;
    size_t i1 = (size_t)(BH + bh)*NTOK + t;
    float l0 = g_lseb[i0], l1 = g_lseb[i1];
    float mx = fmaxf(l0, l1);
    float norm = mx + logf(__expf(l0 - mx) + __expf(l1 - mx));
    float p0 = __expf(l0 - norm), p1 = __expf(l1 - norm);
    float pls = g_qls[bh*NTOK + t] + g_kls[bh];
    float psc = __expf(pls - norm);
    float z = g_dsb[i0]*p0 + g_dsb[i1]*p1 + g_qk1[bh*NTOK + t]*psc;
    z = fmaxf(z, 1e-6f);
    size_t base = ((size_t)bh*NTOK + t)*EH + d;
    float outv = g_ob[i0*EH + d]*p0 + g_ob[i1*EH + d]*p1 + g_qkv[base]*psc;
    g_on[base] = outv / z;
}

// ---------------- K12: final projection (16 tokens/block) ----------------
#define WS 130
#define XS 132
__global__ __launch_bounds__(256) void k_final(const float* __restrict__ Wf,
                                               const float* __restrict__ bias,
                                               float* __restrict__ out) {
    __shared__ float sW2[64*WS];
    __shared__ float sX[16*XS];
    int tid = threadIdx.x;
    int tok = tid >> 6, eo = tid & 63;
    int g0 = blockIdx.x*16;
    u64t acc2[4];
    #pragma unroll
    for (int tt = 0; tt < 4; tt++) acc2[tt] = 0ull;
    for (int c = 0; c < 4; c++) {
        __syncthreads();
        for (int idx = tid; idx < 8192; idx += 256) {
            int e2 = idx >> 7, hd = idx & 127;
            sW2[e2*WS + hd] = Wf[e2*512 + c*128 + hd];
        }
        for (int idx = tid; idx < 2048; idx += 256) {
            int tk = idx >> 7, hd = idx & 127;
            int gg = g0 + tk;
            int b = gg >> 12, t = gg & 4095;
            int hdg = c*128 + hd;
            sX[tk*XS + hd] = g_on[(((size_t)(b*8 + (hdg >> 6)))*NTOK + t)*EH + (hdg & 63)];
        }
        __syncthreads();
        const u64t* wp = (const u64t*)(sW2 + eo*WS);
        #pragma unroll
        for (int tt = 0; tt < 4; tt++) {
            const float4* x4 = (const float4*)(sX + (tok + tt*4)*XS);
            #pragma unroll
            for (int h4 = 0; h4 < 32; h4++) {
                float4 xv = x4[h4];
                fma2(acc2[tt], pack2(xv.x, xv.y), wp[2*h4]);
                fma2(acc2[tt], pack2(xv.z, xv.w), wp[2*h4+1]);
            }
        }
    }
    float bv = bias[eo];
    #pragma unroll
    for (int tt = 0; tt < 4; tt++) {
        float2 u = unpk(acc2[tt]);
        out[(size_t)(g0 + tok + tt*4)*EH + eo] = u.x + u.y + bv;
    }
}

// ---------------- launch ----------------
extern "C" void kernel_launch(void* const* d_in, const int* in_sizes, int n_in,
                              void* d_out, int out_size) {
    const float* query = (const float*)d_in[0];
    const float* key   = (const float*)d_in[1];
    const float* value = (const float*)d_in[2];
    const float* projW = (const float*)d_in[3];
    const float* alpha = (const float*)d_in[4];
    const float* beta  = (const float*)d_in[5];
    const float* outW  = (const float*)d_in[6];
    const float* outb  = (const float*)d_in[7];
    float* out = (float*)d_out;

    cudaFuncSetAttribute(k_featg, cudaFuncAttributeMaxDynamicSharedMemorySize, FEATG_SMEM);
    cudaFuncSetAttribute(k_inner, cudaFuncAttributeMaxDynamicSharedMemorySize, INNER_SMEM);
    cudaFuncSetAttribute(k_prime, cudaFuncAttributeMaxDynamicSharedMemorySize, PRIME_SMEM);
    cudaFuncSetAttribute(k_ov,    cudaFuncAttributeMaxDynamicSharedMemorySize, OV_SMEM);

    k_split<<<dim3(NTOK/4, BH), 256>>>(query, key, value);
    k_maxn<<<BH, 256>>>();
    k_hash<<<dim3(NTOK/256, BH), 256>>>(alpha, beta);
    k_featg<<<dim3(NTOK/128, BH, 2), 256, FEATG_SMEM>>>(projW);
    k_sort<<<128, 512>>>();
    k_kls<<<BH, 256>>>();
    k_kvpart<<<dim3(NCH, BH), 128>>>();
    k_kvred<<<BH*MF*EH/256, 256>>>();
    k_qkv<<<dim3(NTOK/32, BH), 128>>>();
    k_inner<<<dim3(32, BH, 2), 256, INNER_SMEM>>>();
    k_prime<<<dim3(32, BH, 2), 256, PRIME_SMEM>>>();
    k_ov<<<dim3(32, BH, 2), 256, OV_SMEM>>>();
    k_merge<<<dim3(NTOK/4, BH), 256>>>();
    k_final<<<NTOK*4/16, 256>>>(outW, outb, out);
}

// round 7
// speedup vs baseline: 1.8515x; 1.1388x over previous
#include <cuda_runtime.h>
#include <math.h>

#define BH 32
#define NTOK 4096
#define EH 64
#define MF 128
#define DM 512
#define NCH 32
#define IST 132
#define FST 132
#define DST 132

#define SQRT_TEMP 0.35355339059327373f
#define TEMPF 0.125f
#define HALF_LOG_M 2.4260151319598084f
#define LN2F 0.6931471805599453f

typedef unsigned long long u64t;
__device__ __forceinline__ u64t splat2(float x) {
    u64t r; asm("mov.b64 %0, {%1, %1};" : "=l"(r) : "f"(x)); return r;
}
__device__ __forceinline__ u64t pack2(float x, float y) {
    u64t r; asm("mov.b64 %0, {%1, %2};" : "=l"(r) : "f"(x), "f"(y)); return r;
}
__device__ __forceinline__ void fma2(u64t& c, u64t a, u64t b) {
    asm("fma.rn.f32x2 %0, %1, %2, %0;" : "+l"(c) : "l"(a), "l"(b));
}
__device__ __forceinline__ float2 unpk(u64t v) {
    float2 f; asm("mov.b64 {%0, %1}, %2;" : "=f"(f.x), "=f"(f.y) : "l"(v)); return f;
}

// ---------------- scratch ----------------
__device__ float g_q[BH*NTOK*EH];
__device__ float g_k[BH*NTOK*EH];
__device__ float g_v[BH*NTOK*EH];
__device__ float g_qn2[BH*NTOK];
__device__ float g_kn2[BH*NTOK];
__device__ float g_MQ2[BH];
__device__ float g_MK2[BH];
__device__ float g_hashq[2*BH*NTOK];
__device__ float g_hashk[2*BH*NTOK];
__device__ int   g_qpos[2*BH*NTOK];
__device__ int   g_kpos[2*BH*NTOK];
__device__ int   g_qrev[2*BH*NTOK];
__device__ int   g_krev[2*BH*NTOK];
__device__ float g_qp[(size_t)BH*NTOK*MF];
__device__ float g_kp[(size_t)BH*NTOK*MF];    // log-phi (pre-exp)
__device__ float g_qls[BH*NTOK];
__device__ float g_krm[BH*NTOK];
__device__ float g_kls[BH];
__device__ float g_kvp[(size_t)NCH*BH*MF*EH];
__device__ float g_ksp[NCH*BH*MF];
__device__ float g_kv[BH*MF*EH];
__device__ float g_ksum[BH*MF];
__device__ float g_qk1[BH*NTOK];
__device__ float g_qkv[(size_t)BH*NTOK*EH];
__device__ float g_dots[(size_t)2*BH*NTOK*128];   // inner then dots, in place
__device__ float g_ob[(size_t)2*BH*NTOK*EH];
__device__ float g_lseb[2*BH*NTOK];
__device__ float g_dsb[2*BH*NTOK];
__device__ float g_on[(size_t)BH*NTOK*EH];

// ---------------- K1: split heads + squared norms ----------------
__global__ __launch_bounds__(256) void k_split(const float* __restrict__ query,
                                               const float* __restrict__ key,
                                               const float* __restrict__ value) {
    int tid = threadIdx.x;
    int tl = tid >> 6, e = tid & 63;
    int t = blockIdx.x*4 + tl, bh = blockIdx.y;
    int b = bh >> 3, hh = bh & 7;
    size_t gi = ((size_t)(b*NTOK + t))*DM + hh*EH + e;
    float qv = query[gi], kv = key[gi], vv = value[gi];
    size_t oi = ((size_t)bh*NTOK + t)*EH + e;
    g_q[oi] = qv; g_k[oi] = kv; g_v[oi] = vv;
    float q2 = qv*qv, k2 = kv*kv;
    #pragma unroll
    for (int o = 16; o; o >>= 1) {
        q2 += __shfl_down_sync(0xffffffffu, q2, o);
        k2 += __shfl_down_sync(0xffffffffu, k2, o);
    }
    __shared__ float sq[8], sk[8];
    if ((tid & 31) == 0) { sq[tid>>5] = q2; sk[tid>>5] = k2; }
    __syncthreads();
    if (e == 0) {
        g_qn2[bh*NTOK + t] = sq[2*tl] + sq[2*tl+1];
        g_kn2[bh*NTOK + t] = sk[2*tl] + sk[2*tl+1];
    }
}

// ---------------- K2: per-bh max squared norms ----------------
__global__ void k_maxn() {
    int bh = blockIdx.x, tid = threadIdx.x;
    float mq = 0.f, mk = 0.f;
    for (int i = tid; i < NTOK; i += 256) {
        mq = fmaxf(mq, g_qn2[bh*NTOK + i]);
        mk = fmaxf(mk, g_kn2[bh*NTOK + i]);
    }
    #pragma unroll
    for (int o = 16; o; o >>= 1) {
        mq = fmaxf(mq, __shfl_xor_sync(0xffffffffu, mq, o));
        mk = fmaxf(mk, __shfl_xor_sync(0xffffffffu, mk, o));
    }
    __shared__ float sq[8], sk[8];
    if ((tid & 31) == 0) { sq[tid>>5] = mq; sk[tid>>5] = mk; }
    __syncthreads();
    if (tid == 0) {
        float a = sq[0], b = sk[0];
        for (int w = 1; w < 8; w++) { a = fmaxf(a, sq[w]); b = fmaxf(b, sk[w]); }
        g_MQ2[bh] = a; g_MK2[bh] = b;
    }
}

// ---------------- K3: LSH hashes ----------------
__global__ void k_hash(const float* __restrict__ alpha, const float* __restrict__ beta) {
    __shared__ float sal[2*(EH+2)];
    __shared__ float sbe[2];
    int bh = blockIdx.y;
    int tid = threadIdx.x;
    if (tid < 2*(EH+2)) sal[tid] = alpha[tid];
    if (tid < 2) sbe[tid] = beta[tid];
    __syncthreads();
    int t = blockIdx.x*256 + tid;
    const float* qr = g_q + ((size_t)bh*NTOK + t)*EH;
    const float* kr = g_k + ((size_t)bh*NTOK + t)*EH;
    float a0 = 0.f, a1 = 0.f, c0 = 0.f, c1 = 0.f;
    #pragma unroll 8
    for (int e = 0; e < EH; e++) {
        float al0 = sal[e*2], al1 = sal[e*2+1];
        float qe = qr[e], ke = kr[e];
        a0 += qe*al0; a1 += qe*al1;
        c0 += ke*al0; c1 += ke*al1;
    }
    float S = g_MQ2[bh] + g_MK2[bh];
    float extq = sqrtf(fmaxf(S - g_qn2[bh*NTOK + t], 0.f));
    float extk = sqrtf(fmaxf(S - g_kn2[bh*NTOK + t], 0.f));
    g_hashq[bh*NTOK + t]           = a0 + extq*sal[EH*2]       + sbe[0];
    g_hashq[BH*NTOK + bh*NTOK + t] = a1 + extq*sal[EH*2+1]     + sbe[1];
    g_hashk[bh*NTOK + t]           = c0 + extk*sal[(EH+1)*2]   + sbe[0];
    g_hashk[BH*NTOK + bh*NTOK + t] = c1 + extk*sal[(EH+1)*2+1] + sbe[1];
}

// ---------------- K5: performer feature maps as tiled GEMM ----------------
#define FEATG_SMEM (2*64*FST*4 + 128*4)
__global__ __launch_bounds__(256, 2) void k_featg(const float* __restrict__ W) {
    extern __shared__ float sm[];
    float* sXt = sm;                    // [64][FST]
    float* sWt = sm + 64*FST;           // [64][FST]
    float* sN  = sm + 2*64*FST;         // [128]
    int nb = blockIdx.x, bh = blockIdx.y, isK = blockIdx.z;
    int tid = threadIdx.x, tx = tid & 15, ty = tid >> 4;
    const float* X  = isK ? g_k   : g_q;
    const float* n2 = isK ? g_kn2 : g_qn2;
    int tb = nb*128;
    for (int idx = tid; idx < 8192; idx += 256) {
        int i = idx >> 6, e = idx & 63;
        sXt[e*FST + i] = X[((size_t)bh*NTOK + tb + i)*EH + e];
        sWt[e*FST + i] = W[i*EH + e];
    }
    if (tid < 128) sN[tid] = n2[bh*NTOK + tb + tid];
    __syncthreads();
    u64t acc[4][8];
    #pragma unroll
    for (int r = 0; r < 4; r++)
        #pragma unroll
        for (int c = 0; c < 8; c++) acc[r][c] = 0ull;
    for (int e = 0; e < 64; e++) {
        const u64t* ap = (const u64t*)(sXt + e*FST + ty*8);
        float4 b0q = *(const float4*)(sWt + e*FST + tx*8);
        float4 b1q = *(const float4*)(sWt + e*FST + tx*8 + 4);
        u64t bs[8];
        bs[0]=splat2(b0q.x); bs[1]=splat2(b0q.y); bs[2]=splat2(b0q.z); bs[3]=splat2(b0q.w);
        bs[4]=splat2(b1q.x); bs[5]=splat2(b1q.y); bs[6]=splat2(b1q.z); bs[7]=splat2(b1q.w);
        #pragma unroll
        for (int r2 = 0; r2 < 4; r2++) {
            u64t av = ap[r2];
            #pragma unroll
            for (int c = 0; c < 8; c++) fma2(acc[r2][c], av, bs[c]);
        }
    }
    #pragma unroll
    for (int r2 = 0; r2 < 4; r2++) {
        float2 v[8];
        #pragma unroll
        for (int c = 0; c < 8; c++) v[c] = unpk(acc[r2][c]);
        #pragma unroll
        for (int half = 0; half < 2; half++) {
            int row = ty*8 + r2*2 + half;
            int t = tb + row;
            float nn = 0.5f*TEMPF*sN[row] + HALF_LOG_M;
            float lp[8];
            float rm = -1e30f;
            #pragma unroll
            for (int c = 0; c < 8; c++) {
                lp[c] = (half ? v[c].y : v[c].x)*SQRT_TEMP - nn;
                rm = fmaxf(rm, lp[c]);
            }
            #pragma unroll
            for (int off = 8; off; off >>= 1) rm = fmaxf(rm, __shfl_xor_sync(0xffffffffu, rm, off));
            size_t base = ((size_t)bh*NTOK + t)*MF + tx*8;
            if (!isK) {
                *(float4*)(g_qp + base) = make_float4(__expf(lp[0]-rm), __expf(lp[1]-rm),
                                                      __expf(lp[2]-rm), __expf(lp[3]-rm));
                *(float4*)(g_qp + base + 4) = make_float4(__expf(lp[4]-rm), __expf(lp[5]-rm),
                                                          __expf(lp[6]-rm), __expf(lp[7]-rm));
                if (tx == 0) g_qls[bh*NTOK + t] = rm;
            } else {
                *(float4*)(g_kp + base)     = make_float4(lp[0], lp[1], lp[2], lp[3]);
                *(float4*)(g_kp + base + 4) = make_float4(lp[4], lp[5], lp[6], lp[7]);
                if (tx == 0) g_krm[bh*NTOK + t] = rm;
            }
        }
    }
}

// ---------------- K4: stable bitonic argsort ----------------
__global__ void k_sort() {
    __shared__ float sv[NTOK];
    __shared__ int   si[NTOK];
    int which = blockIdx.x >> 6;
    int rem   = blockIdx.x & 63;
    const float* src = which ? (g_hashk + (size_t)rem*NTOK) : (g_hashq + (size_t)rem*NTOK);
    int tid = threadIdx.x;
    for (int i = tid; i < NTOK; i += 512) { sv[i] = src[i]; si[i] = i; }
    __syncthreads();
    for (int k = 2; k <= NTOK; k <<= 1)
        for (int j = k >> 1; j > 0; j >>= 1) {
            for (int p = tid; p < NTOK/2; p += 512) {
                int i  = ((p & ~(j-1)) << 1) | (p & (j-1));
                int ix = i | j;
                bool up = ((i & k) == 0);
                float vi = sv[i], vj = sv[ix];
                int ii = si[i], ij = si[ix];
                bool agt = (vi > vj) || (vi == vj && ii > ij);
                if (agt == up) { sv[i] = vj; sv[ix] = vi; si[i] = ij; si[ix] = ii; }
            }
            __syncthreads();
        }
    int* pos = which ? g_kpos : g_qpos;
    int* rev = which ? g_krev : g_qrev;
    for (int r = tid; r < NTOK; r += 512) {
        int idx = si[r];
        pos[rem*NTOK + r]   = idx;
        rev[rem*NTOK + idx] = r;
    }
}

// ---------------- K6: per-bh max of k log-phi ----------------
__global__ void k_kls() {
    int bh = blockIdx.x, tid = threadIdx.x;
    float m = -1e30f;
    for (int i = tid; i < NTOK; i += 256) m = fmaxf(m, g_krm[bh*NTOK + i]);
    #pragma unroll
    for (int o = 16; o; o >>= 1) m = fmaxf(m, __shfl_xor_sync(0xffffffffu, m, o));
    __shared__ float s[8];
    if ((tid & 31) == 0) s[tid>>5] = m;
    __syncthreads();
    if (tid == 0) {
        float r = s[0];
        for (int w = 1; w < 8; w++) r = fmaxf(r, s[w]);
        g_kls[bh] = r;
    }
}

// ---------------- K8: partial kv = exp(k')^T v, tiled GEMM ----------------
#define KVP_SMEM (128*IST*4 + 128*68*4)
__global__ __launch_bounds__(256, 2) void k_kvpart2() {
    extern __shared__ float sm[];
    float* sKP = sm;                    // [128 t][IST] holds exp(kp) rows
    float* sV  = sm + 128*IST;          // [128 t][68]
    int ch = blockIdx.x, bh = blockIdx.y;
    int tid = threadIdx.x, tx = tid & 15, ty = tid >> 4;
    float kls = g_kls[bh];
    int t0 = ch*128;
    for (int idx = tid; idx < 16384; idx += 256) {
        int t = idx >> 7, m = idx & 127;
        sKP[t*IST + m] = __expf(g_kp[((size_t)bh*NTOK + t0 + t)*MF + m] - kls);
    }
    for (int idx = tid; idx < 8192; idx += 256) {
        int t = idx >> 6, d = idx & 63;
        sV[t*68 + d] = g_v[((size_t)bh*NTOK + t0 + t)*EH + d];
    }
    __syncthreads();
    u64t acc[4][4];
    #pragma unroll
    for (int r = 0; r < 4; r++)
        #pragma unroll
        for (int c = 0; c < 4; c++) acc[r][c] = 0ull;
    for (int t = 0; t < 128; t++) {
        const u64t* ap = (const u64t*)(sKP + t*IST + ty*8);   // 8 m's
        float4 bq = *(const float4*)(sV + t*68 + tx*4);       // 4 d's
        u64t b0 = splat2(bq.x), b1 = splat2(bq.y), b2 = splat2(bq.z), b3 = splat2(bq.w);
        #pragma unroll
        for (int r2 = 0; r2 < 4; r2++) {
            u64t av = ap[r2];
            fma2(acc[r2][0], av, b0); fma2(acc[r2][1], av, b1);
            fma2(acc[r2][2], av, b2); fma2(acc[r2][3], av, b3);
        }
    }
    float* dst = g_kvp + ((size_t)(ch*BH + bh))*MF*EH;
    #pragma unroll
    for (int r2 = 0; r2 < 4; r2++) {
        float2 v0 = unpk(acc[r2][0]), v1 = unpk(acc[r2][1]);
        float2 v2 = unpk(acc[r2][2]), v3 = unpk(acc[r2][3]);
        int m = ty*8 + r2*2;
        *(float4*)(dst + (size_t)m*EH + tx*4)     = make_float4(v0.x, v1.x, v2.x, v3.x);
        *(float4*)(dst + (size_t)(m+1)*EH + tx*4) = make_float4(v0.y, v1.y, v2.y, v3.y);
    }
    // column sums of exp(kp): thread tid<128 handles feature m=tid
    if (tid < 128) {
        float s = 0.f;
        #pragma unroll 8
        for (int t = 0; t < 128; t++) s += sKP[t*IST + tid];
        g_ksp[(ch*BH + bh)*MF + tid] = s;
    }
}

// ---------------- K8b: deterministic reduce ----------------
__global__ void k_kvred() {
    int idx = blockIdx.x*256 + threadIdx.x;
    float s = 0.f;
    #pragma unroll
    for (int c = 0; c < NCH; c++) s += g_kvp[(size_t)c*BH*MF*EH + idx];
    g_kv[idx] = s;
    if (idx < BH*MF) {
        float ss = 0.f;
        #pragma unroll
        for (int c = 0; c < NCH; c++) ss += g_ksp[c*BH*MF + idx];
        g_ksum[idx] = ss;
    }
}

// ---------------- K9: qkv = q' kv + qk1, tiled GEMM ----------------
#define QKV_SMEM (128*IST*4 + 128*68*4 + 128*4)
__global__ __launch_bounds__(256, 2) void k_qkv2() {
    extern __shared__ float sm[];
    float* sQPt = sm;                   // [128 m][IST tokens] transposed q'
    float* sKV  = sm + 128*IST;         // [128 m][68]
    float* sks  = sm + 128*IST + 128*68;
    int nb = blockIdx.x, bh = blockIdx.y;
    int tid = threadIdx.x, tx = tid & 15, ty = tid >> 4;
    int tb = nb*128;
    for (int idx = tid; idx < 16384; idx += 256) {
        int i = idx >> 7, m = idx & 127;
        sQPt[m*IST + i] = g_qp[((size_t)bh*NTOK + tb + i)*MF + m];
    }
    for (int idx = tid; idx < 8192; idx += 256) {
        int m = idx >> 6, d = idx & 63;
        sKV[m*68 + d] = g_kv[(size_t)bh*MF*EH + m*EH + d];
    }
    if (tid < 128) sks[tid] = g_ksum[bh*MF + tid];
    __syncthreads();
    u64t acc[4][4];
    #pragma unroll
    for (int r = 0; r < 4; r++)
        #pragma unroll
        for (int c = 0; c < 4; c++) acc[r][c] = 0ull;
    for (int m = 0; m < 128; m++) {
        const u64t* ap = (const u64t*)(sQPt + m*IST + ty*8);   // 8 tokens
        float4 bq = *(const float4*)(sKV + m*68 + tx*4);       // 4 d's
        u64t b0 = splat2(bq.x), b1 = splat2(bq.y), b2 = splat2(bq.z), b3 = splat2(bq.w);
        #pragma unroll
        for (int r2 = 0; r2 < 4; r2++) {
            u64t av = ap[r2];
            fma2(acc[r2][0], av, b0); fma2(acc[r2][1], av, b1);
            fma2(acc[r2][2], av, b2); fma2(acc[r2][3], av, b3);
        }
    }
    #pragma unroll
    for (int r2 = 0; r2 < 4; r2++) {
        float2 v0 = unpk(acc[r2][0]), v1 = unpk(acc[r2][1]);
        float2 v2 = unpk(acc[r2][2]), v3 = unpk(acc[r2][3]);
        int row = ty*8 + r2*2;
        *(float4*)(g_qkv + ((size_t)bh*NTOK + tb + row)*EH + tx*4)
            = make_float4(v0.x, v1.x, v2.x, v3.x);
        *(float4*)(g_qkv + ((size_t)bh*NTOK + tb + row + 1)*EH + tx*4)
            = make_float4(v0.y, v1.y, v2.y, v3.y);
    }
    // qk1 per token
    if (tid < 128) {
        float s = 0.f;
        #pragma unroll 8
        for (int m = 0; m < 128; m++) s += sQPt[m*IST + tid]*sks[m];
        g_qk1[bh*NTOK + tb + tid] = s;
    }
}

// ================= bucketed correction: 3 kernels =================
#define INNER_SMEM ((2*64*IST)*4 + 2*128*4)
__global__ __launch_bounds__(256, 2) void k_inner() {
    extern __shared__ float sm[];
    float* sQt = sm;                    // [64][IST]
    float* sKt = sm + 64*IST;
    int* sQi = (int*)(sm + 2*64*IST);
    int* sKi = sQi + 128;
    int nb = blockIdx.x, bh = blockIdx.y, h = blockIdx.z;
    int tid = threadIdx.x, tx = tid & 15, ty = tid >> 4;
    if (tid < 128) {
        sQi[tid] = g_qpos[(h*BH + bh)*NTOK + nb*128 + tid];
        sKi[tid] = g_kpos[(h*BH + bh)*NTOK + nb*128 + tid];
    }
    __syncthreads();
    for (int idx = tid; idx < 8192; idx += 256) {
        int i = idx >> 6, e = idx & 63;
        sQt[e*IST + i] = g_q[((size_t)bh*NTOK + sQi[i])*EH + e];
        sKt[e*IST + i] = g_k[((size_t)bh*NTOK + sKi[i])*EH + e];
    }
    __syncthreads();
    u64t aI[4][8];
    #pragma unroll
    for (int r = 0; r < 4; r++)
        #pragma unroll
        for (int c = 0; c < 8; c++) aI[r][c] = 0ull;
    for (int e = 0; e < 64; e++) {
        const u64t* ap = (const u64t*)(sQt + e*IST + ty*8);
        float4 b0q = *(const float4*)(sKt + e*IST + tx*8);
        float4 b1q = *(const float4*)(sKt + e*IST + tx*8 + 4);
        u64t bs[8];
        bs[0]=splat2(b0q.x); bs[1]=splat2(b0q.y); bs[2]=splat2(b0q.z); bs[3]=splat2(b0q.w);
        bs[4]=splat2(b1q.x); bs[5]=splat2(b1q.y); bs[6]=splat2(b1q.z); bs[7]=splat2(b1q.w);
        #pragma unroll
        for (int r2 = 0; r2 < 4; r2++) {
            u64t av = ap[r2];
            #pragma unroll
            for (int c = 0; c < 8; c++) fma2(aI[r2][c], av, bs[c]);
        }
    }
    float* dbase = g_dots + ((size_t)(h*BH + bh)*NTOK + nb*128)*128;
    #pragma unroll
    for (int r2 = 0; r2 < 4; r2++) {
        float2 v[8];
        #pragma unroll
        for (int c = 0; c < 8; c++) v[c] = unpk(aI[r2][c]);
        int row = ty*8 + r2*2;
        *(float4*)(dbase + (size_t)row*128 + tx*8)     = make_float4(v[0].x, v[1].x, v[2].x, v[3].x);
        *(float4*)(dbase + (size_t)row*128 + tx*8 + 4) = make_float4(v[4].x, v[5].x, v[6].x, v[7].x);
        *(float4*)(dbase + (size_t)(row+1)*128 + tx*8)     = make_float4(v[0].y, v[1].y, v[2].y, v[3].y);
        *(float4*)(dbase + (size_t)(row+1)*128 + tx*8 + 4) = make_float4(v[4].y, v[5].y, v[6].y, v[7].y);
    }
}

#define PRIME_SMEM ((2*64*IST)*4 + 128*4 + 4*128*4)
__global__ __launch_bounds__(256, 2) void k_prime() {
    extern __shared__ float sm[];
    float* sQPt = sm;                   // [64][IST] (m-chunked)
    float* sKPt = sm + 64*IST;
    float* sPls = sm + 2*64*IST;
    int* sQi = (int*)(sPls + 128);
    int* sKi = sQi + 128;
    int* sQb = sKi + 128;
    int* sKb = sQb + 128;
    int nb = blockIdx.x, bh = blockIdx.y, h = blockIdx.z;
    int tid = threadIdx.x, tx = tid & 15, ty = tid >> 4;
    int o = 1 - h;
    float kls = g_kls[bh];
    if (tid < 128) {
        int qi = g_qpos[(h*BH + bh)*NTOK + nb*128 + tid];
        int ki = g_kpos[(h*BH + bh)*NTOK + nb*128 + tid];
        sQi[tid] = qi; sKi[tid] = ki;
        sQb[tid] = g_qrev[(o*BH + bh)*NTOK + qi] >> 7;
        sKb[tid] = g_krev[(o*BH + bh)*NTOK + ki] >> 7;
        sPls[tid] = g_qls[bh*NTOK + qi] + kls;
    }
    u64t aP[4][8];
    #pragma unroll
    for (int r = 0; r < 4; r++)
        #pragma unroll
        for (int c = 0; c < 8; c++) aP[r][c] = 0ull;
    for (int mc = 0; mc < 2; mc++) {
        __syncthreads();
        for (int idx = tid; idx < 8192; idx += 256) {
            int i = idx >> 6, ml = idx & 63;
            sQPt[ml*IST + i] = g_qp[((size_t)bh*NTOK + sQi[i])*MF + mc*64 + ml];
            sKPt[ml*IST + i] = __expf(g_kp[((size_t)bh*NTOK + sKi[i])*MF + mc*64 + ml] - kls);
        }
        __syncthreads();
        for (int m = 0; m < 64; m++) {
            const u64t* ap = (const u64t*)(sQPt + m*IST + ty*8);
            float4 b0q = *(const float4*)(sKPt + m*IST + tx*8);
            float4 b1q = *(const float4*)(sKPt + m*IST + tx*8 + 4);
            u64t bs[8];
            bs[0]=splat2(b0q.x); bs[1]=splat2(b0q.y); bs[2]=splat2(b0q.z); bs[3]=splat2(b0q.w);
            bs[4]=splat2(b1q.x); bs[5]=splat2(b1q.y); bs[6]=splat2(b1q.z); bs[7]=splat2(b1q.w);
            #pragma unroll
            for (int r2 = 0; r2 < 4; r2++) {
                u64t av = ap[r2];
                #pragma unroll
                for (int c = 0; c < 8; c++) fma2(aP[r2][c], av, bs[c]);
            }
        }
    }
    int kb[8];
    #pragma unroll
    for (int c = 0; c < 8; c++) kb[c] = sKb[tx*8 + c];
    float* dbase = g_dots + ((size_t)(h*BH + bh)*NTOK + nb*128)*128;
    #pragma unroll
    for (int r2 = 0; r2 < 4; r2++) {
        float2 P[8];
        #pragma unroll
        for (int c = 0; c < 8; c++) P[c] = unpk(aP[r2][c]);
        #pragma unroll
        for (int half = 0; half < 2; half++) {
            int row = ty*8 + r2*2 + half;
            int qb = sQb[row]; float pls = sPls[row];
            float4 in0 = *(const float4*)(dbase + (size_t)row*128 + tx*8);
            float4 in1 = *(const float4*)(dbase + (size_t)row*128 + tx*8 + 4);
            float iv[8] = {in0.x, in0.y, in0.z, in0.w, in1.x, in1.y, in1.z, in1.w};
            float pv[8];
            float rm = -1e30f;
            #pragma unroll
            for (int c = 0; c < 8; c++) {
                bool d2 = (qb == kb[c]);
                iv[c] = iv[c]*TEMPF - (d2 ? LN2F : 0.f);
                pv[c] = (half ? P[c].y : P[c].x) * (d2 ? 0.5f : 1.f);
                rm = fmaxf(rm, iv[c]);
            }
            #pragma unroll
            for (int off = 8; off; off >>= 1) rm = fmaxf(rm, __shfl_xor_sync(0xffffffffu, rm, off));
            float l = fmaxf(rm, pls);
            float pe = __expf(pls - l);
            float dv[8];
            float s = 0.f;
            #pragma unroll
            for (int c = 0; c < 8; c++) { dv[c] = __expf(iv[c] - l) - pv[c]*pe; s += dv[c]; }
            *(float4*)(dbase + (size_t)row*128 + tx*8)     = make_float4(dv[0], dv[1], dv[2], dv[3]);
            *(float4*)(dbase + (size_t)row*128 + tx*8 + 4) = make_float4(dv[4], dv[5], dv[6], dv[7]);
            #pragma unroll
            for (int off = 8; off; off >>= 1) s += __shfl_xor_sync(0xffffffffu, s, off);
            if (tx == 0) {
                int t = sQi[row];
                size_t bi = (size_t)(h*BH + bh)*NTOK + t;
                g_lseb[bi] = l;
                g_dsb[bi]  = s;
            }
        }
    }
}

#define OV_SMEM ((128*DST + 128*68)*4 + 2*128*4)
__global__ __launch_bounds__(256, 2) void k_ov() {
    extern __shared__ float sm[];
    float* sD = sm;                     // [128][DST]
    float* sV = sm + 128*DST;           // [128][68]
    int* sQi = (int*)(sV + 128*68);
    int* sKi = sQi + 128;
    int nb = blockIdx.x, bh = blockIdx.y, h = blockIdx.z;
    int tid = threadIdx.x, tx2 = tid & 15, ty2 = tid >> 4;
    if (tid < 128) {
        sQi[tid] = g_qpos[(h*BH + bh)*NTOK + nb*128 + tid];
        sKi[tid] = g_kpos[(h*BH + bh)*NTOK + nb*128 + tid];
    }
    __syncthreads();
    const float* dbase = g_dots + ((size_t)(h*BH + bh)*NTOK + nb*128)*128;
    for (int idx = tid; idx < 4096; idx += 256) {
        int row = idx >> 5, c4 = idx & 31;
        *(float4*)(sD + row*DST + c4*4) = *(const float4*)(dbase + (size_t)row*128 + c4*4);
    }
    for (int idx = tid; idx < 8192; idx += 256) {
        int i = idx >> 6, d = idx & 63;
        sV[i*68 + d] = g_v[((size_t)bh*NTOK + sKi[i])*EH + d];
    }
    __syncthreads();
    u64t accO[8][2];
    #pragma unroll
    for (int r = 0; r < 8; r++) { accO[r][0] = 0ull; accO[r][1] = 0ull; }
    for (int j0 = 0; j0 < 128; j0 += 4) {
        float4 a[8];
        #pragma unroll
        for (int r = 0; r < 8; r++) a[r] = *(const float4*)(sD + (ty2*8 + r)*DST + j0);
        #pragma unroll
        for (int jj = 0; jj < 4; jj++) {
            float4 t = *(const float4*)(sV + (j0 + jj)*68 + tx2*4);
            u64t bv0 = pack2(t.x, t.y), bv1 = pack2(t.z, t.w);
            #pragma unroll
            for (int r = 0; r < 8; r++) {
                float av = (jj==0)?a[r].x:(jj==1)?a[r].y:(jj==2)?a[r].z:a[r].w;
                u64t s = splat2(av);
                fma2(accO[r][0], s, bv0); fma2(accO[r][1], s, bv1);
            }
        }
    }
    #pragma unroll
    for (int r = 0; r < 8; r++) {
        int t = sQi[ty2*8 + r];
        float2 u0 = unpk(accO[r][0]), u1 = unpk(accO[r][1]);
        *(float4*)(g_ob + ((size_t)(h*BH + bh)*NTOK + t)*EH + tx2*4) =
            make_float4(u0.x, u0.y, u1.x, u1.y);
    }
}

// ---------------- K11: merge performer + LSH branches ----------------
__global__ void k_merge() {
    int tid = threadIdx.x;
    int t = blockIdx.x*4 + (tid >> 6);
    int d = tid & 63;
    int bh = blockIdx.y;
    size_t i0 = (size_t)bh*NTOK + t;
    size_t i1 = (size_t)(BH + bh)*NTOK + t;
    float l0 = g_lseb[i0], l1 = g_lseb[i1];
    float mx = fmaxf(l0, l1);
    float norm = mx + logf(__expf(l0 - mx) + __expf(l1 - mx));
    float p0 = __expf(l0 - norm), p1 = __expf(l1 - norm);
    float pls = g_qls[bh*NTOK + t] + g_kls[bh];
    float psc = __expf(pls - norm);
    float z = g_dsb[i0]*p0 + g_dsb[i1]*p1 + g_qk1[bh*NTOK + t]*psc;
    z = fmaxf(z, 1e-6f);
    size_t base = ((size_t)bh*NTOK + t)*EH + d;
    float outv = g_ob[i0*EH + d]*p0 + g_ob[i1*EH + d]*p1 + g_qkv[base]*psc;
    g_on[base] = outv / z;
}

// ---------------- K12: final projection (16 tokens/block) ----------------
#define WS 130
#define XS 132
__global__ __launch_bounds__(256) void k_final(const float* __restrict__ Wf,
                                               const float* __restrict__ bias,
                                               float* __restrict__ out) {
    __shared__ float sW2[64*WS];
    __shared__ float sX[16*XS];
    int tid = threadIdx.x;
    int tok = tid >> 6, eo = tid & 63;
    int g0 = blockIdx.x*16;
    u64t acc2[4];
    #pragma unroll
    for (int tt = 0; tt < 4; tt++) acc2[tt] = 0ull;
    for (int c = 0; c < 4; c++) {
        __syncthreads();
        for (int idx = tid; idx < 8192; idx += 256) {
            int e2 = idx >> 7, hd = idx & 127;
            sW2[e2*WS + hd] = Wf[e2*512 + c*128 + hd];
        }
        for (int idx = tid; idx < 2048; idx += 256) {
            int tk = idx >> 7, hd = idx & 127;
            int gg = g0 + tk;
            int b = gg >> 12, t = gg & 4095;
            int hdg = c*128 + hd;
            sX[tk*XS + hd] = g_on[(((size_t)(b*8 + (hdg >> 6)))*NTOK + t)*EH + (hdg & 63)];
        }
        __syncthreads();
        const u64t* wp = (const u64t*)(sW2 + eo*WS);
        #pragma unroll
        for (int tt = 0; tt < 4; tt++) {
            const float4* x4 = (const float4*)(sX + (tok + tt*4)*XS);
            #pragma unroll
            for (int h4 = 0; h4 < 32; h4++) {
                float4 xv = x4[h4];
                fma2(acc2[tt], pack2(xv.x, xv.y), wp[2*h4]);
                fma2(acc2[tt], pack2(xv.z, xv.w), wp[2*h4+1]);
            }
        }
    }
    float bv = bias[eo];
    #pragma unroll
    for (int tt = 0; tt < 4; tt++) {
        float2 u = unpk(acc2[tt]);
        out[(size_t)(g0 + tok + tt*4)*EH + eo] = u.x + u.y + bv;
    }
}

// ---------------- launch ----------------
extern "C" void kernel_launch(void* const* d_in, const int* in_sizes, int n_in,
                              void* d_out, int out_size) {
    const float* query = (const float*)d_in[0];
    const float* key   = (const float*)d_in[1];
    const float* value = (const float*)d_in[2];
    const float* projW = (const float*)d_in[3];
    const float* alpha = (const float*)d_in[4];
    const float* beta  = (const float*)d_in[5];
    const float* outW  = (const float*)d_in[6];
    const float* outb  = (const float*)d_in[7];
    float* out = (float*)d_out;

    cudaFuncSetAttribute(k_featg,   cudaFuncAttributeMaxDynamicSharedMemorySize, FEATG_SMEM);
    cudaFuncSetAttribute(k_kvpart2, cudaFuncAttributeMaxDynamicSharedMemorySize, KVP_SMEM);
    cudaFuncSetAttribute(k_qkv2,    cudaFuncAttributeMaxDynamicSharedMemorySize, QKV_SMEM);
    cudaFuncSetAttribute(k_inner,   cudaFuncAttributeMaxDynamicSharedMemorySize, INNER_SMEM);
    cudaFuncSetAttribute(k_prime,   cudaFuncAttributeMaxDynamicSharedMemorySize, PRIME_SMEM);
    cudaFuncSetAttribute(k_ov,      cudaFuncAttributeMaxDynamicSharedMemorySize, OV_SMEM);

    k_split<<<dim3(NTOK/4, BH), 256>>>(query, key, value);
    k_featg<<<dim3(NTOK/128, BH, 2), 256, FEATG_SMEM>>>(projW);
    k_kls<<<BH, 256>>>();
    k_kvpart2<<<dim3(NCH, BH), 256, KVP_SMEM>>>();      // profiled slot (idx 3)
    k_maxn<<<BH, 256>>>();
    k_hash<<<dim3(NTOK/256, BH), 256>>>(alpha, beta);
    k_sort<<<128, 512>>>();
    k_kvred<<<BH*MF*EH/256, 256>>>();
    k_qkv2<<<dim3(NTOK/128, BH), 256, QKV_SMEM>>>();
    k_inner<<<dim3(32, BH, 2), 256, INNER_SMEM>>>();
    k_prime<<<dim3(32, BH, 2), 256, PRIME_SMEM>>>();
    k_ov<<<dim3(32, BH, 2), 256, OV_SMEM>>>();
    k_merge<<<dim3(NTOK/4, BH), 256>>>();
    k_final<<<NTOK*4/16, 256>>>(outW, outb, out);
}

// round 8
// speedup vs baseline: 1.9506x; 1.0535x over previous
#include <cuda_runtime.h>
#include <math.h>

#define BH 32
#define NTOK 4096
#define EH 64
#define MF 128
#define DM 512
#define NCH 32
#define IST 132
#define FST 132
#define DST 132

#define SQRT_TEMP 0.35355339059327373f
#define TEMPF 0.125f
#define HALF_LOG_M 2.4260151319598084f
#define LN2F 0.6931471805599453f

typedef unsigned long long u64t;
__device__ __forceinline__ u64t splat2(float x) {
    u64t r; asm("mov.b64 %0, {%1, %1};" : "=l"(r) : "f"(x)); return r;
}
__device__ __forceinline__ u64t pack2(float x, float y) {
    u64t r; asm("mov.b64 %0, {%1, %2};" : "=l"(r) : "f"(x), "f"(y)); return r;
}
__device__ __forceinline__ void fma2(u64t& c, u64t a, u64t b) {
    asm("fma.rn.f32x2 %0, %1, %2, %0;" : "+l"(c) : "l"(a), "l"(b));
}
__device__ __forceinline__ float2 unpk(u64t v) {
    float2 f; asm("mov.b64 {%0, %1}, %2;" : "=f"(f.x), "=f"(f.y) : "l"(v)); return f;
}

// ---------------- scratch ----------------
__device__ float g_q[BH*NTOK*EH];
__device__ float g_k[BH*NTOK*EH];
__device__ float g_v[BH*NTOK*EH];
__device__ float g_qn2[BH*NTOK];
__device__ float g_kn2[BH*NTOK];
__device__ float g_MQ2[BH];
__device__ float g_MK2[BH];
__device__ float g_hashq[2*BH*NTOK];
__device__ float g_hashk[2*BH*NTOK];
__device__ int   g_qpos[2*BH*NTOK];
__device__ int   g_kpos[2*BH*NTOK];
__device__ int   g_qrev[2*BH*NTOK];
__device__ int   g_krev[2*BH*NTOK];
__device__ float g_qp[(size_t)BH*NTOK*MF];
__device__ float g_kp[(size_t)BH*NTOK*MF];    // log-phi (pre-exp)
__device__ float g_qls[BH*NTOK];
__device__ float g_krm[BH*NTOK];
__device__ float g_kls[BH];
__device__ float g_kvp[(size_t)NCH*BH*MF*EH];
__device__ float g_ksp[NCH*BH*MF];
__device__ float g_kv[BH*MF*EH];
__device__ float g_ksum[BH*MF];
__device__ float g_qk1[BH*NTOK];
__device__ float g_qkv[(size_t)BH*NTOK*EH];
__device__ float g_dots[(size_t)2*BH*NTOK*128];   // raw inner (from k_inner)
__device__ float g_ob[(size_t)2*BH*NTOK*EH];
__device__ float g_lseb[2*BH*NTOK];
__device__ float g_dsb[2*BH*NTOK];
__device__ float g_on[(size_t)BH*NTOK*EH];

// ---------------- K1: split heads + squared norms ----------------
__global__ __launch_bounds__(256) void k_split(const float* __restrict__ query,
                                               const float* __restrict__ key,
                                               const float* __restrict__ value) {
    int tid = threadIdx.x;
    int tl = tid >> 6, e = tid & 63;
    int t = blockIdx.x*4 + tl, bh = blockIdx.y;
    int b = bh >> 3, hh = bh & 7;
    size_t gi = ((size_t)(b*NTOK + t))*DM + hh*EH + e;
    float qv = query[gi], kv = key[gi], vv = value[gi];
    size_t oi = ((size_t)bh*NTOK + t)*EH + e;
    g_q[oi] = qv; g_k[oi] = kv; g_v[oi] = vv;
    float q2 = qv*qv, k2 = kv*kv;
    #pragma unroll
    for (int o = 16; o; o >>= 1) {
        q2 += __shfl_down_sync(0xffffffffu, q2, o);
        k2 += __shfl_down_sync(0xffffffffu, k2, o);
    }
    __shared__ float sq[8], sk[8];
    if ((tid & 31) == 0) { sq[tid>>5] = q2; sk[tid>>5] = k2; }
    __syncthreads();
    if (e == 0) {
        g_qn2[bh*NTOK + t] = sq[2*tl] + sq[2*tl+1];
        g_kn2[bh*NTOK + t] = sk[2*tl] + sk[2*tl+1];
    }
}

// ---------------- K2: per-bh max squared norms ----------------
__global__ void k_maxn() {
    int bh = blockIdx.x, tid = threadIdx.x;
    float mq = 0.f, mk = 0.f;
    for (int i = tid; i < NTOK; i += 256) {
        mq = fmaxf(mq, g_qn2[bh*NTOK + i]);
        mk = fmaxf(mk, g_kn2[bh*NTOK + i]);
    }
    #pragma unroll
    for (int o = 16; o; o >>= 1) {
        mq = fmaxf(mq, __shfl_xor_sync(0xffffffffu, mq, o));
        mk = fmaxf(mk, __shfl_xor_sync(0xffffffffu, mk, o));
    }
    __shared__ float sq[8], sk[8];
    if ((tid & 31) == 0) { sq[tid>>5] = mq; sk[tid>>5] = mk; }
    __syncthreads();
    if (tid == 0) {
        float a = sq[0], b = sk[0];
        for (int w = 1; w < 8; w++) { a = fmaxf(a, sq[w]); b = fmaxf(b, sk[w]); }
        g_MQ2[bh] = a; g_MK2[bh] = b;
    }
}

// ---------------- K3: LSH hashes ----------------
__global__ void k_hash(const float* __restrict__ alpha, const float* __restrict__ beta) {
    __shared__ float sal[2*(EH+2)];
    __shared__ float sbe[2];
    int bh = blockIdx.y;
    int tid = threadIdx.x;
    if (tid < 2*(EH+2)) sal[tid] = alpha[tid];
    if (tid < 2) sbe[tid] = beta[tid];
    __syncthreads();
    int t = blockIdx.x*256 + tid;
    const float* qr = g_q + ((size_t)bh*NTOK + t)*EH;
    const float* kr = g_k + ((size_t)bh*NTOK + t)*EH;
    float a0 = 0.f, a1 = 0.f, c0 = 0.f, c1 = 0.f;
    #pragma unroll 8
    for (int e = 0; e < EH; e++) {
        float al0 = sal[e*2], al1 = sal[e*2+1];
        float qe = qr[e], ke = kr[e];
        a0 += qe*al0; a1 += qe*al1;
        c0 += ke*al0; c1 += ke*al1;
    }
    float S = g_MQ2[bh] + g_MK2[bh];
    float extq = sqrtf(fmaxf(S - g_qn2[bh*NTOK + t], 0.f));
    float extk = sqrtf(fmaxf(S - g_kn2[bh*NTOK + t], 0.f));
    g_hashq[bh*NTOK + t]           = a0 + extq*sal[EH*2]       + sbe[0];
    g_hashq[BH*NTOK + bh*NTOK + t] = a1 + extq*sal[EH*2+1]     + sbe[1];
    g_hashk[bh*NTOK + t]           = c0 + extk*sal[(EH+1)*2]   + sbe[0];
    g_hashk[BH*NTOK + bh*NTOK + t] = c1 + extk*sal[(EH+1)*2+1] + sbe[1];
}

// ---------------- K5: performer feature maps as tiled GEMM ----------------
#define FEATG_SMEM (2*64*FST*4 + 128*4)
__global__ __launch_bounds__(256, 2) void k_featg(const float* __restrict__ W) {
    extern __shared__ float sm[];
    float* sXt = sm;                    // [64][FST]
    float* sWt = sm + 64*FST;           // [64][FST]
    float* sN  = sm + 2*64*FST;         // [128]
    int nb = blockIdx.x, bh = blockIdx.y, isK = blockIdx.z;
    int tid = threadIdx.x, tx = tid & 15, ty = tid >> 4;
    const float* X  = isK ? g_k   : g_q;
    const float* n2 = isK ? g_kn2 : g_qn2;
    int tb = nb*128;
    for (int idx = tid; idx < 8192; idx += 256) {
        int i = idx >> 6, e = idx & 63;
        sXt[e*FST + i] = X[((size_t)bh*NTOK + tb + i)*EH + e];
        sWt[e*FST + i] = W[i*EH + e];
    }
    if (tid < 128) sN[tid] = n2[bh*NTOK + tb + tid];
    __syncthreads();
    u64t acc[4][8];
    #pragma unroll
    for (int r = 0; r < 4; r++)
        #pragma unroll
        for (int c = 0; c < 8; c++) acc[r][c] = 0ull;
    #pragma unroll 2
    for (int e = 0; e < 64; e++) {
        const u64t* ap = (const u64t*)(sXt + e*FST + ty*8);
        float4 b0q = *(const float4*)(sWt + e*FST + tx*8);
        float4 b1q = *(const float4*)(sWt + e*FST + tx*8 + 4);
        u64t bs[8];
        bs[0]=splat2(b0q.x); bs[1]=splat2(b0q.y); bs[2]=splat2(b0q.z); bs[3]=splat2(b0q.w);
        bs[4]=splat2(b1q.x); bs[5]=splat2(b1q.y); bs[6]=splat2(b1q.z); bs[7]=splat2(b1q.w);
        #pragma unroll
        for (int r2 = 0; r2 < 4; r2++) {
            u64t av = ap[r2];
            #pragma unroll
            for (int c = 0; c < 8; c++) fma2(acc[r2][c], av, bs[c]);
        }
    }
    #pragma unroll
    for (int r2 = 0; r2 < 4; r2++) {
        float2 v[8];
        #pragma unroll
        for (int c = 0; c < 8; c++) v[c] = unpk(acc[r2][c]);
        #pragma unroll
        for (int half = 0; half < 2; half++) {
            int row = ty*8 + r2*2 + half;
            int t = tb + row;
            float nn = 0.5f*TEMPF*sN[row] + HALF_LOG_M;
            float lp[8];
            float rm = -1e30f;
            #pragma unroll
            for (int c = 0; c < 8; c++) {
                lp[c] = (half ? v[c].y : v[c].x)*SQRT_TEMP - nn;
                rm = fmaxf(rm, lp[c]);
            }
            #pragma unroll
            for (int off = 8; off; off >>= 1) rm = fmaxf(rm, __shfl_xor_sync(0xffffffffu, rm, off));
            size_t base = ((size_t)bh*NTOK + t)*MF + tx*8;
            if (!isK) {
                *(float4*)(g_qp + base) = make_float4(__expf(lp[0]-rm), __expf(lp[1]-rm),
                                                      __expf(lp[2]-rm), __expf(lp[3]-rm));
                *(float4*)(g_qp + base + 4) = make_float4(__expf(lp[4]-rm), __expf(lp[5]-rm),
                                                          __expf(lp[6]-rm), __expf(lp[7]-rm));
                if (tx == 0) g_qls[bh*NTOK + t] = rm;
            } else {
                *(float4*)(g_kp + base)     = make_float4(lp[0], lp[1], lp[2], lp[3]);
                *(float4*)(g_kp + base + 4) = make_float4(lp[4], lp[5], lp[6], lp[7]);
                if (tx == 0) g_krm[bh*NTOK + t] = rm;
            }
        }
    }
}

// ---------------- K4: stable bitonic argsort ----------------
__global__ void k_sort() {
    __shared__ float sv[NTOK];
    __shared__ int   si[NTOK];
    int which = blockIdx.x >> 6;
    int rem   = blockIdx.x & 63;
    const float* src = which ? (g_hashk + (size_t)rem*NTOK) : (g_hashq + (size_t)rem*NTOK);
    int tid = threadIdx.x;
    for (int i = tid; i < NTOK; i += 512) { sv[i] = src[i]; si[i] = i; }
    __syncthreads();
    for (int k = 2; k <= NTOK; k <<= 1)
        for (int j = k >> 1; j > 0; j >>= 1) {
            for (int p = tid; p < NTOK/2; p += 512) {
                int i  = ((p & ~(j-1)) << 1) | (p & (j-1));
                int ix = i | j;
                bool up = ((i & k) == 0);
                float vi = sv[i], vj = sv[ix];
                int ii = si[i], ij = si[ix];
                bool agt = (vi > vj) || (vi == vj && ii > ij);
                if (agt == up) { sv[i] = vj; sv[ix] = vi; si[i] = ij; si[ix] = ii; }
            }
            __syncthreads();
        }
    int* pos = which ? g_kpos : g_qpos;
    int* rev = which ? g_krev : g_qrev;
    for (int r = tid; r < NTOK; r += 512) {
        int idx = si[r];
        pos[rem*NTOK + r]   = idx;
        rev[rem*NTOK + idx] = r;
    }
}

// ---------------- K6: per-bh max of k log-phi ----------------
__global__ void k_kls() {
    int bh = blockIdx.x, tid = threadIdx.x;
    float m = -1e30f;
    for (int i = tid; i < NTOK; i += 256) m = fmaxf(m, g_krm[bh*NTOK + i]);
    #pragma unroll
    for (int o = 16; o; o >>= 1) m = fmaxf(m, __shfl_xor_sync(0xffffffffu, m, o));
    __shared__ float s[8];
    if ((tid & 31) == 0) s[tid>>5] = m;
    __syncthreads();
    if (tid == 0) {
        float r = s[0];
        for (int w = 1; w < 8; w++) r = fmaxf(r, s[w]);
        g_kls[bh] = r;
    }
}

// ---------------- K8: partial kv = exp(k')^T v, tiled GEMM ----------------
#define KVP_SMEM (128*IST*4 + 128*68*4)
__global__ __launch_bounds__(256, 2) void k_kvpart2() {
    extern __shared__ float sm[];
    float* sKP = sm;                    // [128 t][IST]
    float* sV  = sm + 128*IST;          // [128 t][68]
    int ch = blockIdx.x, bh = blockIdx.y;
    int tid = threadIdx.x, tx = tid & 15, ty = tid >> 4;
    float kls = g_kls[bh];
    int t0 = ch*128;
    for (int idx = tid; idx < 16384; idx += 256) {
        int t = idx >> 7, m = idx & 127;
        sKP[t*IST + m] = __expf(g_kp[((size_t)bh*NTOK + t0 + t)*MF + m] - kls);
    }
    for (int idx = tid; idx < 8192; idx += 256) {
        int t = idx >> 6, d = idx & 63;
        sV[t*68 + d] = g_v[((size_t)bh*NTOK + t0 + t)*EH + d];
    }
    __syncthreads();
    u64t acc[4][4];
    #pragma unroll
    for (int r = 0; r < 4; r++)
        #pragma unroll
        for (int c = 0; c < 4; c++) acc[r][c] = 0ull;
    #pragma unroll 4
    for (int t = 0; t < 128; t++) {
        const u64t* ap = (const u64t*)(sKP + t*IST + ty*8);
        float4 bq = *(const float4*)(sV + t*68 + tx*4);
        u64t b0 = splat2(bq.x), b1 = splat2(bq.y), b2 = splat2(bq.z), b3 = splat2(bq.w);
        #pragma unroll
        for (int r2 = 0; r2 < 4; r2++) {
            u64t av = ap[r2];
            fma2(acc[r2][0], av, b0); fma2(acc[r2][1], av, b1);
            fma2(acc[r2][2], av, b2); fma2(acc[r2][3], av, b3);
        }
    }
    float* dst = g_kvp + ((size_t)(ch*BH + bh))*MF*EH;
    #pragma unroll
    for (int r2 = 0; r2 < 4; r2++) {
        float2 v0 = unpk(acc[r2][0]), v1 = unpk(acc[r2][1]);
        float2 v2 = unpk(acc[r2][2]), v3 = unpk(acc[r2][3]);
        int m = ty*8 + r2*2;
        *(float4*)(dst + (size_t)m*EH + tx*4)     = make_float4(v0.x, v1.x, v2.x, v3.x);
        *(float4*)(dst + (size_t)(m+1)*EH + tx*4) = make_float4(v0.y, v1.y, v2.y, v3.y);
    }
    if (tid < 128) {
        float s = 0.f;
        #pragma unroll 8
        for (int t = 0; t < 128; t++) s += sKP[t*IST + tid];
        g_ksp[(ch*BH + bh)*MF + tid] = s;
    }
}

// ---------------- K8b: deterministic reduce ----------------
__global__ void k_kvred() {
    int idx = blockIdx.x*256 + threadIdx.x;
    float s = 0.f;
    #pragma unroll
    for (int c = 0; c < NCH; c++) s += g_kvp[(size_t)c*BH*MF*EH + idx];
    g_kv[idx] = s;
    if (idx < BH*MF) {
        float ss = 0.f;
        #pragma unroll
        for (int c = 0; c < NCH; c++) ss += g_ksp[c*BH*MF + idx];
        g_ksum[idx] = ss;
    }
}

// ---------------- K9: qkv = q' kv + qk1, tiled GEMM ----------------
#define QKV_SMEM (128*IST*4 + 128*68*4 + 128*4)
__global__ __launch_bounds__(256, 2) void k_qkv2() {
    extern __shared__ float sm[];
    float* sQPt = sm;                   // [128 m][IST tokens]
    float* sKV  = sm + 128*IST;         // [128 m][68]
    float* sks  = sm + 128*IST + 128*68;
    int nb = blockIdx.x, bh = blockIdx.y;
    int tid = threadIdx.x, tx = tid & 15, ty = tid >> 4;
    int tb = nb*128;
    for (int idx = tid; idx < 16384; idx += 256) {
        int i = idx >> 7, m = idx & 127;
        sQPt[m*IST + i] = g_qp[((size_t)bh*NTOK + tb + i)*MF + m];
    }
    for (int idx = tid; idx < 8192; idx += 256) {
        int m = idx >> 6, d = idx & 63;
        sKV[m*68 + d] = g_kv[(size_t)bh*MF*EH + m*EH + d];
    }
    if (tid < 128) sks[tid] = g_ksum[bh*MF + tid];
    __syncthreads();
    u64t acc[4][4];
    #pragma unroll
    for (int r = 0; r < 4; r++)
        #pragma unroll
        for (int c = 0; c < 4; c++) acc[r][c] = 0ull;
    #pragma unroll 4
    for (int m = 0; m < 128; m++) {
        const u64t* ap = (const u64t*)(sQPt + m*IST + ty*8);
        float4 bq = *(const float4*)(sKV + m*68 + tx*4);
        u64t b0 = splat2(bq.x), b1 = splat2(bq.y), b2 = splat2(bq.z), b3 = splat2(bq.w);
        #pragma unroll
        for (int r2 = 0; r2 < 4; r2++) {
            u64t av = ap[r2];
            fma2(acc[r2][0], av, b0); fma2(acc[r2][1], av, b1);
            fma2(acc[r2][2], av, b2); fma2(acc[r2][3], av, b3);
        }
    }
    #pragma unroll
    for (int r2 = 0; r2 < 4; r2++) {
        float2 v0 = unpk(acc[r2][0]), v1 = unpk(acc[r2][1]);
        float2 v2 = unpk(acc[r2][2]), v3 = unpk(acc[r2][3]);
        int row = ty*8 + r2*2;
        *(float4*)(g_qkv + ((size_t)bh*NTOK + tb + row)*EH + tx*4)
            = make_float4(v0.x, v1.x, v2.x, v3.x);
        *(float4*)(g_qkv + ((size_t)bh*NTOK + tb + row + 1)*EH + tx*4)
            = make_float4(v0.y, v1.y, v2.y, v3.y);
    }
    if (tid < 128) {
        float s = 0.f;
        #pragma unroll 8
        for (int m = 0; m < 128; m++) s += sQPt[m*IST + tid]*sks[m];
        g_qk1[bh*NTOK + tb + tid] = s;
    }
}

// ================= bucketed correction =================
#define INNER_SMEM ((2*64*IST)*4 + 2*128*4)
__global__ __launch_bounds__(256, 2) void k_inner() {
    extern __shared__ float sm[];
    float* sQt = sm;                    // [64][IST]
    float* sKt = sm + 64*IST;
    int* sQi = (int*)(sm + 2*64*IST);
    int* sKi = sQi + 128;
    int nb = blockIdx.x, bh = blockIdx.y, h = blockIdx.z;
    int tid = threadIdx.x, tx = tid & 15, ty = tid >> 4;
    if (tid < 128) {
        sQi[tid] = g_qpos[(h*BH + bh)*NTOK + nb*128 + tid];
        sKi[tid] = g_kpos[(h*BH + bh)*NTOK + nb*128 + tid];
    }
    __syncthreads();
    for (int idx = tid; idx < 8192; idx += 256) {
        int i = idx >> 6, e = idx & 63;
        sQt[e*IST + i] = g_q[((size_t)bh*NTOK + sQi[i])*EH + e];
        sKt[e*IST + i] = g_k[((size_t)bh*NTOK + sKi[i])*EH + e];
    }
    __syncthreads();
    u64t aI[4][8];
    #pragma unroll
    for (int r = 0; r < 4; r++)
        #pragma unroll
        for (int c = 0; c < 8; c++) aI[r][c] = 0ull;
    #pragma unroll 2
    for (int e = 0; e < 64; e++) {
        const u64t* ap = (const u64t*)(sQt + e*IST + ty*8);
        float4 b0q = *(const float4*)(sKt + e*IST + tx*8);
        float4 b1q = *(const float4*)(sKt + e*IST + tx*8 + 4);
        u64t bs[8];
        bs[0]=splat2(b0q.x); bs[1]=splat2(b0q.y); bs[2]=splat2(b0q.z); bs[3]=splat2(b0q.w);
        bs[4]=splat2(b1q.x); bs[5]=splat2(b1q.y); bs[6]=splat2(b1q.z); bs[7]=splat2(b1q.w);
        #pragma unroll
        for (int r2 = 0; r2 < 4; r2++) {
            u64t av = ap[r2];
            #pragma unroll
            for (int c = 0; c < 8; c++) fma2(aI[r2][c], av, bs[c]);
        }
    }
    float* dbase = g_dots + ((size_t)(h*BH + bh)*NTOK + nb*128)*128;
    #pragma unroll
    for (int r2 = 0; r2 < 4; r2++) {
        float2 v[8];
        #pragma unroll
        for (int c = 0; c < 8; c++) v[c] = unpk(aI[r2][c]);
        int row = ty*8 + r2*2;
        *(float4*)(dbase + (size_t)row*128 + tx*8)     = make_float4(v[0].x, v[1].x, v[2].x, v[3].x);
        *(float4*)(dbase + (size_t)row*128 + tx*8 + 4) = make_float4(v[4].x, v[5].x, v[6].x, v[7].x);
        *(float4*)(dbase + (size_t)(row+1)*128 + tx*8)     = make_float4(v[0].y, v[1].y, v[2].y, v[3].y);
        *(float4*)(dbase + (size_t)(row+1)*128 + tx*8 + 4) = make_float4(v[4].y, v[5].y, v[6].y, v[7].y);
    }
}

// ---- fused prime GEMM + epilogue + OV GEMM (dots stay in smem) ----
#define PRIMEOV_SMEM ((128*DST + 128*68)*4)
__global__ __launch_bounds__(256, 2) void k_primeov() {
    extern __shared__ float sm[];
    float* sD = sm;                     // tiles during GEMM, then dots [128][DST]
    float* sV = sm + 128*DST;           // [128][68]
    __shared__ int sQi[128], sKi[128], sQb[128], sKb[128];
    __shared__ float sPls[128];
    int nb = blockIdx.x, bh = blockIdx.y, h = blockIdx.z;
    int tid = threadIdx.x, tx = tid & 15, ty = tid >> 4;
    int o = 1 - h;
    float kls = g_kls[bh];
    if (tid < 128) {
        int qi = g_qpos[(h*BH + bh)*NTOK + nb*128 + tid];
        int ki = g_kpos[(h*BH + bh)*NTOK + nb*128 + tid];
        sQi[tid] = qi; sKi[tid] = ki;
        sQb[tid] = g_qrev[(o*BH + bh)*NTOK + qi] >> 7;
        sKb[tid] = g_krev[(o*BH + bh)*NTOK + ki] >> 7;
        sPls[tid] = g_qls[bh*NTOK + qi] + kls;
    }
    float* sQPt = sm;                   // [64][IST]
    float* sKPt = sm + 64*IST;
    u64t aP[4][8];
    #pragma unroll
    for (int r = 0; r < 4; r++)
        #pragma unroll
        for (int c = 0; c < 8; c++) aP[r][c] = 0ull;
    for (int mc = 0; mc < 2; mc++) {
        __syncthreads();
        for (int idx = tid; idx < 8192; idx += 256) {
            int i = idx >> 6, ml = idx & 63;
            sQPt[ml*IST + i] = g_qp[((size_t)bh*NTOK + sQi[i])*MF + mc*64 + ml];
            sKPt[ml*IST + i] = __expf(g_kp[((size_t)bh*NTOK + sKi[i])*MF + mc*64 + ml] - kls);
        }
        __syncthreads();
        #pragma unroll 2
        for (int m = 0; m < 64; m++) {
            const u64t* ap = (const u64t*)(sQPt + m*IST + ty*8);
            float4 b0q = *(const float4*)(sKPt + m*IST + tx*8);
            float4 b1q = *(const float4*)(sKPt + m*IST + tx*8 + 4);
            u64t bs[8];
            bs[0]=splat2(b0q.x); bs[1]=splat2(b0q.y); bs[2]=splat2(b0q.z); bs[3]=splat2(b0q.w);
            bs[4]=splat2(b1q.x); bs[5]=splat2(b1q.y); bs[6]=splat2(b1q.z); bs[7]=splat2(b1q.w);
            #pragma unroll
            for (int r2 = 0; r2 < 4; r2++) {
                u64t av = ap[r2];
                #pragma unroll
                for (int c = 0; c < 8; c++) fma2(aP[r2][c], av, bs[c]);
            }
        }
    }
    __syncthreads();   // all tile reads done; sD overwrite safe below
    // epilogue: read raw inner from global, dup-correct, LSE, exp → dots in smem
    int kb[8];
    #pragma unroll
    for (int c = 0; c < 8; c++) kb[c] = sKb[tx*8 + c];
    const float* ibase = g_dots + ((size_t)(h*BH + bh)*NTOK + nb*128)*128;
    #pragma unroll
    for (int r2 = 0; r2 < 4; r2++) {
        float2 P[8];
        #pragma unroll
        for (int c = 0; c < 8; c++) P[c] = unpk(aP[r2][c]);
        #pragma unroll
        for (int half = 0; half < 2; half++) {
            int row = ty*8 + r2*2 + half;
            int qb = sQb[row]; float pls = sPls[row];
            float4 in0 = *(const float4*)(ibase + (size_t)row*128 + tx*8);
            float4 in1 = *(const float4*)(ibase + (size_t)row*128 + tx*8 + 4);
            float iv[8] = {in0.x, in0.y, in0.z, in0.w, in1.x, in1.y, in1.z, in1.w};
            float pv[8];
            float rm = -1e30f;
            #pragma unroll
            for (int c = 0; c < 8; c++) {
                bool d2 = (qb == kb[c]);
                iv[c] = iv[c]*TEMPF - (d2 ? LN2F : 0.f);
                pv[c] = (half ? P[c].y : P[c].x) * (d2 ? 0.5f : 1.f);
                rm = fmaxf(rm, iv[c]);
            }
            #pragma unroll
            for (int off = 8; off; off >>= 1) rm = fmaxf(rm, __shfl_xor_sync(0xffffffffu, rm, off));
            float l = fmaxf(rm, pls);
            float pe = __expf(pls - l);
            float dv[8];
            float s = 0.f;
            #pragma unroll
            for (int c = 0; c < 8; c++) { dv[c] = __expf(iv[c] - l) - pv[c]*pe; s += dv[c]; }
            *(float4*)(sD + row*DST + tx*8)     = make_float4(dv[0], dv[1], dv[2], dv[3]);
            *(float4*)(sD + row*DST + tx*8 + 4) = make_float4(dv[4], dv[5], dv[6], dv[7]);
            #pragma unroll
            for (int off = 8; off; off >>= 1) s += __shfl_xor_sync(0xffffffffu, s, off);
            if (tx == 0) {
                int t = sQi[row];
                size_t bi = (size_t)(h*BH + bh)*NTOK + t;
                g_lseb[bi] = l;
                g_dsb[bi]  = s;
            }
        }
    }
    // gather V
    for (int idx = tid; idx < 8192; idx += 256) {
        int i = idx >> 6, d = idx & 63;
        sV[i*68 + d] = g_v[((size_t)bh*NTOK + sKi[i])*EH + d];
    }
    __syncthreads();
    // OV GEMM: so = dots @ V, scatter unsorted
    int tx2 = tid & 15, ty2 = tid >> 4;
    u64t accO[8][2];
    #pragma unroll
    for (int r = 0; r < 8; r++) { accO[r][0] = 0ull; accO[r][1] = 0ull; }
    for (int j0 = 0; j0 < 128; j0 += 4) {
        float4 a[8];
        #pragma unroll
        for (int r = 0; r < 8; r++) a[r] = *(const float4*)(sD + (ty2*8 + r)*DST + j0);
        #pragma unroll
        for (int jj = 0; jj < 4; jj++) {
            float4 t = *(const float4*)(sV + (j0 + jj)*68 + tx2*4);
            u64t bv0 = pack2(t.x, t.y), bv1 = pack2(t.z, t.w);
            #pragma unroll
            for (int r = 0; r < 8; r++) {
                float av = (jj==0)?a[r].x:(jj==1)?a[r].y:(jj==2)?a[r].z:a[r].w;
                u64t s = splat2(av);
                fma2(accO[r][0], s, bv0); fma2(accO[r][1], s, bv1);
            }
        }
    }
    #pragma unroll
    for (int r = 0; r < 8; r++) {
        int t = sQi[ty2*8 + r];
        float2 u0 = unpk(accO[r][0]), u1 = unpk(accO[r][1]);
        *(float4*)(g_ob + ((size_t)(h*BH + bh)*NTOK + t)*EH + tx2*4) =
            make_float4(u0.x, u0.y, u1.x, u1.y);
    }
}

// ---------------- K11: merge performer + LSH branches ----------------
__global__ void k_merge() {
    int tid = threadIdx.x;
    int t = blockIdx.x*4 + (tid >> 6);
    int d = tid & 63;
    int bh = blockIdx.y;
    size_t i0 = (size_t)bh*NTOK + t;
    size_t i1 = (size_t)(BH + bh)*NTOK + t;
    float l0 = g_lseb[i0], l1 = g_lseb[i1];
    float mx = fmaxf(l0, l1);
    float norm = mx + logf(__expf(l0 - mx) + __expf(l1 - mx));
    float p0 = __expf(l0 - norm), p1 = __expf(l1 - norm);
    float pls = g_qls[bh*NTOK + t] + g_kls[bh];
    float psc = __expf(pls - norm);
    float z = g_dsb[i0]*p0 + g_dsb[i1]*p1 + g_qk1[bh*NTOK + t]*psc;
    z = fmaxf(z, 1e-6f);
    size_t base = ((size_t)bh*NTOK + t)*EH + d;
    float outv = g_ob[i0*EH + d]*p0 + g_ob[i1*EH + d]*p1 + g_qkv[base]*psc;
    g_on[base] = outv / z;
}

// ---------------- K12: final projection (16 tokens/block) ----------------
#define WS 130
#define XS 132
__global__ __launch_bounds__(256) void k_final(const float* __restrict__ Wf,
                                               const float* __restrict__ bias,
                                               float* __restrict__ out) {
    __shared__ float sW2[64*WS];
    __shared__ float sX[16*XS];
    int tid = threadIdx.x;
    int tok = tid >> 6, eo = tid & 63;
    int g0 = blockIdx.x*16;
    u64t acc2[4];
    #pragma unroll
    for (int tt = 0; tt < 4; tt++) acc2[tt] = 0ull;
    for (int c = 0; c < 4; c++) {
        __syncthreads();
        for (int idx = tid; idx < 8192; idx += 256) {
            int e2 = idx >> 7, hd = idx & 127;
            sW2[e2*WS + hd] = Wf[e2*512 + c*128 + hd];
        }
        for (int idx = tid; idx < 2048; idx += 256) {
            int tk = idx >> 7, hd = idx & 127;
            int gg = g0 + tk;
            int b = gg >> 12, t = gg & 4095;
            int hdg = c*128 + hd;
            sX[tk*XS + hd] = g_on[(((size_t)(b*8 + (hdg >> 6)))*NTOK + t)*EH + (hdg & 63)];
        }
        __syncthreads();
        const u64t* wp = (const u64t*)(sW2 + eo*WS);
        #pragma unroll
        for (int tt = 0; tt < 4; tt++) {
            const float4* x4 = (const float4*)(sX + (tok + tt*4)*XS);
            #pragma unroll
            for (int h4 = 0; h4 < 32; h4++) {
                float4 xv = x4[h4];
                fma2(acc2[tt], pack2(xv.x, xv.y), wp[2*h4]);
                fma2(acc2[tt], pack2(xv.z, xv.w), wp[2*h4+1]);
            }
        }
    }
    float bv = bias[eo];
    #pragma unroll
    for (int tt = 0; tt < 4; tt++) {
        float2 u = unpk(acc2[tt]);
        out[(size_t)(g0 + tok + tt*4)*EH + eo] = u.x + u.y + bv;
    }
}

// ---------------- launch ----------------
extern "C" void kernel_launch(void* const* d_in, const int* in_sizes, int n_in,
                              void* d_out, int out_size) {
    const float* query = (const float*)d_in[0];
    const float* key   = (const float*)d_in[1];
    const float* value = (const float*)d_in[2];
    const float* projW = (const float*)d_in[3];
    const float* alpha = (const float*)d_in[4];
    const float* beta  = (const float*)d_in[5];
    const float* outW  = (const float*)d_in[6];
    const float* outb  = (const float*)d_in[7];
    float* out = (float*)d_out;

    cudaFuncSetAttribute(k_featg,   cudaFuncAttributeMaxDynamicSharedMemorySize, FEATG_SMEM);
    cudaFuncSetAttribute(k_kvpart2, cudaFuncAttributeMaxDynamicSharedMemorySize, KVP_SMEM);
    cudaFuncSetAttribute(k_qkv2,    cudaFuncAttributeMaxDynamicSharedMemorySize, QKV_SMEM);
    cudaFuncSetAttribute(k_inner,   cudaFuncAttributeMaxDynamicSharedMemorySize, INNER_SMEM);
    cudaFuncSetAttribute(k_primeov, cudaFuncAttributeMaxDynamicSharedMemorySize, PRIMEOV_SMEM);

    k_split<<<dim3(NTOK/4, BH), 256>>>(query, key, value);
    k_featg<<<dim3(NTOK/128, BH, 2), 256, FEATG_SMEM>>>(projW);
    k_kls<<<BH, 256>>>();
    k_kvpart2<<<dim3(NCH, BH), 256, KVP_SMEM>>>();      // profiled slot (idx 3)
    k_maxn<<<BH, 256>>>();
    k_hash<<<dim3(NTOK/256, BH), 256>>>(alpha, beta);
    k_sort<<<128, 512>>>();
    k_kvred<<<BH*MF*EH/256, 256>>>();
    k_qkv2<<<dim3(NTOK/128, BH), 256, QKV_SMEM>>>();
    k_inner<<<dim3(32, BH, 2), 256, INNER_SMEM>>>();
    k_primeov<<<dim3(32, BH, 2), 256, PRIMEOV_SMEM>>>();
    k_merge<<<dim3(NTOK/4, BH), 256>>>();
    k_final<<<NTOK*4/16, 256>>>(outW, outb, out);
}

// round 9
// speedup vs baseline: 2.0028x; 1.0268x over previous
#include <cuda_runtime.h>
#include <math.h>

#define BH 32
#define NTOK 4096
#define EH 64
#define MF 128
#define DM 512
#define NCH 32
#define IST 132
#define FST 132
#define DST 132

#define SQRT_TEMP 0.35355339059327373f
#define TEMPF 0.125f
#define HALF_LOG_M 2.4260151319598084f
#define LN2F 0.6931471805599453f

typedef unsigned long long u64t;
__device__ __forceinline__ u64t splat2(float x) {
    u64t r; asm("mov.b64 %0, {%1, %1};" : "=l"(r) : "f"(x)); return r;
}
__device__ __forceinline__ u64t pack2(float x, float y) {
    u64t r; asm("mov.b64 %0, {%1, %2};" : "=l"(r) : "f"(x), "f"(y)); return r;
}
__device__ __forceinline__ void fma2(u64t& c, u64t a, u64t b) {
    asm("fma.rn.f32x2 %0, %1, %2, %0;" : "+l"(c) : "l"(a), "l"(b));
}
__device__ __forceinline__ float2 unpk(u64t v) {
    float2 f; asm("mov.b64 {%0, %1}, %2;" : "=f"(f.x), "=f"(f.y) : "l"(v)); return f;
}

// ---------------- scratch ----------------
__device__ float g_q[BH*NTOK*EH];
__device__ float g_k[BH*NTOK*EH];
__device__ float g_v[BH*NTOK*EH];
__device__ float g_qn2[BH*NTOK];
__device__ float g_kn2[BH*NTOK];
__device__ float g_MQ2[BH];
__device__ float g_MK2[BH];
__device__ float g_hashq[2*BH*NTOK];
__device__ float g_hashk[2*BH*NTOK];
__device__ int   g_qpos[2*BH*NTOK];
__device__ int   g_kpos[2*BH*NTOK];
__device__ int   g_qrev[2*BH*NTOK];
__device__ int   g_krev[2*BH*NTOK];
__device__ float g_qp[(size_t)BH*NTOK*MF];
__device__ float g_kp[(size_t)BH*NTOK*MF];    // log-phi (pre-exp)
__device__ float g_qls[BH*NTOK];
__device__ float g_krm[BH*NTOK];
__device__ float g_kls[BH];
__device__ float g_kvp[(size_t)NCH*BH*MF*EH];
__device__ float g_ksp[NCH*BH*MF];
__device__ float g_kv[BH*MF*EH];
__device__ float g_ksum[BH*MF];
__device__ float g_qk1[BH*NTOK];
__device__ float g_qkv[(size_t)BH*NTOK*EH];
__device__ float g_ob[(size_t)2*BH*NTOK*EH];
__device__ float g_lseb[2*BH*NTOK];
__device__ float g_dsb[2*BH*NTOK];
__device__ float g_on[(size_t)BH*NTOK*EH];

// ---------------- K1: split heads + squared norms ----------------
__global__ __launch_bounds__(256) void k_split(const float* __restrict__ query,
                                               const float* __restrict__ key,
                                               const float* __restrict__ value) {
    int tid = threadIdx.x;
    int tl = tid >> 6, e = tid & 63;
    int t = blockIdx.x*4 + tl, bh = blockIdx.y;
    int b = bh >> 3, hh = bh & 7;
    size_t gi = ((size_t)(b*NTOK + t))*DM + hh*EH + e;
    float qv = query[gi], kv = key[gi], vv = value[gi];
    size_t oi = ((size_t)bh*NTOK + t)*EH + e;
    g_q[oi] = qv; g_k[oi] = kv; g_v[oi] = vv;
    float q2 = qv*qv, k2 = kv*kv;
    #pragma unroll
    for (int o = 16; o; o >>= 1) {
        q2 += __shfl_down_sync(0xffffffffu, q2, o);
        k2 += __shfl_down_sync(0xffffffffu, k2, o);
    }
    __shared__ float sq[8], sk[8];
    if ((tid & 31) == 0) { sq[tid>>5] = q2; sk[tid>>5] = k2; }
    __syncthreads();
    if (e == 0) {
        g_qn2[bh*NTOK + t] = sq[2*tl] + sq[2*tl+1];
        g_kn2[bh*NTOK + t] = sk[2*tl] + sk[2*tl+1];
    }
}

// ---------------- K2: per-bh max squared norms ----------------
__global__ void k_maxn() {
    int bh = blockIdx.x, tid = threadIdx.x;
    float mq = 0.f, mk = 0.f;
    for (int i = tid; i < NTOK; i += 256) {
        mq = fmaxf(mq, g_qn2[bh*NTOK + i]);
        mk = fmaxf(mk, g_kn2[bh*NTOK + i]);
    }
    #pragma unroll
    for (int o = 16; o; o >>= 1) {
        mq = fmaxf(mq, __shfl_xor_sync(0xffffffffu, mq, o));
        mk = fmaxf(mk, __shfl_xor_sync(0xffffffffu, mk, o));
    }
    __shared__ float sq[8], sk[8];
    if ((tid & 31) == 0) { sq[tid>>5] = mq; sk[tid>>5] = mk; }
    __syncthreads();
    if (tid == 0) {
        float a = sq[0], b = sk[0];
        for (int w = 1; w < 8; w++) { a = fmaxf(a, sq[w]); b = fmaxf(b, sk[w]); }
        g_MQ2[bh] = a; g_MK2[bh] = b;
    }
}

// ---------------- K3: LSH hashes ----------------
__global__ void k_hash(const float* __restrict__ alpha, const float* __restrict__ beta) {
    __shared__ float sal[2*(EH+2)];
    __shared__ float sbe[2];
    int bh = blockIdx.y;
    int tid = threadIdx.x;
    if (tid < 2*(EH+2)) sal[tid] = alpha[tid];
    if (tid < 2) sbe[tid] = beta[tid];
    __syncthreads();
    int t = blockIdx.x*256 + tid;
    const float* qr = g_q + ((size_t)bh*NTOK + t)*EH;
    const float* kr = g_k + ((size_t)bh*NTOK + t)*EH;
    float a0 = 0.f, a1 = 0.f, c0 = 0.f, c1 = 0.f;
    #pragma unroll 8
    for (int e = 0; e < EH; e++) {
        float al0 = sal[e*2], al1 = sal[e*2+1];
        float qe = qr[e], ke = kr[e];
        a0 += qe*al0; a1 += qe*al1;
        c0 += ke*al0; c1 += ke*al1;
    }
    float S = g_MQ2[bh] + g_MK2[bh];
    float extq = sqrtf(fmaxf(S - g_qn2[bh*NTOK + t], 0.f));
    float extk = sqrtf(fmaxf(S - g_kn2[bh*NTOK + t], 0.f));
    g_hashq[bh*NTOK + t]           = a0 + extq*sal[EH*2]       + sbe[0];
    g_hashq[BH*NTOK + bh*NTOK + t] = a1 + extq*sal[EH*2+1]     + sbe[1];
    g_hashk[bh*NTOK + t]           = c0 + extk*sal[(EH+1)*2]   + sbe[0];
    g_hashk[BH*NTOK + bh*NTOK + t] = c1 + extk*sal[(EH+1)*2+1] + sbe[1];
}

// ---------------- K5: performer feature maps as tiled GEMM ----------------
#define FEATG_SMEM (2*64*FST*4 + 128*4)
__global__ __launch_bounds__(256, 2) void k_featg(const float* __restrict__ W) {
    extern __shared__ float sm[];
    float* sXt = sm;                    // [64][FST]
    float* sWt = sm + 64*FST;           // [64][FST]
    float* sN  = sm + 2*64*FST;         // [128]
    int nb = blockIdx.x, bh = blockIdx.y, isK = blockIdx.z;
    int tid = threadIdx.x, tx = tid & 15, ty = tid >> 4;
    const float* X  = isK ? g_k   : g_q;
    const float* n2 = isK ? g_kn2 : g_qn2;
    int tb = nb*128;
    for (int idx = tid; idx < 8192; idx += 256) {
        int i = idx >> 6, e = idx & 63;
        sXt[e*FST + i] = X[((size_t)bh*NTOK + tb + i)*EH + e];
        sWt[e*FST + i] = W[i*EH + e];
    }
    if (tid < 128) sN[tid] = n2[bh*NTOK + tb + tid];
    __syncthreads();
    u64t acc[4][8];
    #pragma unroll
    for (int r = 0; r < 4; r++)
        #pragma unroll
        for (int c = 0; c < 8; c++) acc[r][c] = 0ull;
    #pragma unroll 2
    for (int e = 0; e < 64; e++) {
        const u64t* ap = (const u64t*)(sXt + e*FST + ty*8);
        float4 b0q = *(const float4*)(sWt + e*FST + tx*8);
        float4 b1q = *(const float4*)(sWt + e*FST + tx*8 + 4);
        u64t bs[8];
        bs[0]=splat2(b0q.x); bs[1]=splat2(b0q.y); bs[2]=splat2(b0q.z); bs[3]=splat2(b0q.w);
        bs[4]=splat2(b1q.x); bs[5]=splat2(b1q.y); bs[6]=splat2(b1q.z); bs[7]=splat2(b1q.w);
        #pragma unroll
        for (int r2 = 0; r2 < 4; r2++) {
            u64t av = ap[r2];
            #pragma unroll
            for (int c = 0; c < 8; c++) fma2(acc[r2][c], av, bs[c]);
        }
    }
    #pragma unroll
    for (int r2 = 0; r2 < 4; r2++) {
        float2 v[8];
        #pragma unroll
        for (int c = 0; c < 8; c++) v[c] = unpk(acc[r2][c]);
        #pragma unroll
        for (int half = 0; half < 2; half++) {
            int row = ty*8 + r2*2 + half;
            int t = tb + row;
            float nn = 0.5f*TEMPF*sN[row] + HALF_LOG_M;
            float lp[8];
            float rm = -1e30f;
            #pragma unroll
            for (int c = 0; c < 8; c++) {
                lp[c] = (half ? v[c].y : v[c].x)*SQRT_TEMP - nn;
                rm = fmaxf(rm, lp[c]);
            }
            #pragma unroll
            for (int off = 8; off; off >>= 1) rm = fmaxf(rm, __shfl_xor_sync(0xffffffffu, rm, off));
            size_t base = ((size_t)bh*NTOK + t)*MF + tx*8;
            if (!isK) {
                *(float4*)(g_qp + base) = make_float4(__expf(lp[0]-rm), __expf(lp[1]-rm),
                                                      __expf(lp[2]-rm), __expf(lp[3]-rm));
                *(float4*)(g_qp + base + 4) = make_float4(__expf(lp[4]-rm), __expf(lp[5]-rm),
                                                          __expf(lp[6]-rm), __expf(lp[7]-rm));
                if (tx == 0) g_qls[bh*NTOK + t] = rm;
            } else {
                *(float4*)(g_kp + base)     = make_float4(lp[0], lp[1], lp[2], lp[3]);
                *(float4*)(g_kp + base + 4) = make_float4(lp[4], lp[5], lp[6], lp[7]);
                if (tx == 0) g_krm[bh*NTOK + t] = rm;
            }
        }
    }
}

// ---------------- K4: stable bitonic argsort ----------------
__global__ void k_sort() {
    __shared__ float sv[NTOK];
    __shared__ int   si[NTOK];
    int which = blockIdx.x >> 6;
    int rem   = blockIdx.x & 63;
    const float* src = which ? (g_hashk + (size_t)rem*NTOK) : (g_hashq + (size_t)rem*NTOK);
    int tid = threadIdx.x;
    for (int i = tid; i < NTOK; i += 512) { sv[i] = src[i]; si[i] = i; }
    __syncthreads();
    for (int k = 2; k <= NTOK; k <<= 1)
        for (int j = k >> 1; j > 0; j >>= 1) {
            for (int p = tid; p < NTOK/2; p += 512) {
                int i  = ((p & ~(j-1)) << 1) | (p & (j-1));
                int ix = i | j;
                bool up = ((i & k) == 0);
                float vi = sv[i], vj = sv[ix];
                int ii = si[i], ij = si[ix];
                bool agt = (vi > vj) || (vi == vj && ii > ij);
                if (agt == up) { sv[i] = vj; sv[ix] = vi; si[i] = ij; si[ix] = ii; }
            }
            __syncthreads();
        }
    int* pos = which ? g_kpos : g_qpos;
    int* rev = which ? g_krev : g_qrev;
    for (int r = tid; r < NTOK; r += 512) {
        int idx = si[r];
        pos[rem*NTOK + r]   = idx;
        rev[rem*NTOK + idx] = r;
    }
}

// ---------------- K6: per-bh max of k log-phi ----------------
__global__ void k_kls() {
    int bh = blockIdx.x, tid = threadIdx.x;
    float m = -1e30f;
    for (int i = tid; i < NTOK; i += 256) m = fmaxf(m, g_krm[bh*NTOK + i]);
    #pragma unroll
    for (int o = 16; o; o >>= 1) m = fmaxf(m, __shfl_xor_sync(0xffffffffu, m, o));
    __shared__ float s[8];
    if ((tid & 31) == 0) s[tid>>5] = m;
    __syncthreads();
    if (tid == 0) {
        float r = s[0];
        for (int w = 1; w < 8; w++) r = fmaxf(r, s[w]);
        g_kls[bh] = r;
    }
}

// ---------------- K8: partial kv = exp(k')^T v, tiled GEMM ----------------
#define KVP_SMEM (128*IST*4 + 128*68*4)
__global__ __launch_bounds__(256, 2) void k_kvpart2() {
    extern __shared__ float sm[];
    float* sKP = sm;                    // [128 t][IST]
    float* sV  = sm + 128*IST;          // [128 t][68]
    int ch = blockIdx.x, bh = blockIdx.y;
    int tid = threadIdx.x, tx = tid & 15, ty = tid >> 4;
    float kls = g_kls[bh];
    int t0 = ch*128;
    for (int idx = tid; idx < 16384; idx += 256) {
        int t = idx >> 7, m = idx & 127;
        sKP[t*IST + m] = __expf(g_kp[((size_t)bh*NTOK + t0 + t)*MF + m] - kls);
    }
    for (int idx = tid; idx < 8192; idx += 256) {
        int t = idx >> 6, d = idx & 63;
        sV[t*68 + d] = g_v[((size_t)bh*NTOK + t0 + t)*EH + d];
    }
    __syncthreads();
    u64t acc[4][4];
    #pragma unroll
    for (int r = 0; r < 4; r++)
        #pragma unroll
        for (int c = 0; c < 4; c++) acc[r][c] = 0ull;
    #pragma unroll 4
    for (int t = 0; t < 128; t++) {
        const u64t* ap = (const u64t*)(sKP + t*IST + ty*8);
        float4 bq = *(const float4*)(sV + t*68 + tx*4);
        u64t b0 = splat2(bq.x), b1 = splat2(bq.y), b2 = splat2(bq.z), b3 = splat2(bq.w);
        #pragma unroll
        for (int r2 = 0; r2 < 4; r2++) {
            u64t av = ap[r2];
            fma2(acc[r2][0], av, b0); fma2(acc[r2][1], av, b1);
            fma2(acc[r2][2], av, b2); fma2(acc[r2][3], av, b3);
        }
    }
    float* dst = g_kvp + ((size_t)(ch*BH + bh))*MF*EH;
    #pragma unroll
    for (int r2 = 0; r2 < 4; r2++) {
        float2 v0 = unpk(acc[r2][0]), v1 = unpk(acc[r2][1]);
        float2 v2 = unpk(acc[r2][2]), v3 = unpk(acc[r2][3]);
        int m = ty*8 + r2*2;
        *(float4*)(dst + (size_t)m*EH + tx*4)     = make_float4(v0.x, v1.x, v2.x, v3.x);
        *(float4*)(dst + (size_t)(m+1)*EH + tx*4) = make_float4(v0.y, v1.y, v2.y, v3.y);
    }
    if (tid < 128) {
        float s = 0.f;
        #pragma unroll 8
        for (int t = 0; t < 128; t++) s += sKP[t*IST + tid];
        g_ksp[(ch*BH + bh)*MF + tid] = s;
    }
}

// ---------------- K8b: deterministic reduce ----------------
__global__ void k_kvred() {
    int idx = blockIdx.x*256 + threadIdx.x;
    float s = 0.f;
    #pragma unroll
    for (int c = 0; c < NCH; c++) s += g_kvp[(size_t)c*BH*MF*EH + idx];
    g_kv[idx] = s;
    if (idx < BH*MF) {
        float ss = 0.f;
        #pragma unroll
        for (int c = 0; c < NCH; c++) ss += g_ksp[c*BH*MF + idx];
        g_ksum[idx] = ss;
    }
}

// ---------------- K9: qkv = q' kv + qk1, tiled GEMM ----------------
#define QKV_SMEM (128*IST*4 + 128*68*4 + 128*4)
__global__ __launch_bounds__(256, 2) void k_qkv2() {
    extern __shared__ float sm[];
    float* sQPt = sm;                   // [128 m][IST tokens]
    float* sKV  = sm + 128*IST;         // [128 m][68]
    float* sks  = sm + 128*IST + 128*68;
    int nb = blockIdx.x, bh = blockIdx.y;
    int tid = threadIdx.x, tx = tid & 15, ty = tid >> 4;
    int tb = nb*128;
    for (int idx = tid; idx < 16384; idx += 256) {
        int i = idx >> 7, m = idx & 127;
        sQPt[m*IST + i] = g_qp[((size_t)bh*NTOK + tb + i)*MF + m];
    }
    for (int idx = tid; idx < 8192; idx += 256) {
        int m = idx >> 6, d = idx & 63;
        sKV[m*68 + d] = g_kv[(size_t)bh*MF*EH + m*EH + d];
    }
    if (tid < 128) sks[tid] = g_ksum[bh*MF + tid];
    __syncthreads();
    u64t acc[4][4];
    #pragma unroll
    for (int r = 0; r < 4; r++)
        #pragma unroll
        for (int c = 0; c < 4; c++) acc[r][c] = 0ull;
    #pragma unroll 4
    for (int m = 0; m < 128; m++) {
        const u64t* ap = (const u64t*)(sQPt + m*IST + ty*8);
        float4 bq = *(const float4*)(sKV + m*68 + tx*4);
        u64t b0 = splat2(bq.x), b1 = splat2(bq.y), b2 = splat2(bq.z), b3 = splat2(bq.w);
        #pragma unroll
        for (int r2 = 0; r2 < 4; r2++) {
            u64t av = ap[r2];
            fma2(acc[r2][0], av, b0); fma2(acc[r2][1], av, b1);
            fma2(acc[r2][2], av, b2); fma2(acc[r2][3], av, b3);
        }
    }
    #pragma unroll
    for (int r2 = 0; r2 < 4; r2++) {
        float2 v0 = unpk(acc[r2][0]), v1 = unpk(acc[r2][1]);
        float2 v2 = unpk(acc[r2][2]), v3 = unpk(acc[r2][3]);
        int row = ty*8 + r2*2;
        *(float4*)(g_qkv + ((size_t)bh*NTOK + tb + row)*EH + tx*4)
            = make_float4(v0.x, v1.x, v2.x, v3.x);
        *(float4*)(g_qkv + ((size_t)bh*NTOK + tb + row + 1)*EH + tx*4)
            = make_float4(v0.y, v1.y, v2.y, v3.y);
    }
    if (tid < 128) {
        float s = 0.f;
        #pragma unroll 8
        for (int m = 0; m < 128; m++) s += sQPt[m*IST + tid]*sks[m];
        g_qk1[bh*NTOK + tb + tid] = s;
    }
}

// ======= K10: fully fused bucketed correction (QK^T + Q'K'^T + epi + OV) =======
// smem: R2 = dots/inner [128][DST] (67.6KB); R1 = chunked tiles / V (34.8KB)
#define R1_FLOATS 8704
#define BKT_SMEM ((128*DST + R1_FLOATS)*4)
__global__ __launch_bounds__(256, 2) void k_bucket2() {
    extern __shared__ float sm[];
    float* sD  = sm;                    // [128][DST]
    float* sR1 = sm + 128*DST;          // tiles: [32][IST] x2 ; later V [128][68]
    __shared__ int sQi[128], sKi[128], sQb[128], sKb[128];
    __shared__ float sPls[128];
    int nb = blockIdx.x, bh = blockIdx.y, h = blockIdx.z;
    int tid = threadIdx.x, tx = tid & 15, ty = tid >> 4;
    int o = 1 - h;
    float kls = g_kls[bh];
    if (tid < 128) {
        int qi = g_qpos[(h*BH + bh)*NTOK + nb*128 + tid];
        int ki = g_kpos[(h*BH + bh)*NTOK + nb*128 + tid];
        sQi[tid] = qi; sKi[tid] = ki;
        sQb[tid] = g_qrev[(o*BH + bh)*NTOK + qi] >> 7;
        sKb[tid] = g_krev[(o*BH + bh)*NTOK + ki] >> 7;
        sPls[tid] = g_qls[bh*NTOK + qi] + kls;
    }
    float* sQt = sR1;                   // [32][IST]
    float* sKt = sR1 + 32*IST;

    // ---- Phase A: inner = q k^T (2 e-chunks of 32) ----
    u64t aI[4][8];
    #pragma unroll
    for (int r = 0; r < 4; r++)
        #pragma unroll
        for (int c = 0; c < 8; c++) aI[r][c] = 0ull;
    for (int ec = 0; ec < 2; ec++) {
        __syncthreads();
        for (int idx = tid; idx < 4096; idx += 256) {
            int i = idx >> 5, el = idx & 31;
            sQt[el*IST + i] = g_q[((size_t)bh*NTOK + sQi[i])*EH + ec*32 + el];
            sKt[el*IST + i] = g_k[((size_t)bh*NTOK + sKi[i])*EH + ec*32 + el];
        }
        __syncthreads();
        #pragma unroll 2
        for (int e = 0; e < 32; e++) {
            const u64t* ap = (const u64t*)(sQt + e*IST + ty*8);
            float4 b0q = *(const float4*)(sKt + e*IST + tx*8);
            float4 b1q = *(const float4*)(sKt + e*IST + tx*8 + 4);
            u64t bs[8];
            bs[0]=splat2(b0q.x); bs[1]=splat2(b0q.y); bs[2]=splat2(b0q.z); bs[3]=splat2(b0q.w);
            bs[4]=splat2(b1q.x); bs[5]=splat2(b1q.y); bs[6]=splat2(b1q.z); bs[7]=splat2(b1q.w);
            #pragma unroll
            for (int r2 = 0; r2 < 4; r2++) {
                u64t av = ap[r2];
                #pragma unroll
                for (int c = 0; c < 8; c++) fma2(aI[r2][c], av, bs[c]);
            }
        }
    }
    // park raw inner in sD (per-thread; same mapping is read back in epilogue)
    #pragma unroll
    for (int r2 = 0; r2 < 4; r2++) {
        float2 v[8];
        #pragma unroll
        for (int c = 0; c < 8; c++) v[c] = unpk(aI[r2][c]);
        int row = ty*8 + r2*2;
        *(float4*)(sD + row*DST + tx*8)     = make_float4(v[0].x, v[1].x, v[2].x, v[3].x);
        *(float4*)(sD + row*DST + tx*8 + 4) = make_float4(v[4].x, v[5].x, v[6].x, v[7].x);
        *(float4*)(sD + (row+1)*DST + tx*8)     = make_float4(v[0].y, v[1].y, v[2].y, v[3].y);
        *(float4*)(sD + (row+1)*DST + tx*8 + 4) = make_float4(v[4].y, v[5].y, v[6].y, v[7].y);
    }

    // ---- Phase B: dots_prime = q' exp(k')^T (4 m-chunks of 32) ----
    u64t aP[4][8];
    #pragma unroll
    for (int r = 0; r < 4; r++)
        #pragma unroll
        for (int c = 0; c < 8; c++) aP[r][c] = 0ull;
    for (int mc = 0; mc < 4; mc++) {
        __syncthreads();
        for (int idx = tid; idx < 4096; idx += 256) {
            int i = idx >> 5, ml = idx & 31;
            sQt[ml*IST + i] = g_qp[((size_t)bh*NTOK + sQi[i])*MF + mc*32 + ml];
            sKt[ml*IST + i] = __expf(g_kp[((size_t)bh*NTOK + sKi[i])*MF + mc*32 + ml] - kls);
        }
        __syncthreads();
        #pragma unroll 2
        for (int m = 0; m < 32; m++) {
            const u64t* ap = (const u64t*)(sQt + m*IST + ty*8);
            float4 b0q = *(const float4*)(sKt + m*IST + tx*8);
            float4 b1q = *(const float4*)(sKt + m*IST + tx*8 + 4);
            u64t bs[8];
            bs[0]=splat2(b0q.x); bs[1]=splat2(b0q.y); bs[2]=splat2(b0q.z); bs[3]=splat2(b0q.w);
            bs[4]=splat2(b1q.x); bs[5]=splat2(b1q.y); bs[6]=splat2(b1q.z); bs[7]=splat2(b1q.w);
            #pragma unroll
            for (int r2 = 0; r2 < 4; r2++) {
                u64t av = ap[r2];
                #pragma unroll
                for (int c = 0; c < 8; c++) fma2(aP[r2][c], av, bs[c]);
            }
        }
    }
    __syncthreads();   // all tile reads done before V overwrites sR1

    // ---- Epilogue (per-thread on own sD rows) + V gather ----
    int kb[8];
    #pragma unroll
    for (int c = 0; c < 8; c++) kb[c] = sKb[tx*8 + c];
    #pragma unroll
    for (int r2 = 0; r2 < 4; r2++) {
        float2 P[8];
        #pragma unroll
        for (int c = 0; c < 8; c++) P[c] = unpk(aP[r2][c]);
        #pragma unroll
        for (int half = 0; half < 2; half++) {
            int row = ty*8 + r2*2 + half;
            int qb = sQb[row]; float pls = sPls[row];
            float4 in0 = *(const float4*)(sD + row*DST + tx*8);
            float4 in1 = *(const float4*)(sD + row*DST + tx*8 + 4);
            float iv[8] = {in0.x, in0.y, in0.z, in0.w, in1.x, in1.y, in1.z, in1.w};
            float pv[8];
            float rm = -1e30f;
            #pragma unroll
            for (int c = 0; c < 8; c++) {
                bool d2 = (qb == kb[c]);
                iv[c] = iv[c]*TEMPF - (d2 ? LN2F : 0.f);
                pv[c] = (half ? P[c].y : P[c].x) * (d2 ? 0.5f : 1.f);
                rm = fmaxf(rm, iv[c]);
            }
            #pragma unroll
            for (int off = 8; off; off >>= 1) rm = fmaxf(rm, __shfl_xor_sync(0xffffffffu, rm, off));
            float l = fmaxf(rm, pls);
            float pe = __expf(pls - l);
            float dv[8];
            float s = 0.f;
            #pragma unroll
            for (int c = 0; c < 8; c++) { dv[c] = __expf(iv[c] - l) - pv[c]*pe; s += dv[c]; }
            *(float4*)(sD + row*DST + tx*8)     = make_float4(dv[0], dv[1], dv[2], dv[3]);
            *(float4*)(sD + row*DST + tx*8 + 4) = make_float4(dv[4], dv[5], dv[6], dv[7]);
            #pragma unroll
            for (int off = 8; off; off >>= 1) s += __shfl_xor_sync(0xffffffffu, s, off);
            if (tx == 0) {
                int t = sQi[row];
                size_t bi = (size_t)(h*BH + bh)*NTOK + t;
                g_lseb[bi] = l;
                g_dsb[bi]  = s;
            }
        }
    }
    float* sV = sR1;                    // [128][68]
    for (int idx = tid; idx < 8192; idx += 256) {
        int i = idx >> 6, d = idx & 63;
        sV[i*68 + d] = g_v[((size_t)bh*NTOK + sKi[i])*EH + d];
    }
    __syncthreads();

    // ---- OV GEMM: so = dots @ V, scatter unsorted ----
    int tx2 = tid & 15, ty2 = tid >> 4;
    u64t accO[8][2];
    #pragma unroll
    for (int r = 0; r < 8; r++) { accO[r][0] = 0ull; accO[r][1] = 0ull; }
    for (int j0 = 0; j0 < 128; j0 += 4) {
        float4 a[8];
        #pragma unroll
        for (int r = 0; r < 8; r++) a[r] = *(const float4*)(sD + (ty2*8 + r)*DST + j0);
        #pragma unroll
        for (int jj = 0; jj < 4; jj++) {
            float4 t = *(const float4*)(sV + (j0 + jj)*68 + tx2*4);
            u64t bv0 = pack2(t.x, t.y), bv1 = pack2(t.z, t.w);
            #pragma unroll
            for (int r = 0; r < 8; r++) {
                float av = (jj==0)?a[r].x:(jj==1)?a[r].y:(jj==2)?a[r].z:a[r].w;
                u64t s = splat2(av);
                fma2(accO[r][0], s, bv0); fma2(accO[r][1], s, bv1);
            }
        }
    }
    #pragma unroll
    for (int r = 0; r < 8; r++) {
        int t = sQi[ty2*8 + r];
        float2 u0 = unpk(accO[r][0]), u1 = unpk(accO[r][1]);
        *(float4*)(g_ob + ((size_t)(h*BH + bh)*NTOK + t)*EH + tx2*4) =
            make_float4(u0.x, u0.y, u1.x, u1.y);
    }
}

// ---------------- K11: merge performer + LSH branches ----------------
__global__ void k_merge() {
    int tid = threadIdx.x;
    int t = blockIdx.x*4 + (tid >> 6);
    int d = tid & 63;
    int bh = blockIdx.y;
    size_t i0 = (size_t)bh*NTOK + t;
    size_t i1 = (size_t)(BH + bh)*NTOK + t;
    float l0 = g_lseb[i0], l1 = g_lseb[i1];
    float mx = fmaxf(l0, l1);
    float norm = mx + logf(__expf(l0 - mx) + __expf(l1 - mx));
    float p0 = __expf(l0 - norm), p1 = __expf(l1 - norm);
    float pls = g_qls[bh*NTOK + t] + g_kls[bh];
    float psc = __expf(pls - norm);
    float z = g_dsb[i0]*p0 + g_dsb[i1]*p1 + g_qk1[bh*NTOK + t]*psc;
    z = fmaxf(z, 1e-6f);
    size_t base = ((size_t)bh*NTOK + t)*EH + d;
    float outv = g_ob[i0*EH + d]*p0 + g_ob[i1*EH + d]*p1 + g_qkv[base]*psc;
    g_on[base] = outv / z;
}

// ---------------- K12: final projection (16 tokens/block) ----------------
#define WS 130
#define XS 132
__global__ __launch_bounds__(256) void k_final(const float* __restrict__ Wf,
                                               const float* __restrict__ bias,
                                               float* __restrict__ out) {
    __shared__ float sW2[64*WS];
    __shared__ float sX[16*XS];
    int tid = threadIdx.x;
    int tok = tid >> 6, eo = tid & 63;
    int g0 = blockIdx.x*16;
    u64t acc2[4];
    #pragma unroll
    for (int tt = 0; tt < 4; tt++) acc2[tt] = 0ull;
    for (int c = 0; c < 4; c++) {
        __syncthreads();
        for (int idx = tid; idx < 8192; idx += 256) {
            int e2 = idx >> 7, hd = idx & 127;
            sW2[e2*WS + hd] = Wf[e2*512 + c*128 + hd];
        }
        for (int idx = tid; idx < 2048; idx += 256) {
            int tk = idx >> 7, hd = idx & 127;
            int gg = g0 + tk;
            int b = gg >> 12, t = gg & 4095;
            int hdg = c*128 + hd;
            sX[tk*XS + hd] = g_on[(((size_t)(b*8 + (hdg >> 6)))*NTOK + t)*EH + (hdg & 63)];
        }
        __syncthreads();
        const u64t* wp = (const u64t*)(sW2 + eo*WS);
        #pragma unroll
        for (int tt = 0; tt < 4; tt++) {
            const float4* x4 = (const float4*)(sX + (tok + tt*4)*XS);
            #pragma unroll
            for (int h4 = 0; h4 < 32; h4++) {
                float4 xv = x4[h4];
                fma2(acc2[tt], pack2(xv.x, xv.y), wp[2*h4]);
                fma2(acc2[tt], pack2(xv.z, xv.w), wp[2*h4+1]);
            }
        }
    }
    float bv = bias[eo];
    #pragma unroll
    for (int tt = 0; tt < 4; tt++) {
        float2 u = unpk(acc2[tt]);
        out[(size_t)(g0 + tok + tt*4)*EH + eo] = u.x + u.y + bv;
    }
}

// ---------------- launch ----------------
extern "C" void kernel_launch(void* const* d_in, const int* in_sizes, int n_in,
                              void* d_out, int out_size) {
    const float* query = (const float*)d_in[0];
    const float* key   = (const float*)d_in[1];
    const float* value = (const float*)d_in[2];
    const float* projW = (const float*)d_in[3];
    const float* alpha = (const float*)d_in[4];
    const float* beta  = (const float*)d_in[5];
    const float* outW  = (const float*)d_in[6];
    const float* outb  = (const float*)d_in[7];
    float* out = (float*)d_out;

    cudaFuncSetAttribute(k_featg,   cudaFuncAttributeMaxDynamicSharedMemorySize, FEATG_SMEM);
    cudaFuncSetAttribute(k_kvpart2, cudaFuncAttributeMaxDynamicSharedMemorySize, KVP_SMEM);
    cudaFuncSetAttribute(k_qkv2,    cudaFuncAttributeMaxDynamicSharedMemorySize, QKV_SMEM);
    cudaFuncSetAttribute(k_bucket2, cudaFuncAttributeMaxDynamicSharedMemorySize, BKT_SMEM);

    k_split<<<dim3(NTOK/4, BH), 256>>>(query, key, value);
    k_featg<<<dim3(NTOK/128, BH, 2), 256, FEATG_SMEM>>>(projW);
    k_kls<<<BH, 256>>>();
    k_kvpart2<<<dim3(NCH, BH), 256, KVP_SMEM>>>();      // profiled slot (idx 3)
    k_maxn<<<BH, 256>>>();
    k_hash<<<dim3(NTOK/256, BH), 256>>>(alpha, beta);
    k_sort<<<128, 512>>>();
    k_kvred<<<BH*MF*EH/256, 256>>>();
    k_qkv2<<<dim3(NTOK/128, BH), 256, QKV_SMEM>>>();
    k_bucket2<<<dim3(32, BH, 2), 256, BKT_SMEM>>>();
    k_merge<<<dim3(NTOK/4, BH), 256>>>();
    k_final<<<NTOK*4/16, 256>>>(outW, outb, out);
}

// round 10
// speedup vs baseline: 2.0284x; 1.0128x over previous
#include <cuda_runtime.h>
#include <math.h>

#define BH 32
#define NTOK 4096
#define EH 64
#define MF 128
#define DM 512
#define NCH 16
#define IST 132
#define FST 132
#define DST 132

#define SQRT_TEMP 0.35355339059327373f
#define TEMPF 0.125f
#define HALF_LOG_M 2.4260151319598084f
#define LN2F 0.6931471805599453f

typedef unsigned long long u64t;
__device__ __forceinline__ u64t splat2(float x) {
    u64t r; asm("mov.b64 %0, {%1, %1};" : "=l"(r) : "f"(x)); return r;
}
__device__ __forceinline__ u64t pack2(float x, float y) {
    u64t r; asm("mov.b64 %0, {%1, %2};" : "=l"(r) : "f"(x), "f"(y)); return r;
}
__device__ __forceinline__ void fma2(u64t& c, u64t a, u64t b) {
    asm("fma.rn.f32x2 %0, %1, %2, %0;" : "+l"(c) : "l"(a), "l"(b));
}
__device__ __forceinline__ float2 unpk(u64t v) {
    float2 f; asm("mov.b64 {%0, %1}, %2;" : "=f"(f.x), "=f"(f.y) : "l"(v)); return f;
}

// ---------------- scratch ----------------
__device__ float g_q[BH*NTOK*EH];
__device__ float g_k[BH*NTOK*EH];
__device__ float g_v[BH*NTOK*EH];
__device__ float g_qn2[BH*NTOK];
__device__ float g_kn2[BH*NTOK];
__device__ float g_MQ2[BH];
__device__ float g_MK2[BH];
__device__ float g_hashq[2*BH*NTOK];
__device__ float g_hashk[2*BH*NTOK];
__device__ int   g_qpos[2*BH*NTOK];
__device__ int   g_kpos[2*BH*NTOK];
__device__ int   g_qrev[2*BH*NTOK];
__device__ int   g_krev[2*BH*NTOK];
__device__ float g_qp[(size_t)BH*NTOK*MF];
__device__ float g_kp[(size_t)BH*NTOK*MF];    // log-phi (pre-exp)
__device__ float g_qls[BH*NTOK];
__device__ float g_krm[BH*NTOK];
__device__ float g_kls[BH];
__device__ float g_kvp[(size_t)NCH*BH*MF*EH];
__device__ float g_ksp[NCH*BH*MF];
__device__ float g_kv[BH*MF*EH];
__device__ float g_ksum[BH*MF];
__device__ float g_qk1[BH*NTOK];
__device__ float g_qkv[(size_t)BH*NTOK*EH];
__device__ float g_ob[(size_t)2*BH*NTOK*EH];
__device__ float g_lseb[2*BH*NTOK];
__device__ float g_dsb[2*BH*NTOK];
__device__ float4 g_msc[BH*NTOK];

// ---------------- K1: split heads + squared norms ----------------
__global__ __launch_bounds__(256) void k_split(const float* __restrict__ query,
                                               const float* __restrict__ key,
                                               const float* __restrict__ value) {
    int tid = threadIdx.x;
    int tl = tid >> 6, e = tid & 63;
    int t = blockIdx.x*4 + tl, bh = blockIdx.y;
    int b = bh >> 3, hh = bh & 7;
    size_t gi = ((size_t)(b*NTOK + t))*DM + hh*EH + e;
    float qv = query[gi], kv = key[gi], vv = value[gi];
    size_t oi = ((size_t)bh*NTOK + t)*EH + e;
    g_q[oi] = qv; g_k[oi] = kv; g_v[oi] = vv;
    float q2 = qv*qv, k2 = kv*kv;
    #pragma unroll
    for (int o = 16; o; o >>= 1) {
        q2 += __shfl_down_sync(0xffffffffu, q2, o);
        k2 += __shfl_down_sync(0xffffffffu, k2, o);
    }
    __shared__ float sq[8], sk[8];
    if ((tid & 31) == 0) { sq[tid>>5] = q2; sk[tid>>5] = k2; }
    __syncthreads();
    if (e == 0) {
        g_qn2[bh*NTOK + t] = sq[2*tl] + sq[2*tl+1];
        g_kn2[bh*NTOK + t] = sk[2*tl] + sk[2*tl+1];
    }
}

// ---------------- K2: per-bh max squared norms ----------------
__global__ void k_maxn() {
    int bh = blockIdx.x, tid = threadIdx.x;
    float mq = 0.f, mk = 0.f;
    for (int i = tid; i < NTOK; i += 256) {
        mq = fmaxf(mq, g_qn2[bh*NTOK + i]);
        mk = fmaxf(mk, g_kn2[bh*NTOK + i]);
    }
    #pragma unroll
    for (int o = 16; o; o >>= 1) {
        mq = fmaxf(mq, __shfl_xor_sync(0xffffffffu, mq, o));
        mk = fmaxf(mk, __shfl_xor_sync(0xffffffffu, mk, o));
    }
    __shared__ float sq[8], sk[8];
    if ((tid & 31) == 0) { sq[tid>>5] = mq; sk[tid>>5] = mk; }
    __syncthreads();
    if (tid == 0) {
        float a = sq[0], b = sk[0];
        for (int w = 1; w < 8; w++) { a = fmaxf(a, sq[w]); b = fmaxf(b, sk[w]); }
        g_MQ2[bh] = a; g_MK2[bh] = b;
    }
}

// ---------------- K3: LSH hashes ----------------
__global__ void k_hash(const float* __restrict__ alpha, const float* __restrict__ beta) {
    __shared__ float sal[2*(EH+2)];
    __shared__ float sbe[2];
    int bh = blockIdx.y;
    int tid = threadIdx.x;
    if (tid < 2*(EH+2)) sal[tid] = alpha[tid];
    if (tid < 2) sbe[tid] = beta[tid];
    __syncthreads();
    int t = blockIdx.x*256 + tid;
    const float* qr = g_q + ((size_t)bh*NTOK + t)*EH;
    const float* kr = g_k + ((size_t)bh*NTOK + t)*EH;
    float a0 = 0.f, a1 = 0.f, c0 = 0.f, c1 = 0.f;
    #pragma unroll 8
    for (int e = 0; e < EH; e++) {
        float al0 = sal[e*2], al1 = sal[e*2+1];
        float qe = qr[e], ke = kr[e];
        a0 += qe*al0; a1 += qe*al1;
        c0 += ke*al0; c1 += ke*al1;
    }
    float S = g_MQ2[bh] + g_MK2[bh];
    float extq = sqrtf(fmaxf(S - g_qn2[bh*NTOK + t], 0.f));
    float extk = sqrtf(fmaxf(S - g_kn2[bh*NTOK + t], 0.f));
    g_hashq[bh*NTOK + t]           = a0 + extq*sal[EH*2]       + sbe[0];
    g_hashq[BH*NTOK + bh*NTOK + t] = a1 + extq*sal[EH*2+1]     + sbe[1];
    g_hashk[bh*NTOK + t]           = c0 + extk*sal[(EH+1)*2]   + sbe[0];
    g_hashk[BH*NTOK + bh*NTOK + t] = c1 + extk*sal[(EH+1)*2+1] + sbe[1];
}

// ---------------- K5: performer feature maps as tiled GEMM ----------------
#define FEATG_SMEM (2*64*FST*4 + 128*4)
__global__ __launch_bounds__(256, 2) void k_featg(const float* __restrict__ W) {
    extern __shared__ float sm[];
    float* sXt = sm;                    // [64][FST]
    float* sWt = sm + 64*FST;           // [64][FST]
    float* sN  = sm + 2*64*FST;         // [128]
    int nb = blockIdx.x, bh = blockIdx.y, isK = blockIdx.z;
    int tid = threadIdx.x, tx = tid & 15, ty = tid >> 4;
    const float* X  = isK ? g_k   : g_q;
    const float* n2 = isK ? g_kn2 : g_qn2;
    int tb = nb*128;
    for (int idx = tid; idx < 8192; idx += 256) {
        int i = idx >> 6, e = idx & 63;
        sXt[e*FST + i] = X[((size_t)bh*NTOK + tb + i)*EH + e];
        sWt[e*FST + i] = W[i*EH + e];
    }
    if (tid < 128) sN[tid] = n2[bh*NTOK + tb + tid];
    __syncthreads();
    u64t acc[4][8];
    #pragma unroll
    for (int r = 0; r < 4; r++)
        #pragma unroll
        for (int c = 0; c < 8; c++) acc[r][c] = 0ull;
    #pragma unroll 2
    for (int e = 0; e < 64; e++) {
        const u64t* ap = (const u64t*)(sXt + e*FST + ty*8);
        float4 b0q = *(const float4*)(sWt + e*FST + tx*8);
        float4 b1q = *(const float4*)(sWt + e*FST + tx*8 + 4);
        u64t bs[8];
        bs[0]=splat2(b0q.x); bs[1]=splat2(b0q.y); bs[2]=splat2(b0q.z); bs[3]=splat2(b0q.w);
        bs[4]=splat2(b1q.x); bs[5]=splat2(b1q.y); bs[6]=splat2(b1q.z); bs[7]=splat2(b1q.w);
        #pragma unroll
        for (int r2 = 0; r2 < 4; r2++) {
            u64t av = ap[r2];
            #pragma unroll
            for (int c = 0; c < 8; c++) fma2(acc[r2][c], av, bs[c]);
        }
    }
    #pragma unroll
    for (int r2 = 0; r2 < 4; r2++) {
        float2 v[8];
        #pragma unroll
        for (int c = 0; c < 8; c++) v[c] = unpk(acc[r2][c]);
        #pragma unroll
        for (int half = 0; half < 2; half++) {
            int row = ty*8 + r2*2 + half;
            int t = tb + row;
            float nn = 0.5f*TEMPF*sN[row] + HALF_LOG_M;
            float lp[8];
            float rm = -1e30f;
            #pragma unroll
            for (int c = 0; c < 8; c++) {
                lp[c] = (half ? v[c].y : v[c].x)*SQRT_TEMP - nn;
                rm = fmaxf(rm, lp[c]);
            }
            #pragma unroll
            for (int off = 8; off; off >>= 1) rm = fmaxf(rm, __shfl_xor_sync(0xffffffffu, rm, off));
            size_t base = ((size_t)bh*NTOK + t)*MF + tx*8;
            if (!isK) {
                *(float4*)(g_qp + base) = make_float4(__expf(lp[0]-rm), __expf(lp[1]-rm),
                                                      __expf(lp[2]-rm), __expf(lp[3]-rm));
                *(float4*)(g_qp + base + 4) = make_float4(__expf(lp[4]-rm), __expf(lp[5]-rm),
                                                          __expf(lp[6]-rm), __expf(lp[7]-rm));
                if (tx == 0) g_qls[bh*NTOK + t] = rm;
            } else {
                *(float4*)(g_kp + base)     = make_float4(lp[0], lp[1], lp[2], lp[3]);
                *(float4*)(g_kp + base + 4) = make_float4(lp[4], lp[5], lp[6], lp[7]);
                if (tx == 0) g_krm[bh*NTOK + t] = rm;
            }
        }
    }
}

// ---------------- K4: stable bitonic argsort ----------------
__global__ void k_sort() {
    __shared__ float sv[NTOK];
    __shared__ int   si[NTOK];
    int which = blockIdx.x >> 6;
    int rem   = blockIdx.x & 63;
    const float* src = which ? (g_hashk + (size_t)rem*NTOK) : (g_hashq + (size_t)rem*NTOK);
    int tid = threadIdx.x;
    for (int i = tid; i < NTOK; i += 512) { sv[i] = src[i]; si[i] = i; }
    __syncthreads();
    for (int k = 2; k <= NTOK; k <<= 1)
        for (int j = k >> 1; j > 0; j >>= 1) {
            for (int p = tid; p < NTOK/2; p += 512) {
                int i  = ((p & ~(j-1)) << 1) | (p & (j-1));
                int ix = i | j;
                bool up = ((i & k) == 0);
                float vi = sv[i], vj = sv[ix];
                int ii = si[i], ij = si[ix];
                bool agt = (vi > vj) || (vi == vj && ii > ij);
                if (agt == up) { sv[i] = vj; sv[ix] = vi; si[i] = ij; si[ix] = ii; }
            }
            __syncthreads();
        }
    int* pos = which ? g_kpos : g_qpos;
    int* rev = which ? g_krev : g_qrev;
    for (int r = tid; r < NTOK; r += 512) {
        int idx = si[r];
        pos[rem*NTOK + r]   = idx;
        rev[rem*NTOK + idx] = r;
    }
}

// ---------------- K6: per-bh max of k log-phi ----------------
__global__ void k_kls() {
    int bh = blockIdx.x, tid = threadIdx.x;
    float m = -1e30f;
    for (int i = tid; i < NTOK; i += 256) m = fmaxf(m, g_krm[bh*NTOK + i]);
    #pragma unroll
    for (int o = 16; o; o >>= 1) m = fmaxf(m, __shfl_xor_sync(0xffffffffu, m, o));
    __shared__ float s[8];
    if ((tid & 31) == 0) s[tid>>5] = m;
    __syncthreads();
    if (tid == 0) {
        float r = s[0];
        for (int w = 1; w < 8; w++) r = fmaxf(r, s[w]);
        g_kls[bh] = r;
    }
}

// ---------------- K8: partial kv = exp(k')^T v (2 tiles per block) ----------------
#define KVP_SMEM (128*IST*4 + 128*68*4)
__global__ __launch_bounds__(256, 2) void k_kvpart2() {
    extern __shared__ float sm[];
    float* sKP = sm;                    // [128 t][IST]
    float* sV  = sm + 128*IST;          // [128 t][68]
    int ch = blockIdx.x, bh = blockIdx.y;
    int tid = threadIdx.x, tx = tid & 15, ty = tid >> 4;
    float kls = g_kls[bh];
    u64t acc[4][4];
    #pragma unroll
    for (int r = 0; r < 4; r++)
        #pragma unroll
        for (int c = 0; c < 4; c++) acc[r][c] = 0ull;
    float csum = 0.f;
    for (int tile = 0; tile < 2; tile++) {
        int t0 = ch*256 + tile*128;
        __syncthreads();
        for (int idx = tid; idx < 16384; idx += 256) {
            int t = idx >> 7, m = idx & 127;
            sKP[t*IST + m] = __expf(g_kp[((size_t)bh*NTOK + t0 + t)*MF + m] - kls);
        }
        for (int idx = tid; idx < 8192; idx += 256) {
            int t = idx >> 6, d = idx & 63;
            sV[t*68 + d] = g_v[((size_t)bh*NTOK + t0 + t)*EH + d];
        }
        __syncthreads();
        #pragma unroll 4
        for (int t = 0; t < 128; t++) {
            const u64t* ap = (const u64t*)(sKP + t*IST + ty*8);
            float4 bq = *(const float4*)(sV + t*68 + tx*4);
            u64t b0 = splat2(bq.x), b1 = splat2(bq.y), b2 = splat2(bq.z), b3 = splat2(bq.w);
            #pragma unroll
            for (int r2 = 0; r2 < 4; r2++) {
                u64t av = ap[r2];
                fma2(acc[r2][0], av, b0); fma2(acc[r2][1], av, b1);
                fma2(acc[r2][2], av, b2); fma2(acc[r2][3], av, b3);
            }
        }
        if (tid < 128) {
            float s = 0.f;
            #pragma unroll 8
            for (int t = 0; t < 128; t++) s += sKP[t*IST + tid];
            csum += s;
        }
    }
    float* dst = g_kvp + ((size_t)(ch*BH + bh))*MF*EH;
    #pragma unroll
    for (int r2 = 0; r2 < 4; r2++) {
        float2 v0 = unpk(acc[r2][0]), v1 = unpk(acc[r2][1]);
        float2 v2 = unpk(acc[r2][2]), v3 = unpk(acc[r2][3]);
        int m = ty*8 + r2*2;
        *(float4*)(dst + (size_t)m*EH + tx*4)     = make_float4(v0.x, v1.x, v2.x, v3.x);
        *(float4*)(dst + (size_t)(m+1)*EH + tx*4) = make_float4(v0.y, v1.y, v2.y, v3.y);
    }
    if (tid < 128) g_ksp[(ch*BH + bh)*MF + tid] = csum;
}

// ---------------- K8b: deterministic reduce ----------------
__global__ void k_kvred() {
    int idx = blockIdx.x*256 + threadIdx.x;
    float s = 0.f;
    #pragma unroll
    for (int c = 0; c < NCH; c++) s += g_kvp[(size_t)c*BH*MF*EH + idx];
    g_kv[idx] = s;
    if (idx < BH*MF) {
        float ss = 0.f;
        #pragma unroll
        for (int c = 0; c < NCH; c++) ss += g_ksp[c*BH*MF + idx];
        g_ksum[idx] = ss;
    }
}

// ---------------- K9: qkv = q' kv + qk1, tiled GEMM ----------------
#define QKV_SMEM (128*IST*4 + 128*68*4 + 128*4)
__global__ __launch_bounds__(256, 2) void k_qkv2() {
    extern __shared__ float sm[];
    float* sQPt = sm;                   // [128 m][IST tokens]
    float* sKV  = sm + 128*IST;         // [128 m][68]
    float* sks  = sm + 128*IST + 128*68;
    int nb = blockIdx.x, bh = blockIdx.y;
    int tid = threadIdx.x, tx = tid & 15, ty = tid >> 4;
    int tb = nb*128;
    for (int idx = tid; idx < 16384; idx += 256) {
        int i = idx >> 7, m = idx & 127;
        sQPt[m*IST + i] = g_qp[((size_t)bh*NTOK + tb + i)*MF + m];
    }
    for (int idx = tid; idx < 8192; idx += 256) {
        int m = idx >> 6, d = idx & 63;
        sKV[m*68 + d] = g_kv[(size_t)bh*MF*EH + m*EH + d];
    }
    if (tid < 128) sks[tid] = g_ksum[bh*MF + tid];
    __syncthreads();
    u64t acc[4][4];
    #pragma unroll
    for (int r = 0; r < 4; r++)
        #pragma unroll
        for (int c = 0; c < 4; c++) acc[r][c] = 0ull;
    #pragma unroll 4
    for (int m = 0; m < 128; m++) {
        const u64t* ap = (const u64t*)(sQPt + m*IST + ty*8);
        float4 bq = *(const float4*)(sKV + m*68 + tx*4);
        u64t b0 = splat2(bq.x), b1 = splat2(bq.y), b2 = splat2(bq.z), b3 = splat2(bq.w);
        #pragma unroll
        for (int r2 = 0; r2 < 4; r2++) {
            u64t av = ap[r2];
            fma2(acc[r2][0], av, b0); fma2(acc[r2][1], av, b1);
            fma2(acc[r2][2], av, b2); fma2(acc[r2][3], av, b3);
        }
    }
    #pragma unroll
    for (int r2 = 0; r2 < 4; r2++) {
        float2 v0 = unpk(acc[r2][0]), v1 = unpk(acc[r2][1]);
        float2 v2 = unpk(acc[r2][2]), v3 = unpk(acc[r2][3]);
        int row = ty*8 + r2*2;
        *(float4*)(g_qkv + ((size_t)bh*NTOK + tb + row)*EH + tx*4)
            = make_float4(v0.x, v1.x, v2.x, v3.x);
        *(float4*)(g_qkv + ((size_t)bh*NTOK + tb + row + 1)*EH + tx*4)
            = make_float4(v0.y, v1.y, v2.y, v3.y);
    }
    if (tid < 128) {
        float s = 0.f;
        #pragma unroll 8
        for (int m = 0; m < 128; m++) s += sQPt[m*IST + tid]*sks[m];
        g_qk1[bh*NTOK + tb + tid] = s;
    }
}

// ======= K10: fully fused bucketed correction =======
#define R1_FLOATS 8704
#define BKT_SMEM ((128*DST + R1_FLOATS)*4)
__global__ __launch_bounds__(256, 2) void k_bucket2() {
    extern __shared__ float sm[];
    float* sD  = sm;                    // [128][DST]
    float* sR1 = sm + 128*DST;          // tiles: [32][IST] x2 ; later V [128][68]
    __shared__ int sQi[128], sKi[128], sQb[128], sKb[128];
    __shared__ float sPls[128];
    int nb = blockIdx.x, bh = blockIdx.y, h = blockIdx.z;
    int tid = threadIdx.x, tx = tid & 15, ty = tid >> 4;
    int o = 1 - h;
    float kls = g_kls[bh];
    if (tid < 128) {
        int qi = g_qpos[(h*BH + bh)*NTOK + nb*128 + tid];
        int ki = g_kpos[(h*BH + bh)*NTOK + nb*128 + tid];
        sQi[tid] = qi; sKi[tid] = ki;
        sQb[tid] = g_qrev[(o*BH + bh)*NTOK + qi] >> 7;
        sKb[tid] = g_krev[(o*BH + bh)*NTOK + ki] >> 7;
        sPls[tid] = g_qls[bh*NTOK + qi] + kls;
    }
    float* sQt = sR1;                   // [32][IST]
    float* sKt = sR1 + 32*IST;

    u64t aI[4][8];
    #pragma unroll
    for (int r = 0; r < 4; r++)
        #pragma unroll
        for (int c = 0; c < 8; c++) aI[r][c] = 0ull;
    for (int ec = 0; ec < 2; ec++) {
        __syncthreads();
        for (int idx = tid; idx < 4096; idx += 256) {
            int i = idx >> 5, el = idx & 31;
            sQt[el*IST + i] = g_q[((size_t)bh*NTOK + sQi[i])*EH + ec*32 + el];
            sKt[el*IST + i] = g_k[((size_t)bh*NTOK + sKi[i])*EH + ec*32 + el];
        }
        __syncthreads();
        #pragma unroll 2
        for (int e = 0; e < 32; e++) {
            const u64t* ap = (const u64t*)(sQt + e*IST + ty*8);
            float4 b0q = *(const float4*)(sKt + e*IST + tx*8);
            float4 b1q = *(const float4*)(sKt + e*IST + tx*8 + 4);
            u64t bs[8];
            bs[0]=splat2(b0q.x); bs[1]=splat2(b0q.y); bs[2]=splat2(b0q.z); bs[3]=splat2(b0q.w);
            bs[4]=splat2(b1q.x); bs[5]=splat2(b1q.y); bs[6]=splat2(b1q.z); bs[7]=splat2(b1q.w);
            #pragma unroll
            for (int r2 = 0; r2 < 4; r2++) {
                u64t av = ap[r2];
                #pragma unroll
                for (int c = 0; c < 8; c++) fma2(aI[r2][c], av, bs[c]);
            }
        }
    }
    #pragma unroll
    for (int r2 = 0; r2 < 4; r2++) {
        float2 v[8];
        #pragma unroll
        for (int c = 0; c < 8; c++) v[c] = unpk(aI[r2][c]);
        int row = ty*8 + r2*2;
        *(float4*)(sD + row*DST + tx*8)     = make_float4(v[0].x, v[1].x, v[2].x, v[3].x);
        *(float4*)(sD + row*DST + tx*8 + 4) = make_float4(v[4].x, v[5].x, v[6].x, v[7].x);
        *(float4*)(sD + (row+1)*DST + tx*8)     = make_float4(v[0].y, v[1].y, v[2].y, v[3].y);
        *(float4*)(sD + (row+1)*DST + tx*8 + 4) = make_float4(v[4].y, v[5].y, v[6].y, v[7].y);
    }

    u64t aP[4][8];
    #pragma unroll
    for (int r = 0; r < 4; r++)
        #pragma unroll
        for (int c = 0; c < 8; c++) aP[r][c] = 0ull;
    for (int mc = 0; mc < 4; mc++) {
        __syncthreads();
        for (int idx = tid; idx < 4096; idx += 256) {
            int i = idx >> 5, ml = idx & 31;
            sQt[ml*IST + i] = g_qp[((size_t)bh*NTOK + sQi[i])*MF + mc*32 + ml];
            sKt[ml*IST + i] = __expf(g_kp[((size_t)bh*NTOK + sKi[i])*MF + mc*32 + ml] - kls);
        }
        __syncthreads();
        #pragma unroll 2
        for (int m = 0; m < 32; m++) {
            const u64t* ap = (const u64t*)(sQt + m*IST + ty*8);
            float4 b0q = *(const float4*)(sKt + m*IST + tx*8);
            float4 b1q = *(const float4*)(sKt + m*IST + tx*8 + 4);
            u64t bs[8];
            bs[0]=splat2(b0q.x); bs[1]=splat2(b0q.y); bs[2]=splat2(b0q.z); bs[3]=splat2(b0q.w);
            bs[4]=splat2(b1q.x); bs[5]=splat2(b1q.y); bs[6]=splat2(b1q.z); bs[7]=splat2(b1q.w);
            #pragma unroll
            for (int r2 = 0; r2 < 4; r2++) {
                u64t av = ap[r2];
                #pragma unroll
                for (int c = 0; c < 8; c++) fma2(aP[r2][c], av, bs[c]);
            }
        }
    }
    __syncthreads();

    int kb[8];
    #pragma unroll
    for (int c = 0; c < 8; c++) kb[c] = sKb[tx*8 + c];
    #pragma unroll
    for (int r2 = 0; r2 < 4; r2++) {
        float2 P[8];
        #pragma unroll
        for (int c = 0; c < 8; c++) P[c] = unpk(aP[r2][c]);
        #pragma unroll
        for (int half = 0; half < 2; half++) {
            int row = ty*8 + r2*2 + half;
            int qb = sQb[row]; float pls = sPls[row];
            float4 in0 = *(const float4*)(sD + row*DST + tx*8);
            float4 in1 = *(const float4*)(sD + row*DST + tx*8 + 4);
            float iv[8] = {in0.x, in0.y, in0.z, in0.w, in1.x, in1.y, in1.z, in1.w};
            float pv[8];
            float rm = -1e30f;
            #pragma unroll
            for (int c = 0; c < 8; c++) {
                bool d2 = (qb == kb[c]);
                iv[c] = iv[c]*TEMPF - (d2 ? LN2F : 0.f);
                pv[c] = (half ? P[c].y : P[c].x) * (d2 ? 0.5f : 1.f);
                rm = fmaxf(rm, iv[c]);
            }
            #pragma unroll
            for (int off = 8; off; off >>= 1) rm = fmaxf(rm, __shfl_xor_sync(0xffffffffu, rm, off));
            float l = fmaxf(rm, pls);
            float pe = __expf(pls - l);
            float dv[8];
            float s = 0.f;
            #pragma unroll
            for (int c = 0; c < 8; c++) { dv[c] = __expf(iv[c] - l) - pv[c]*pe; s += dv[c]; }
            *(float4*)(sD + row*DST + tx*8)     = make_float4(dv[0], dv[1], dv[2], dv[3]);
            *(float4*)(sD + row*DST + tx*8 + 4) = make_float4(dv[4], dv[5], dv[6], dv[7]);
            #pragma unroll
            for (int off = 8; off; off >>= 1) s += __shfl_xor_sync(0xffffffffu, s, off);
            if (tx == 0) {
                int t = sQi[row];
                size_t bi = (size_t)(h*BH + bh)*NTOK + t;
                g_lseb[bi] = l;
                g_dsb[bi]  = s;
            }
        }
    }
    float* sV = sR1;                    // [128][68]
    for (int idx = tid; idx < 8192; idx += 256) {
        int i = idx >> 6, d = idx & 63;
        sV[i*68 + d] = g_v[((size_t)bh*NTOK + sKi[i])*EH + d];
    }
    __syncthreads();

    int tx2 = tid & 15, ty2 = tid >> 4;
    u64t accO[8][2];
    #pragma unroll
    for (int r = 0; r < 8; r++) { accO[r][0] = 0ull; accO[r][1] = 0ull; }
    for (int j0 = 0; j0 < 128; j0 += 4) {
        float4 a[8];
        #pragma unroll
        for (int r = 0; r < 8; r++) a[r] = *(const float4*)(sD + (ty2*8 + r)*DST + j0);
        #pragma unroll
        for (int jj = 0; jj < 4; jj++) {
            float4 t = *(const float4*)(sV + (j0 + jj)*68 + tx2*4);
            u64t bv0 = pack2(t.x, t.y), bv1 = pack2(t.z, t.w);
            #pragma unroll
            for (int r = 0; r < 8; r++) {
                float av = (jj==0)?a[r].x:(jj==1)?a[r].y:(jj==2)?a[r].z:a[r].w;
                u64t s = splat2(av);
                fma2(accO[r][0], s, bv0); fma2(accO[r][1], s, bv1);
            }
        }
    }
    #pragma unroll
    for (int r = 0; r < 8; r++) {
        int t = sQi[ty2*8 + r];
        float2 u0 = unpk(accO[r][0]), u1 = unpk(accO[r][1]);
        *(float4*)(g_ob + ((size_t)(h*BH + bh)*NTOK + t)*EH + tx2*4) =
            make_float4(u0.x, u0.y, u1.x, u1.y);
    }
}

// ---------------- K11: merge scalars per (bh, t) ----------------
__global__ void k_mscal() {
    int t = blockIdx.x*256 + threadIdx.x;
    int bh = blockIdx.y;
    size_t i0 = (size_t)bh*NTOK + t;
    size_t i1 = (size_t)(BH + bh)*NTOK + t;
    float l0 = g_lseb[i0], l1 = g_lseb[i1];
    float mx = fmaxf(l0, l1);
    float norm = mx + logf(__expf(l0 - mx) + __expf(l1 - mx));
    float p0 = __expf(l0 - norm), p1 = __expf(l1 - norm);
    float pls = g_qls[bh*NTOK + t] + g_kls[bh];
    float psc = __expf(pls - norm);
    float z = g_dsb[i0]*p0 + g_dsb[i1]*p1 + g_qk1[bh*NTOK + t]*psc;
    float invz = 1.f / fmaxf(z, 1e-6f);
    g_msc[i0] = make_float4(p0*invz, p1*invz, psc*invz, 0.f);
}

// ---------------- K12: final projection with fused merge ----------------
#define WS 130
#define XS 132
__global__ __launch_bounds__(256) void k_final(const float* __restrict__ Wf,
                                               const float* __restrict__ bias,
                                               float* __restrict__ out) {
    __shared__ float sW2[64*WS];
    __shared__ float sX[16*XS];
    int tid = threadIdx.x;
    int tok = tid >> 6, eo = tid & 63;
    int g0 = blockIdx.x*16;
    u64t acc2[4];
    #pragma unroll
    for (int tt = 0; tt < 4; tt++) acc2[tt] = 0ull;
    for (int c = 0; c < 4; c++) {
        __syncthreads();
        for (int idx = tid; idx < 8192; idx += 256) {
            int e2 = idx >> 7, hd = idx & 127;
            sW2[e2*WS + hd] = Wf[e2*512 + c*128 + hd];
        }
        for (int idx = tid; idx < 2048; idx += 256) {
            int tk = idx >> 7, hd = idx & 127;
            int gg = g0 + tk;
            int b = gg >> 12, t = gg & 4095;
            int hdg = c*128 + hd;
            int bh = b*8 + (hdg >> 6);
            int d = hdg & 63;
            size_t ti = (size_t)bh*NTOK + t;
            float4 ms = g_msc[ti];
            float val = g_ob[ti*EH + d]*ms.x
                      + g_ob[(size_t)BH*NTOK*EH + ti*EH + d]*ms.y
                      + g_qkv[ti*EH + d]*ms.z;
            sX[tk*XS + hd] = val;
        }
        __syncthreads();
        const u64t* wp = (const u64t*)(sW2 + eo*WS);
        #pragma unroll
        for (int tt = 0; tt < 4; tt++) {
            const float4* x4 = (const float4*)(sX + (tok + tt*4)*XS);
            #pragma unroll
            for (int h4 = 0; h4 < 32; h4++) {
                float4 xv = x4[h4];
                fma2(acc2[tt], pack2(xv.x, xv.y), wp[2*h4]);
                fma2(acc2[tt], pack2(xv.z, xv.w), wp[2*h4+1]);
            }
        }
    }
    float bv = bias[eo];
    #pragma unroll
    for (int tt = 0; tt < 4; tt++) {
        float2 u = unpk(acc2[tt]);
        out[(size_t)(g0 + tok + tt*4)*EH + eo] = u.x + u.y + bv;
    }
}

// ---------------- launch ----------------
extern "C" void kernel_launch(void* const* d_in, const int* in_sizes, int n_in,
                              void* d_out, int out_size) {
    const float* query = (const float*)d_in[0];
    const float* key   = (const float*)d_in[1];
    const float* value = (const float*)d_in[2];
    const float* projW = (const float*)d_in[3];
    const float* alpha = (const float*)d_in[4];
    const float* beta  = (const float*)d_in[5];
    const float* outW  = (const float*)d_in[6];
    const float* outb  = (const float*)d_in[7];
    float* out = (float*)d_out;

    cudaFuncSetAttribute(k_featg,   cudaFuncAttributeMaxDynamicSharedMemorySize, FEATG_SMEM);
    cudaFuncSetAttribute(k_kvpart2, cudaFuncAttributeMaxDynamicSharedMemorySize, KVP_SMEM);
    cudaFuncSetAttribute(k_qkv2,    cudaFuncAttributeMaxDynamicSharedMemorySize, QKV_SMEM);
    cudaFuncSetAttribute(k_bucket2, cudaFuncAttributeMaxDynamicSharedMemorySize, BKT_SMEM);

    k_split<<<dim3(NTOK/4, BH), 256>>>(query, key, value);
    k_featg<<<dim3(NTOK/128, BH, 2), 256, FEATG_SMEM>>>(projW);
    k_kls<<<BH, 256>>>();
    k_kvpart2<<<dim3(NCH, BH), 256, KVP_SMEM>>>();      // profiled slot (idx 3)
    k_maxn<<<BH, 256>>>();
    k_hash<<<dim3(NTOK/256, BH), 256>>>(alpha, beta);
    k_sort<<<128, 512>>>();
    k_kvred<<<BH*MF*EH/256, 256>>>();
    k_qkv2<<<dim3(NTOK/128, BH), 256, QKV_SMEM>>>();
    k_bucket2<<<dim3(32, BH, 2), 256, BKT_SMEM>>>();
    k_mscal<<<dim3(NTOK/256, BH), 256>>>();
    k_final<<<NTOK*4/16, 256>>>(outW, outb, out);
}